// round 7
// baseline (speedup 1.0000x reference)
#include <cuda_runtime.h>
#include <math.h>
#include <stdint.h>

#define BB 2
#define NN 8192
#define DIMM 512
#define GH 6
#define DH 64
#define NBF 256
#define NWIN 32
#define WINSZ 256
#define BHG (BB*GH)      // 12
#define BHL 4            // B * LOCAL_HEADS
#define NSPLIT 16

typedef unsigned long long ull;

// ---------------- packed f32x2 helpers (Blackwell FFMA2 path) ----------------
__device__ __forceinline__ ull ffma2(ull a, ull b, ull c) {
    ull d;
    asm("fma.rn.f32x2 %0, %1, %2, %3;" : "=l"(d) : "l"(a), "l"(b), "l"(c));
    return d;
}
__device__ __forceinline__ ull pk2(float x) {
    ull r;
    asm("mov.b64 %0, {%1, %2};" : "=l"(r) : "f"(x), "f"(x));
    return r;
}
__device__ __forceinline__ float2 upk(ull a) {
    float2 t;
    asm("mov.b64 {%0, %1}, %2;" : "=f"(t.x), "=f"(t.y) : "l"(a));
    return t;
}
__device__ __forceinline__ float4 mk4(ull a, ull b) {
    float2 x = upk(a), y = upk(b);
    return make_float4(x.x, x.y, y.x, y.y);
}

// ---------------- scratch (device globals: alloc-free) ----------------
__device__ float g_q[BB*NN*DIMM];
__device__ float g_k[BB*NN*DIMM];
__device__ float g_v[BB*NN*DIMM];
__device__ float g_qp[BHG*NN*NBF];
__device__ float g_kp[BHG*NN*NBF];
__device__ float g_kmaxp[BHG*64];
__device__ float g_kmax[BHG];
__device__ float g_part[BHG*NSPLIT*256*65];
__device__ float g_ctx[BHG*256*68];
__device__ float g_dinv[BHG*NN];
__device__ float g_att[BB*NN*DIMM];
__device__ float g_sc[(size_t)BHL*NWIN*WINSZ*768];
__device__ float g_rq[BHL*NN*DH];
__device__ float g_rk[BHL*NN*DH];

// ---------------- generic 128x128x16 SGEMM, row-major, optional bias ----------------
__global__ void __launch_bounds__(256) sgemm128(
    const float* __restrict__ A, const float* __restrict__ Bm,
    const float* __restrict__ bias, float* __restrict__ C,
    int M, int Nn, int K)
{
    __shared__ __align__(16) float As[16][128];
    __shared__ __align__(16) float Bs[16][128];
    int bx = blockIdx.x, by = blockIdx.y;
    int tid = threadIdx.x;
    int tx = tid % 16, ty = tid / 16;
    ull acc[8][4] = {};

    int a_row  = tid >> 2;         // 0..63
    int a_col4 = (tid & 3) * 4;    // 0,4,8,12
    int b_row  = tid >> 5;         // 0..7
    int b_col4 = (tid & 31) * 4;   // 0..124

    const float* Aptr = A + (size_t)(by * 128) * K;
    const float* Bptr = Bm + bx * 128;

    for (int k0 = 0; k0 < K; k0 += 16) {
#pragma unroll
        for (int i = 0; i < 2; i++) {
            int r = a_row + i * 64;
            float4 va = *(const float4*)(Aptr + (size_t)r * K + k0 + a_col4);
            As[a_col4+0][r] = va.x; As[a_col4+1][r] = va.y;
            As[a_col4+2][r] = va.z; As[a_col4+3][r] = va.w;
        }
#pragma unroll
        for (int i = 0; i < 2; i++) {
            int r = b_row + i * 8;
            float4 vb = *(const float4*)(Bptr + (size_t)(k0 + r) * Nn + b_col4);
            *(float4*)&Bs[r][b_col4] = vb;
        }
        __syncthreads();
#pragma unroll
        for (int kk = 0; kk < 16; kk++) {
            float4 a0 = *(const float4*)&As[kk][ty*8];
            float4 a1 = *(const float4*)&As[kk][ty*8+4];
            ulonglong2 b01 = *(const ulonglong2*)&Bs[kk][tx*8];
            ulonglong2 b23 = *(const ulonglong2*)&Bs[kk][tx*8+4];
            float af[8] = {a0.x,a0.y,a0.z,a0.w,a1.x,a1.y,a1.z,a1.w};
#pragma unroll
            for (int i = 0; i < 8; i++) {
                ull aa = pk2(af[i]);
                acc[i][0] = ffma2(aa, b01.x, acc[i][0]);
                acc[i][1] = ffma2(aa, b01.y, acc[i][1]);
                acc[i][2] = ffma2(aa, b23.x, acc[i][2]);
                acc[i][3] = ffma2(aa, b23.y, acc[i][3]);
            }
        }
        __syncthreads();
    }
#pragma unroll
    for (int i = 0; i < 8; i++) {
        int r = by * 128 + ty * 8 + i;
        int c = bx * 128 + tx * 8;
        float4 v0 = mk4(acc[i][0], acc[i][1]);
        float4 v1 = mk4(acc[i][2], acc[i][3]);
        if (bias) {
            float4 b0 = *(const float4*)(bias + c);
            float4 b1 = *(const float4*)(bias + c + 4);
            v0.x += b0.x; v0.y += b0.y; v0.z += b0.z; v0.w += b0.w;
            v1.x += b1.x; v1.y += b1.y; v1.z += b1.z; v1.w += b1.w;
        }
        *(float4*)(C + (size_t)r * Nn + c) = v0;
        *(float4*)(C + (size_t)r * Nn + c + 4) = v1;
    }
}

// ---------------- dd = (data*norm) @ proj^T, 128x128 tile, 8x8/thread ----------------
__global__ void __launch_bounds__(256) dd128(
    const float* __restrict__ data, const float* __restrict__ proj, float* __restrict__ dd)
{
    __shared__ __align__(16) float As[16][128];
    __shared__ __align__(16) float Bs[16][128];
    int bh = blockIdx.z; int b = bh / GH, h = bh % GH;
    int n0 = blockIdx.y * 128, j0 = blockIdx.x * 128;
    int tid = threadIdx.x;
    int tx = tid & 15, ty = tid >> 4;
    ull acc[8][4] = {};
    const float NORM = 0.35355339059327373f;
    int a_row  = tid >> 2;        // 0..63
    int a_col4 = (tid & 3) * 4;   // 0,4,8,12
    const float* db = data + ((size_t)b * NN + n0) * DIMM + h * 64;
    const float* pb = proj + (size_t)j0 * 64;

    for (int k0 = 0; k0 < 64; k0 += 16) {
#pragma unroll
        for (int i = 0; i < 2; i++) {
            int r = a_row + i * 64;
            float4 va = *(const float4*)(db + (size_t)r * DIMM + k0 + a_col4);
            As[a_col4+0][r] = va.x * NORM; As[a_col4+1][r] = va.y * NORM;
            As[a_col4+2][r] = va.z * NORM; As[a_col4+3][r] = va.w * NORM;
            float4 vb = *(const float4*)(pb + (size_t)r * 64 + k0 + a_col4);
            Bs[a_col4+0][r] = vb.x; Bs[a_col4+1][r] = vb.y;
            Bs[a_col4+2][r] = vb.z; Bs[a_col4+3][r] = vb.w;
        }
        __syncthreads();
#pragma unroll
        for (int kk = 0; kk < 16; kk++) {
            float4 a0 = *(const float4*)&As[kk][ty*8];
            float4 a1 = *(const float4*)&As[kk][ty*8+4];
            ulonglong2 b01 = *(const ulonglong2*)&Bs[kk][tx*8];
            ulonglong2 b23 = *(const ulonglong2*)&Bs[kk][tx*8+4];
            float af[8] = {a0.x,a0.y,a0.z,a0.w,a1.x,a1.y,a1.z,a1.w};
#pragma unroll
            for (int i = 0; i < 8; i++) {
                ull aa = pk2(af[i]);
                acc[i][0] = ffma2(aa, b01.x, acc[i][0]);
                acc[i][1] = ffma2(aa, b01.y, acc[i][1]);
                acc[i][2] = ffma2(aa, b23.x, acc[i][2]);
                acc[i][3] = ffma2(aa, b23.y, acc[i][3]);
            }
        }
        __syncthreads();
    }
    float* ob = dd + ((size_t)bh * NN + n0 + ty * 8) * NBF + j0 + tx * 8;
#pragma unroll
    for (int i = 0; i < 8; i++) {
        *(float4*)(ob + (size_t)i * NBF)     = mk4(acc[i][0], acc[i][1]);
        *(float4*)(ob + (size_t)i * NBF + 4) = mk4(acc[i][2], acc[i][3]);
    }
}

// ---------------- k max reduction (two stage) ----------------
__global__ void kmax_part_kernel(const float* __restrict__ kdd, float* __restrict__ kpart)
{
    int bh = blockIdx.y, s = blockIdx.x;
    const int CH = NN * NBF / 64;
    const float* p = kdd + (size_t)bh * NN * NBF + (size_t)s * CH;
    float m = -1e30f;
    for (int i = threadIdx.x; i < CH; i += 256) m = fmaxf(m, p[i]);
#pragma unroll
    for (int o = 16; o > 0; o >>= 1) m = fmaxf(m, __shfl_xor_sync(0xffffffffu, m, o));
    __shared__ float red[8];
    if ((threadIdx.x & 31) == 0) red[threadIdx.x >> 5] = m;
    __syncthreads();
    if (threadIdx.x == 0) {
        float z = red[0];
#pragma unroll
        for (int i = 1; i < 8; i++) z = fmaxf(z, red[i]);
        kpart[bh * 64 + s] = z;
    }
}
__global__ void kmax_final_kernel(const float* __restrict__ kpart, float* __restrict__ kmax)
{
    int bh = blockIdx.x;
    float m = kpart[bh * 64 + threadIdx.x];
#pragma unroll
    for (int o = 16; o > 0; o >>= 1) m = fmaxf(m, __shfl_xor_sync(0xffffffffu, m, o));
    __shared__ float red[2];
    if ((threadIdx.x & 31) == 0) red[threadIdx.x >> 5] = m;
    __syncthreads();
    if (threadIdx.x == 0) kmax[bh] = fmaxf(red[0], red[1]);
}

// ---------------- qp/kp = ratio*(exp(dd - diag - m) + eps) ----------------
__global__ void qexp_kernel(const float* __restrict__ qdata, float* __restrict__ qp)
{
    int row = blockIdx.x * 8 + (threadIdx.x >> 5);
    int lane = threadIdx.x & 31;
    int bh = row >> 13, n = row & (NN - 1);
    int b = bh / GH, h = bh % GH;
    const float* dr = qdata + ((size_t)b * NN + n) * DIMM + h * 64;
    float2 v2 = *(const float2*)(dr + lane * 2);
    float sq = v2.x * v2.x + v2.y * v2.y;
#pragma unroll
    for (int o = 16; o > 0; o >>= 1) sq += __shfl_xor_sync(0xffffffffu, sq, o);
    float diag = sq * 0.0625f;
    float* pr = qp + (size_t)row * NBF;
    float vals[8]; float m = -1e30f;
#pragma unroll
    for (int i = 0; i < 8; i++) { vals[i] = pr[lane + i * 32]; m = fmaxf(m, vals[i]); }
#pragma unroll
    for (int o = 16; o > 0; o >>= 1) m = fmaxf(m, __shfl_xor_sync(0xffffffffu, m, o));
#pragma unroll
    for (int i = 0; i < 8; i++)
        pr[lane + i * 32] = 0.0625f * (expf(vals[i] - diag - m) + 1e-4f);
}
__global__ void kexp_kernel(const float* __restrict__ kdata, const float* __restrict__ kmax,
                            float* __restrict__ kp)
{
    int row = blockIdx.x * 8 + (threadIdx.x >> 5);
    int lane = threadIdx.x & 31;
    int bh = row >> 13, n = row & (NN - 1);
    int b = bh / GH, h = bh % GH;
    const float* dr = kdata + ((size_t)b * NN + n) * DIMM + h * 64;
    float2 v2 = *(const float2*)(dr + lane * 2);
    float sq = v2.x * v2.x + v2.y * v2.y;
#pragma unroll
    for (int o = 16; o > 0; o >>= 1) sq += __shfl_xor_sync(0xffffffffu, sq, o);
    float diag = sq * 0.0625f;
    float m = kmax[bh];
    float* pr = kp + (size_t)row * NBF;
#pragma unroll
    for (int i = 0; i < 8; i++)
        pr[lane + i * 32] = 0.0625f * (expf(pr[lane + i * 32] - diag - m) + 1e-4f);
}

// ---------------- ctx[j][d] = sum_n kp[n,j]*v[n,d]  (split-K, col 64 = k_sum) ----------------
__global__ void __launch_bounds__(256) ctx_partial_kernel(
    const float* __restrict__ kp, const float* __restrict__ v, float* __restrict__ part)
{
    int bh = blockIdx.x, sp = blockIdx.y;
    int b = bh / GH, h = bh % GH;
    int j = threadIdx.x;
    ull acc2[32] = {};
    float acc64 = 0.f;
    __shared__ __align__(16) float vs[16][68];
    const float* kpb = kp + ((size_t)bh * NN + sp * 512) * NBF + j;
    const float* vb = v + ((size_t)b * NN + sp * 512) * DIMM + h * 64;
    for (int n0 = 0; n0 < 512; n0 += 16) {
        __syncthreads();
        int r = threadIdx.x >> 4;
        int c = (threadIdx.x & 15) * 4;
        float4 vv = *(const float4*)(vb + (size_t)(n0 + r) * DIMM + c);
        *(float4*)&vs[r][c] = vv;
        __syncthreads();
#pragma unroll 2
        for (int nn = 0; nn < 16; nn++) {
            float p = kpb[(size_t)(n0 + nn) * NBF];
            ull pp = pk2(p);
            const ulonglong2* vr = (const ulonglong2*)&vs[nn][0];
#pragma unroll
            for (int d2 = 0; d2 < 16; d2++) {
                ulonglong2 t = vr[d2];
                acc2[d2*2]   = ffma2(pp, t.x, acc2[d2*2]);
                acc2[d2*2+1] = ffma2(pp, t.y, acc2[d2*2+1]);
            }
            acc64 += p;
        }
    }
    float* o = part + (((size_t)bh * NSPLIT + sp) * 256 + j) * 65;
#pragma unroll
    for (int d2 = 0; d2 < 32; d2++) {
        float2 t = upk(acc2[d2]);
        o[d2*2] = t.x; o[d2*2+1] = t.y;
    }
    o[64] = acc64;
}
__global__ void ctx_reduce_kernel(const float* __restrict__ part, float* __restrict__ ctx)
{
    int idx = blockIdx.x * 256 + threadIdx.x;
    if (idx >= BHG * 256 * 65) return;
    int bh = idx / (256 * 65); int rem = idx - bh * 256 * 65;
    int j = rem / 65, d = rem % 65;
    float s = 0.f;
#pragma unroll
    for (int sp = 0; sp < NSPLIT; sp++)
        s += part[(((size_t)bh * NSPLIT + sp) * 256 + j) * 65 + d];
    ctx[((size_t)bh * 256 + j) * 68 + d] = s;
}

// ---------------- d_inv = 1 / (qp . k_sum) ----------------
__global__ void denom_kernel(const float* __restrict__ qp, const float* __restrict__ ctx,
                             float* __restrict__ dinv)
{
    int row = blockIdx.x * 8 + (threadIdx.x >> 5);
    int lane = threadIdx.x & 31;
    int bh = row >> 13;
    const float* q = qp + (size_t)row * NBF;
    const float* ks = ctx + (size_t)bh * 256 * 68 + 64;
    float s = 0.f;
#pragma unroll
    for (int i = 0; i < 8; i++) s += q[lane + i * 32] * ks[(size_t)(lane + i * 32) * 68];
#pragma unroll
    for (int o = 16; o > 0; o >>= 1) s += __shfl_xor_sync(0xffffffffu, s, o);
    if (lane == 0) dinv[row] = 1.f / s;
}

// ---------------- out_g = (qp @ ctx) * d_inv -> att  (256x64 tile, 8x8/thread) ----------------
__global__ void __launch_bounds__(256) outg256(
    const float* __restrict__ qp, const float* __restrict__ ctx,
    const float* __restrict__ dinv, float* __restrict__ att)
{
    __shared__ __align__(16) float Qs[16][256];
    __shared__ __align__(16) float Cs[16][68];
    int bh = blockIdx.y; int b = bh / GH, h = bh % GH;
    int n0 = blockIdx.x * 256;
    int tid = threadIdx.x;
    int tx = tid & 7, ty = tid >> 3;   // ty 0..31 rows, tx 0..7 cols
    ull acc[8][4] = {};
    const float* qbase = qp + ((size_t)bh * NN + n0) * NBF;
    const float* cbase = ctx + (size_t)bh * 256 * 68;

    for (int k0 = 0; k0 < 256; k0 += 16) {
#pragma unroll
        for (int i = 0; i < 4; i++) {
            int idx = tid + i * 256;
            int r = idx >> 2, c4 = (idx & 3) * 4;
            float4 v = *(const float4*)(qbase + (size_t)r * NBF + k0 + c4);
            Qs[c4+0][r] = v.x; Qs[c4+1][r] = v.y; Qs[c4+2][r] = v.z; Qs[c4+3][r] = v.w;
        }
        {
            int r = tid >> 4, c4 = (tid & 15) * 4;
            float4 v = *(const float4*)(cbase + (size_t)(k0 + r) * 68 + c4);
            *(float4*)&Cs[r][c4] = v;
        }
        __syncthreads();
#pragma unroll
        for (int kk = 0; kk < 16; kk++) {
            float4 a0 = *(const float4*)&Qs[kk][ty*8];
            float4 a1 = *(const float4*)&Qs[kk][ty*8+4];
            ulonglong2 b01 = *(const ulonglong2*)&Cs[kk][tx*8];
            ulonglong2 b23 = *(const ulonglong2*)&Cs[kk][tx*8+4];
            float af[8] = {a0.x,a0.y,a0.z,a0.w,a1.x,a1.y,a1.z,a1.w};
#pragma unroll
            for (int i = 0; i < 8; i++) {
                ull aa = pk2(af[i]);
                acc[i][0] = ffma2(aa, b01.x, acc[i][0]);
                acc[i][1] = ffma2(aa, b01.y, acc[i][1]);
                acc[i][2] = ffma2(aa, b23.x, acc[i][2]);
                acc[i][3] = ffma2(aa, b23.y, acc[i][3]);
            }
        }
        __syncthreads();
    }
#pragma unroll
    for (int i = 0; i < 8; i++) {
        int n = n0 + ty * 8 + i;
        float di = dinv[(size_t)bh * NN + n];
        float4 v0 = mk4(acc[i][0], acc[i][1]);
        float4 v1 = mk4(acc[i][2], acc[i][3]);
        v0.x *= di; v0.y *= di; v0.z *= di; v0.w *= di;
        v1.x *= di; v1.y *= di; v1.z *= di; v1.w *= di;
        float* op = att + ((size_t)b * NN + n) * DIMM + h * 64 + tx * 8;
        *(float4*)op = v0;
        *(float4*)(op + 4) = v1;
    }
}

// ---------------- RoPE for local heads ----------------
__global__ void rope_kernel(const float* __restrict__ q, const float* __restrict__ k,
                            float* __restrict__ rq, float* __restrict__ rk)
{
    int idx = blockIdx.x * blockDim.x + threadIdx.x; // over BHL*NN*32
    int i = idx & 31;
    int n = (idx >> 5) & (NN - 1);
    int bh = idx >> 18;
    int b = bh >> 1, lh = bh & 1;
    float invf = (float)exp(-(double)(2 * i) / 64.0 * 9.210340371976184);
    float ang = (float)n * invf;
    float s, c;
    sincosf(ang, &s, &c);
    size_t base = ((size_t)b * NN + n) * DIMM + (GH + lh) * 64;
    float q1 = q[base + i], q2 = q[base + 32 + i];
    float k1 = k[base + i], k2 = k[base + 32 + i];
    size_t ob = ((size_t)bh * NN + n) * DH;
    rq[ob + i]      = q1 * c - q2 * s;
    rq[ob + 32 + i] = q2 * c + q1 * s;
    rk[ob + i]      = k1 * c - k2 * s;
    rk[ob + 32 + i] = k2 * c + k1 * s;
}

// ---------------- local scores (128x128 tile, 8x8/thread) ----------------
__global__ void __launch_bounds__(256) lscore128(
    const float* __restrict__ rq, const float* __restrict__ rk, float* __restrict__ sc)
{
    __shared__ __align__(16) float Qs[16][128];
    __shared__ __align__(16) float Ks[16][128];
    int bw = blockIdx.z; int bh = bw >> 5; int w = bw & 31;
    int m0 = blockIdx.y * 128, c0 = blockIdx.x * 128;
    int tid = threadIdx.x;
    int tx = tid & 15, ty = tid >> 4;
    int kwin = (w - 1) * WINSZ + c0;
    bool valid = (kwin >= 0) && (kwin < NN);   // uniform per 128-col block
    float* ob = sc + ((size_t)bw * WINSZ + m0 + ty * 8) * 768 + c0 + tx * 8;
    if (!valid) {
        float4 neg = make_float4(-1e9f, -1e9f, -1e9f, -1e9f);
#pragma unroll
        for (int i = 0; i < 8; i++) {
            *(float4*)(ob + (size_t)i * 768) = neg;
            *(float4*)(ob + (size_t)i * 768 + 4) = neg;
        }
        return;
    }
    ull acc[8][4] = {};
    int a_row  = tid >> 2;
    int a_col4 = (tid & 3) * 4;
    const float* qb = rq + ((size_t)bh * NN + w * WINSZ + m0) * DH;
    const float* kb = rk + ((size_t)bh * NN + kwin) * DH;

    for (int k0 = 0; k0 < 64; k0 += 16) {
#pragma unroll
        for (int i = 0; i < 2; i++) {
            int r = a_row + i * 64;
            float4 va = *(const float4*)(qb + (size_t)r * DH + k0 + a_col4);
            Qs[a_col4+0][r] = va.x; Qs[a_col4+1][r] = va.y;
            Qs[a_col4+2][r] = va.z; Qs[a_col4+3][r] = va.w;
            float4 vk = *(const float4*)(kb + (size_t)r * DH + k0 + a_col4);
            Ks[a_col4+0][r] = vk.x; Ks[a_col4+1][r] = vk.y;
            Ks[a_col4+2][r] = vk.z; Ks[a_col4+3][r] = vk.w;
        }
        __syncthreads();
#pragma unroll
        for (int kk = 0; kk < 16; kk++) {
            float4 a0 = *(const float4*)&Qs[kk][ty*8];
            float4 a1 = *(const float4*)&Qs[kk][ty*8+4];
            ulonglong2 b01 = *(const ulonglong2*)&Ks[kk][tx*8];
            ulonglong2 b23 = *(const ulonglong2*)&Ks[kk][tx*8+4];
            float af[8] = {a0.x,a0.y,a0.z,a0.w,a1.x,a1.y,a1.z,a1.w};
#pragma unroll
            for (int i = 0; i < 8; i++) {
                ull aa = pk2(af[i]);
                acc[i][0] = ffma2(aa, b01.x, acc[i][0]);
                acc[i][1] = ffma2(aa, b01.y, acc[i][1]);
                acc[i][2] = ffma2(aa, b23.x, acc[i][2]);
                acc[i][3] = ffma2(aa, b23.y, acc[i][3]);
            }
        }
        __syncthreads();
    }
#pragma unroll
    for (int i = 0; i < 8; i++) {
        float4 v0 = mk4(acc[i][0], acc[i][1]);
        float4 v1 = mk4(acc[i][2], acc[i][3]);
        v0.x *= 0.125f; v0.y *= 0.125f; v0.z *= 0.125f; v0.w *= 0.125f;
        v1.x *= 0.125f; v1.y *= 0.125f; v1.z *= 0.125f; v1.w *= 0.125f;
        *(float4*)(ob + (size_t)i * 768) = v0;
        *(float4*)(ob + (size_t)i * 768 + 4) = v1;
    }
}

// ---------------- softmax over 768 keys ----------------
__global__ void lsoftmax_kernel(float* __restrict__ sc)
{
    float* r = sc + (size_t)blockIdx.x * 768;
    int t = threadIdx.x;
    float v0 = r[t], v1 = r[t + 256], v2 = r[t + 512];
    float m = fmaxf(v0, fmaxf(v1, v2));
    __shared__ float red[8], red2[8];
#pragma unroll
    for (int o = 16; o > 0; o >>= 1) m = fmaxf(m, __shfl_xor_sync(0xffffffffu, m, o));
    if ((t & 31) == 0) red[t >> 5] = m;
    __syncthreads();
    float bm = fmaxf(fmaxf(fmaxf(red[0], red[1]), fmaxf(red[2], red[3])),
                     fmaxf(fmaxf(red[4], red[5]), fmaxf(red[6], red[7])));
    float e0 = expf(v0 - bm), e1 = expf(v1 - bm), e2 = expf(v2 - bm);
    float s = e0 + e1 + e2;
#pragma unroll
    for (int o = 16; o > 0; o >>= 1) s += __shfl_xor_sync(0xffffffffu, s, o);
    if ((t & 31) == 0) red2[t >> 5] = s;
    __syncthreads();
    float bs = red2[0]+red2[1]+red2[2]+red2[3]+red2[4]+red2[5]+red2[6]+red2[7];
    float inv = 1.f / bs;
    r[t] = e0 * inv; r[t + 256] = e1 * inv; r[t + 512] = e2 * inv;
}

// ---------------- out_l = attn @ bv3 -> att  (256x64 tile, 8x8/thread) ----------------
__global__ void __launch_bounds__(256) outl256(
    const float* __restrict__ sc, const float* __restrict__ v, float* __restrict__ att)
{
    __shared__ __align__(16) float As[16][256];
    __shared__ __align__(16) float Vs[16][68];
    int bw = blockIdx.x; int bh = bw >> 5; int w = bw & 31;
    int b = bh >> 1, lh = bh & 1;
    int tid = threadIdx.x;
    int tx = tid & 7, ty = tid >> 3;   // ty 0..31 rows, tx 0..7 cols
    ull acc[8][4] = {};
    const float* sb = sc + (size_t)bw * WINSZ * 768;
    const float* vb = v + (size_t)b * NN * DIMM + (GH + lh) * 64;

    for (int k0 = 0; k0 < 768; k0 += 16) {
#pragma unroll
        for (int i = 0; i < 4; i++) {
            int idx = tid + i * 256;
            int r = idx >> 2, c4 = (idx & 3) * 4;
            float4 a = *(const float4*)(sb + (size_t)r * 768 + k0 + c4);
            As[c4+0][r] = a.x; As[c4+1][r] = a.y; As[c4+2][r] = a.z; As[c4+3][r] = a.w;
        }
        {
            int r = tid >> 4, c4 = (tid & 15) * 4;
            int kn = (w - 1) * WINSZ + k0 + r;
            float4 vv = make_float4(0.f, 0.f, 0.f, 0.f);
            if ((unsigned)kn < (unsigned)NN)
                vv = *(const float4*)(vb + (size_t)kn * DIMM + c4);
            *(float4*)&Vs[r][c4] = vv;
        }
        __syncthreads();
#pragma unroll
        for (int kk = 0; kk < 16; kk++) {
            float4 a0 = *(const float4*)&As[kk][ty*8];
            float4 a1 = *(const float4*)&As[kk][ty*8+4];
            ulonglong2 b01 = *(const ulonglong2*)&Vs[kk][tx*8];
            ulonglong2 b23 = *(const ulonglong2*)&Vs[kk][tx*8+4];
            float af[8] = {a0.x,a0.y,a0.z,a0.w,a1.x,a1.y,a1.z,a1.w};
#pragma unroll
            for (int i = 0; i < 8; i++) {
                ull aa = pk2(af[i]);
                acc[i][0] = ffma2(aa, b01.x, acc[i][0]);
                acc[i][1] = ffma2(aa, b01.y, acc[i][1]);
                acc[i][2] = ffma2(aa, b23.x, acc[i][2]);
                acc[i][3] = ffma2(aa, b23.y, acc[i][3]);
            }
        }
        __syncthreads();
    }
#pragma unroll
    for (int i = 0; i < 8; i++) {
        int n = w * WINSZ + ty * 8 + i;
        float* op = att + ((size_t)b * NN + n) * DIMM + (GH + lh) * 64 + tx * 8;
        *(float4*)op = mk4(acc[i][0], acc[i][1]);
        *(float4*)(op + 4) = mk4(acc[i][2], acc[i][3]);
    }
}

// ---------------- launcher ----------------
extern "C" void kernel_launch(void* const* d_in, const int* in_sizes, int n_in,
                              void* d_out, int out_size)
{
    (void)in_sizes; (void)n_in; (void)out_size;
    const float* x    = (const float*)d_in[0];
    const float* Wq   = (const float*)d_in[1];
    const float* Wk   = (const float*)d_in[2];
    const float* Wv   = (const float*)d_in[3];
    const float* Wo   = (const float*)d_in[4];
    const float* bo   = (const float*)d_in[5];
    const float* proj = (const float*)d_in[6];
    float* out = (float*)d_out;

    float *q, *k, *v, *qp, *kp, *kmp, *km, *part, *ctx, *dinv, *att, *sc, *rq, *rk;
    cudaGetSymbolAddress((void**)&q, g_q);
    cudaGetSymbolAddress((void**)&k, g_k);
    cudaGetSymbolAddress((void**)&v, g_v);
    cudaGetSymbolAddress((void**)&qp, g_qp);
    cudaGetSymbolAddress((void**)&kp, g_kp);
    cudaGetSymbolAddress((void**)&kmp, g_kmaxp);
    cudaGetSymbolAddress((void**)&km, g_kmax);
    cudaGetSymbolAddress((void**)&part, g_part);
    cudaGetSymbolAddress((void**)&ctx, g_ctx);
    cudaGetSymbolAddress((void**)&dinv, g_dinv);
    cudaGetSymbolAddress((void**)&att, g_att);
    cudaGetSymbolAddress((void**)&sc, g_sc);
    cudaGetSymbolAddress((void**)&rq, g_rq);
    cudaGetSymbolAddress((void**)&rk, g_rk);

    const int M = BB * NN; // 16384
    dim3 gg(DIMM / 128, M / 128);
    sgemm128<<<gg, 256>>>(x, Wq, nullptr, q, M, DIMM, DIMM);
    sgemm128<<<gg, 256>>>(x, Wk, nullptr, k, M, DIMM, DIMM);
    sgemm128<<<gg, 256>>>(x, Wv, nullptr, v, M, DIMM, DIMM);

    dim3 gdd(NBF / 128, NN / 128, BHG);
    dd128<<<gdd, 256>>>(q, proj, qp);
    dd128<<<gdd, 256>>>(k, proj, kp);

    kmax_part_kernel<<<dim3(64, BHG), 256>>>(kp, kmp);
    kmax_final_kernel<<<BHG, 64>>>(kmp, km);

    qexp_kernel<<<BHG * NN / 8, 256>>>(q, qp);
    kexp_kernel<<<BHG * NN / 8, 256>>>(k, km, kp);

    ctx_partial_kernel<<<dim3(BHG, NSPLIT), 256>>>(kp, v, part);
    ctx_reduce_kernel<<<(BHG * 256 * 65 + 255) / 256, 256>>>(part, ctx);

    denom_kernel<<<BHG * NN / 8, 256>>>(qp, ctx, dinv);
    outg256<<<dim3(NN / 256, BHG), 256>>>(qp, ctx, dinv, att);

    rope_kernel<<<BHL * NN * 32 / 256, 256>>>(q, k, rq, rk);
    lscore128<<<dim3(6, 2, BHL * NWIN), 256>>>(rq, rk, sc);
    lsoftmax_kernel<<<BHL * NWIN * WINSZ, 256>>>(sc);
    outl256<<<BHL * NWIN, 256>>>(sc, v, att);

    sgemm128<<<gg, 256>>>(att, Wo, bo, out, M, DIMM, DIMM);
}

// round 8
// speedup vs baseline: 1.1146x; 1.1146x over previous
#include <cuda_runtime.h>
#include <math.h>
#include <stdint.h>

#define BB 2
#define NN 8192
#define DIMM 512
#define GH 6
#define DH 64
#define NBF 256
#define NWIN 32
#define WINSZ 256
#define BHG (BB*GH)      // 12
#define BHL 4            // B * LOCAL_HEADS
#define NSPLIT 16

// ---------------- scratch (device globals: alloc-free) ----------------
__device__ float g_q[BB*NN*DIMM];
__device__ float g_k[BB*NN*DIMM];
__device__ float g_v[BB*NN*DIMM];
__device__ float g_qp[BHG*NN*NBF];
__device__ float g_kp[BHG*NN*NBF];
__device__ float g_kmaxp[BHG*64];
__device__ float g_kmax[BHG];
__device__ float g_part[BHG*NSPLIT*256*65];
__device__ float g_ctx[BHG*256*68];
__device__ float g_dinv[BHG*NN];
__device__ float g_att[BB*NN*DIMM];
__device__ float g_sc[(size_t)BHL*NWIN*WINSZ*768];
__device__ float g_rq[BHL*NN*DH];
__device__ float g_rk[BHL*NN*DH];

// ================= 3xTF32 tensor-core GEMM (mma.sync m16n8k8) =================
// C[M][Nn] = A[M][K] @ Bm[K][Nn] (+bias). CTA tile 128x64, K-chunk 16.
__device__ __forceinline__ void split_tf32(float x, float& h, float& l) {
    uint32_t u;
    asm("cvt.rna.tf32.f32 %0, %1;" : "=r"(u) : "f"(x));
    h = __uint_as_float(u);
    l = x - h;
}
__device__ __forceinline__ void mma_tf32(float* c, const uint32_t* a, const uint32_t* b) {
    asm volatile(
        "mma.sync.aligned.m16n8k8.row.col.f32.tf32.tf32.f32 "
        "{%0,%1,%2,%3}, {%4,%5,%6,%7}, {%8,%9}, {%0,%1,%2,%3};"
        : "+f"(c[0]), "+f"(c[1]), "+f"(c[2]), "+f"(c[3])
        : "r"(a[0]), "r"(a[1]), "r"(a[2]), "r"(a[3]), "r"(b[0]), "r"(b[1]));
}

__global__ void __launch_bounds__(256) gemm_tc(
    const float* __restrict__ A, const float* __restrict__ Bm,
    const float* __restrict__ bias, float* __restrict__ C,
    int M, int Nn, int K)
{
    __shared__ float Ah[128][17], Al[128][17];
    __shared__ float Bh[16][72], Bl[16][72];
    int tid = threadIdx.x;
    int wid = tid >> 5, lane = tid & 31;
    int wm = wid >> 1, wn = wid & 1;       // warp grid 4(m) x 2(n)
    int m0 = blockIdx.y * 128, n0 = blockIdx.x * 64;
    float acc[2][4][4] = {};

    int ar = tid >> 1, ac = (tid & 1) * 8; // A stage: 2 float4 per thread
    int br = tid >> 4, bc = (tid & 15) * 4; // B stage: 1 float4 per thread
    int r = lane >> 2, cq = lane & 3;

    for (int k0 = 0; k0 < K; k0 += 16) {
        __syncthreads();
        {
            const float* ap = A + (size_t)(m0 + ar) * K + k0 + ac;
            float4 v0 = *(const float4*)ap;
            float4 v1 = *(const float4*)(ap + 4);
            float va[8] = {v0.x, v0.y, v0.z, v0.w, v1.x, v1.y, v1.z, v1.w};
#pragma unroll
            for (int i = 0; i < 8; i++) {
                float h, l;
                split_tf32(va[i], h, l);
                Ah[ar][ac + i] = h;
                Al[ar][ac + i] = l;
            }
            float4 vb = *(const float4*)(Bm + (size_t)(k0 + br) * Nn + n0 + bc);
            float vbb[4] = {vb.x, vb.y, vb.z, vb.w};
#pragma unroll
            for (int i = 0; i < 4; i++) {
                float h, l;
                split_tf32(vbb[i], h, l);
                Bh[br][bc + i] = h;
                Bl[br][bc + i] = l;
            }
        }
        __syncthreads();
#pragma unroll
        for (int k8 = 0; k8 < 16; k8 += 8) {
            uint32_t afh[2][4], afl[2][4], bfh[4][2], bfl[4][2];
#pragma unroll
            for (int mt = 0; mt < 2; mt++) {
                int base = wm * 32 + mt * 16;
                afh[mt][0] = __float_as_uint(Ah[base + r][k8 + cq]);
                afh[mt][1] = __float_as_uint(Ah[base + r + 8][k8 + cq]);
                afh[mt][2] = __float_as_uint(Ah[base + r][k8 + cq + 4]);
                afh[mt][3] = __float_as_uint(Ah[base + r + 8][k8 + cq + 4]);
                afl[mt][0] = __float_as_uint(Al[base + r][k8 + cq]);
                afl[mt][1] = __float_as_uint(Al[base + r + 8][k8 + cq]);
                afl[mt][2] = __float_as_uint(Al[base + r][k8 + cq + 4]);
                afl[mt][3] = __float_as_uint(Al[base + r + 8][k8 + cq + 4]);
            }
#pragma unroll
            for (int nt = 0; nt < 4; nt++) {
                int col = wn * 32 + nt * 8 + r;
                bfh[nt][0] = __float_as_uint(Bh[k8 + cq][col]);
                bfh[nt][1] = __float_as_uint(Bh[k8 + cq + 4][col]);
                bfl[nt][0] = __float_as_uint(Bl[k8 + cq][col]);
                bfl[nt][1] = __float_as_uint(Bl[k8 + cq + 4][col]);
            }
#pragma unroll
            for (int mt = 0; mt < 2; mt++)
#pragma unroll
                for (int nt = 0; nt < 4; nt++) {
                    mma_tf32(acc[mt][nt], afh[mt], bfh[nt]);
                    mma_tf32(acc[mt][nt], afh[mt], bfl[nt]);
                    mma_tf32(acc[mt][nt], afl[mt], bfh[nt]);
                }
        }
    }
    // epilogue
#pragma unroll
    for (int mt = 0; mt < 2; mt++)
#pragma unroll
        for (int nt = 0; nt < 4; nt++) {
            int row = m0 + wm * 32 + mt * 16 + r;
            int col = n0 + wn * 32 + nt * 8 + 2 * cq;
            float2 v0 = make_float2(acc[mt][nt][0], acc[mt][nt][1]);
            float2 v1 = make_float2(acc[mt][nt][2], acc[mt][nt][3]);
            if (bias) {
                float2 bv = *(const float2*)(bias + col);
                v0.x += bv.x; v0.y += bv.y;
                v1.x += bv.x; v1.y += bv.y;
            }
            *(float2*)(C + (size_t)row * Nn + col) = v0;
            *(float2*)(C + (size_t)(row + 8) * Nn + col) = v1;
        }
}

// ---------------- dd = (data*norm) @ proj^T  per global head ----------------
__global__ void __launch_bounds__(256) dd_kernel(
    const float* __restrict__ data, const float* __restrict__ proj, float* __restrict__ dd)
{
    __shared__ __align__(16) float As[64][68];
    __shared__ __align__(16) float Bs[64][68];
    int bh = blockIdx.z; int b = bh / GH, h = bh % GH;
    int n0 = blockIdx.y * 64, j0 = blockIdx.x * 64;
    int tid = threadIdx.x;
    int lr = tid >> 2, lc4 = (tid & 3) * 4;
    const float* db = data + ((size_t)b * NN + n0) * DIMM + h * 64;
    const float* pb = proj + (size_t)j0 * 64;
    const float NORM = 0.35355339059327373f;
#pragma unroll
    for (int i = 0; i < 4; i++) {
        int c = lc4 + i * 16;
        float4 va = *(const float4*)(db + (size_t)lr * DIMM + c);
        As[c+0][lr] = va.x * NORM; As[c+1][lr] = va.y * NORM;
        As[c+2][lr] = va.z * NORM; As[c+3][lr] = va.w * NORM;
        float4 vb = *(const float4*)(pb + (size_t)lr * 64 + c);
        Bs[c+0][lr] = vb.x; Bs[c+1][lr] = vb.y; Bs[c+2][lr] = vb.z; Bs[c+3][lr] = vb.w;
    }
    __syncthreads();
    int tx = tid & 15, ty = tid >> 4;
    float acc[4][4] = {};
#pragma unroll
    for (int kk = 0; kk < 64; kk++) {
        float4 a  = *(const float4*)&As[kk][ty*4];
        float4 bv = *(const float4*)&Bs[kk][tx*4];
        float av[4] = {a.x,a.y,a.z,a.w}, bb[4] = {bv.x,bv.y,bv.z,bv.w};
#pragma unroll
        for (int i = 0; i < 4; i++)
#pragma unroll
            for (int j = 0; j < 4; j++) acc[i][j] += av[i] * bb[j];
    }
    float* ob = dd + ((size_t)bh * NN + n0) * NBF + j0;
#pragma unroll
    for (int i = 0; i < 4; i++) {
        float4 o = {acc[i][0], acc[i][1], acc[i][2], acc[i][3]};
        *(float4*)(ob + (size_t)(ty*4+i) * NBF + tx*4) = o;
    }
}

// ---------------- k max reduction (two stage) ----------------
__global__ void kmax_part_kernel(const float* __restrict__ kdd, float* __restrict__ kpart)
{
    int bh = blockIdx.y, s = blockIdx.x;
    const int CH = NN * NBF / 64;
    const float* p = kdd + (size_t)bh * NN * NBF + (size_t)s * CH;
    float m = -1e30f;
    for (int i = threadIdx.x; i < CH; i += 256) m = fmaxf(m, p[i]);
#pragma unroll
    for (int o = 16; o > 0; o >>= 1) m = fmaxf(m, __shfl_xor_sync(0xffffffffu, m, o));
    __shared__ float red[8];
    if ((threadIdx.x & 31) == 0) red[threadIdx.x >> 5] = m;
    __syncthreads();
    if (threadIdx.x == 0) {
        float z = red[0];
#pragma unroll
        for (int i = 1; i < 8; i++) z = fmaxf(z, red[i]);
        kpart[bh * 64 + s] = z;
    }
}
__global__ void kmax_final_kernel(const float* __restrict__ kpart, float* __restrict__ kmax)
{
    int bh = blockIdx.x;
    float m = kpart[bh * 64 + threadIdx.x];
#pragma unroll
    for (int o = 16; o > 0; o >>= 1) m = fmaxf(m, __shfl_xor_sync(0xffffffffu, m, o));
    __shared__ float red[2];
    if ((threadIdx.x & 31) == 0) red[threadIdx.x >> 5] = m;
    __syncthreads();
    if (threadIdx.x == 0) kmax[bh] = fmaxf(red[0], red[1]);
}

// ---------------- qp/kp = ratio*(exp(dd - diag - m) + eps) ----------------
__global__ void qexp_kernel(const float* __restrict__ qdata, float* __restrict__ qp)
{
    int row = blockIdx.x * 8 + (threadIdx.x >> 5);
    int lane = threadIdx.x & 31;
    int bh = row >> 13, n = row & (NN - 1);
    int b = bh / GH, h = bh % GH;
    const float* dr = qdata + ((size_t)b * NN + n) * DIMM + h * 64;
    float2 v2 = *(const float2*)(dr + lane * 2);
    float sq = v2.x * v2.x + v2.y * v2.y;
#pragma unroll
    for (int o = 16; o > 0; o >>= 1) sq += __shfl_xor_sync(0xffffffffu, sq, o);
    float diag = sq * 0.0625f;
    float* pr = qp + (size_t)row * NBF;
    float vals[8]; float m = -1e30f;
#pragma unroll
    for (int i = 0; i < 8; i++) { vals[i] = pr[lane + i * 32]; m = fmaxf(m, vals[i]); }
#pragma unroll
    for (int o = 16; o > 0; o >>= 1) m = fmaxf(m, __shfl_xor_sync(0xffffffffu, m, o));
#pragma unroll
    for (int i = 0; i < 8; i++)
        pr[lane + i * 32] = 0.0625f * (expf(vals[i] - diag - m) + 1e-4f);
}
__global__ void kexp_kernel(const float* __restrict__ kdata, const float* __restrict__ kmax,
                            float* __restrict__ kp)
{
    int row = blockIdx.x * 8 + (threadIdx.x >> 5);
    int lane = threadIdx.x & 31;
    int bh = row >> 13, n = row & (NN - 1);
    int b = bh / GH, h = bh % GH;
    const float* dr = kdata + ((size_t)b * NN + n) * DIMM + h * 64;
    float2 v2 = *(const float2*)(dr + lane * 2);
    float sq = v2.x * v2.x + v2.y * v2.y;
#pragma unroll
    for (int o = 16; o > 0; o >>= 1) sq += __shfl_xor_sync(0xffffffffu, sq, o);
    float diag = sq * 0.0625f;
    float m = kmax[bh];
    float* pr = kp + (size_t)row * NBF;
#pragma unroll
    for (int i = 0; i < 8; i++)
        pr[lane + i * 32] = 0.0625f * (expf(pr[lane + i * 32] - diag - m) + 1e-4f);
}

// ---------------- ctx[j][d] = sum_n kp[n,j]*v[n,d]  (split-K, col 64 = k_sum) ----------------
__global__ void __launch_bounds__(256) ctx_partial_kernel(
    const float* __restrict__ kp, const float* __restrict__ v, float* __restrict__ part)
{
    int bh = blockIdx.x, sp = blockIdx.y;
    int b = bh / GH, h = bh % GH;
    int j = threadIdx.x;
    float acc[65];
#pragma unroll
    for (int d = 0; d < 65; d++) acc[d] = 0.f;
    __shared__ __align__(16) float vs[16][68];
    const float* kpb = kp + ((size_t)bh * NN + sp * 512) * NBF + j;
    const float* vb = v + ((size_t)b * NN + sp * 512) * DIMM + h * 64;
    for (int n0 = 0; n0 < 512; n0 += 16) {
        __syncthreads();
        int r = threadIdx.x >> 4;
        int c = (threadIdx.x & 15) * 4;
        float4 vv = *(const float4*)(vb + (size_t)(n0 + r) * DIMM + c);
        *(float4*)&vs[r][c] = vv;
        if ((threadIdx.x & 15) == 0) vs[r][64] = 1.f;
        __syncthreads();
#pragma unroll 2
        for (int nn = 0; nn < 16; nn++) {
            float p = kpb[(size_t)(n0 + nn) * NBF];
#pragma unroll
            for (int d = 0; d < 65; d++) acc[d] += p * vs[nn][d];
        }
    }
    float* o = part + (((size_t)bh * NSPLIT + sp) * 256 + j) * 65;
#pragma unroll
    for (int d = 0; d < 65; d++) o[d] = acc[d];
}
__global__ void ctx_reduce_kernel(const float* __restrict__ part, float* __restrict__ ctx)
{
    int idx = blockIdx.x * 256 + threadIdx.x;
    if (idx >= BHG * 256 * 65) return;
    int bh = idx / (256 * 65); int rem = idx - bh * 256 * 65;
    int j = rem / 65, d = rem % 65;
    float s = 0.f;
#pragma unroll
    for (int sp = 0; sp < NSPLIT; sp++)
        s += part[(((size_t)bh * NSPLIT + sp) * 256 + j) * 65 + d];
    ctx[((size_t)bh * 256 + j) * 68 + d] = s;
}

// ---------------- d_inv = 1 / (qp . k_sum) ----------------
__global__ void denom_kernel(const float* __restrict__ qp, const float* __restrict__ ctx,
                             float* __restrict__ dinv)
{
    int row = blockIdx.x * 8 + (threadIdx.x >> 5);
    int lane = threadIdx.x & 31;
    int bh = row >> 13;
    const float* q = qp + (size_t)row * NBF;
    const float* ks = ctx + (size_t)bh * 256 * 68 + 64;
    float s = 0.f;
#pragma unroll
    for (int i = 0; i < 8; i++) s += q[lane + i * 32] * ks[(size_t)(lane + i * 32) * 68];
#pragma unroll
    for (int o = 16; o > 0; o >>= 1) s += __shfl_xor_sync(0xffffffffu, s, o);
    if (lane == 0) dinv[row] = 1.f / s;
}

// ---------------- out_g = (qp @ ctx) * d_inv -> att ----------------
__global__ void __launch_bounds__(256) outg_kernel(
    const float* __restrict__ qp, const float* __restrict__ ctx,
    const float* __restrict__ dinv, float* __restrict__ att)
{
    __shared__ __align__(16) float Qs[32][68];
    __shared__ __align__(16) float Cs[32][68];
    int bh = blockIdx.y; int b = bh / GH, h = bh % GH;
    int n0 = blockIdx.x * 64;
    int tid = threadIdx.x;
    int tx = tid & 15, ty = tid >> 4;
    float acc[4][4] = {};
    const float* qbase = qp + ((size_t)bh * NN + n0) * NBF;
    const float* cbase = ctx + (size_t)bh * 256 * 68;
    for (int k0 = 0; k0 < 256; k0 += 32) {
        int r = tid >> 3, c4 = (tid & 7) * 4;
#pragma unroll
        for (int i = 0; i < 2; i++) {
            float4 v = *(const float4*)(qbase + (size_t)(r + i * 32) * NBF + k0 + c4);
            Qs[c4+0][r+i*32] = v.x; Qs[c4+1][r+i*32] = v.y;
            Qs[c4+2][r+i*32] = v.z; Qs[c4+3][r+i*32] = v.w;
        }
        int cr = tid >> 4, cc4 = (tid & 15) * 4;
#pragma unroll
        for (int i = 0; i < 2; i++) {
            float4 v = *(const float4*)(cbase + (size_t)(k0 + cr + i * 16) * 68 + cc4);
            *(float4*)&Cs[cr + i * 16][cc4] = v;
        }
        __syncthreads();
#pragma unroll
        for (int kk = 0; kk < 32; kk++) {
            float4 a  = *(const float4*)&Qs[kk][ty*4];
            float4 bv = *(const float4*)&Cs[kk][tx*4];
            float av[4] = {a.x,a.y,a.z,a.w}, bb[4] = {bv.x,bv.y,bv.z,bv.w};
#pragma unroll
            for (int i = 0; i < 4; i++)
#pragma unroll
                for (int j = 0; j < 4; j++) acc[i][j] += av[i] * bb[j];
        }
        __syncthreads();
    }
#pragma unroll
    for (int i = 0; i < 4; i++) {
        int n = n0 + ty * 4 + i;
        float di = dinv[(size_t)bh * NN + n];
        float4 o = {acc[i][0]*di, acc[i][1]*di, acc[i][2]*di, acc[i][3]*di};
        *(float4*)(att + ((size_t)b * NN + n) * DIMM + h * 64 + tx * 4) = o;
    }
}

// ---------------- RoPE for local heads ----------------
__global__ void rope_kernel(const float* __restrict__ q, const float* __restrict__ k,
                            float* __restrict__ rq, float* __restrict__ rk)
{
    int idx = blockIdx.x * blockDim.x + threadIdx.x; // over BHL*NN*32
    int i = idx & 31;
    int n = (idx >> 5) & (NN - 1);
    int bh = idx >> 18;
    int b = bh >> 1, lh = bh & 1;
    float invf = (float)exp(-(double)(2 * i) / 64.0 * 9.210340371976184);
    float ang = (float)n * invf;
    float s, c;
    sincosf(ang, &s, &c);
    size_t base = ((size_t)b * NN + n) * DIMM + (GH + lh) * 64;
    float q1 = q[base + i], q2 = q[base + 32 + i];
    float k1 = k[base + i], k2 = k[base + 32 + i];
    size_t ob = ((size_t)bh * NN + n) * DH;
    rq[ob + i]      = q1 * c - q2 * s;
    rq[ob + 32 + i] = q2 * c + q1 * s;
    rk[ob + i]      = k1 * c - k2 * s;
    rk[ob + 32 + i] = k2 * c + k1 * s;
}

// ---------------- local scores = 0.125 * bq @ bk3^T with masking ----------------
__global__ void __launch_bounds__(256) lscore_kernel(
    const float* __restrict__ rq, const float* __restrict__ rk, float* __restrict__ sc)
{
    __shared__ __align__(16) float Qs[64][68];
    __shared__ __align__(16) float Ks[64][68];
    int bw = blockIdx.z; int bh = bw >> 5; int w = bw & 31;
    int m0 = blockIdx.y * 64, c0 = blockIdx.x * 64;
    int tid = threadIdx.x;
    int lr = tid >> 2, lc4 = (tid & 3) * 4;
    const float* qb = rq + ((size_t)bh * NN + w * WINSZ + m0) * DH;
    const float* kb = rk + (size_t)bh * NN * DH;
    int knr = (w - 1) * WINSZ + c0 + lr;
    bool kvalid = (unsigned)knr < (unsigned)NN;
#pragma unroll
    for (int i = 0; i < 4; i++) {
        int c = lc4 + i * 16;
        float4 va = *(const float4*)(qb + (size_t)lr * DH + c);
        Qs[c+0][lr] = va.x; Qs[c+1][lr] = va.y; Qs[c+2][lr] = va.z; Qs[c+3][lr] = va.w;
        float4 vk = make_float4(0.f, 0.f, 0.f, 0.f);
        if (kvalid) vk = *(const float4*)(kb + (size_t)knr * DH + c);
        Ks[c+0][lr] = vk.x; Ks[c+1][lr] = vk.y; Ks[c+2][lr] = vk.z; Ks[c+3][lr] = vk.w;
    }
    __syncthreads();
    int tx = tid & 15, ty = tid >> 4;
    float acc[4][4] = {};
#pragma unroll
    for (int kk = 0; kk < 64; kk++) {
        float4 a  = *(const float4*)&Qs[kk][ty*4];
        float4 bv = *(const float4*)&Ks[kk][tx*4];
        float av[4] = {a.x,a.y,a.z,a.w}, bb[4] = {bv.x,bv.y,bv.z,bv.w};
#pragma unroll
        for (int i = 0; i < 4; i++)
#pragma unroll
            for (int j = 0; j < 4; j++) acc[i][j] += av[i] * bb[j];
    }
    int kn0 = (w - 1) * WINSZ + c0 + tx * 4;
    bool valid = (unsigned)kn0 < (unsigned)NN;
    float* ob = sc + ((size_t)bw * WINSZ + m0) * 768 + c0;
#pragma unroll
    for (int i = 0; i < 4; i++) {
        float4 o;
        o.x = valid ? acc[i][0] * 0.125f : -1e9f;
        o.y = valid ? acc[i][1] * 0.125f : -1e9f;
        o.z = valid ? acc[i][2] * 0.125f : -1e9f;
        o.w = valid ? acc[i][3] * 0.125f : -1e9f;
        *(float4*)(ob + (size_t)(ty * 4 + i) * 768 + tx * 4) = o;
    }
}

// ---------------- softmax over 768 keys ----------------
__global__ void lsoftmax_kernel(float* __restrict__ sc)
{
    float* r = sc + (size_t)blockIdx.x * 768;
    int t = threadIdx.x;
    float v0 = r[t], v1 = r[t + 256], v2 = r[t + 512];
    float m = fmaxf(v0, fmaxf(v1, v2));
    __shared__ float red[8], red2[8];
#pragma unroll
    for (int o = 16; o > 0; o >>= 1) m = fmaxf(m, __shfl_xor_sync(0xffffffffu, m, o));
    if ((t & 31) == 0) red[t >> 5] = m;
    __syncthreads();
    float bm = fmaxf(fmaxf(fmaxf(red[0], red[1]), fmaxf(red[2], red[3])),
                     fmaxf(fmaxf(red[4], red[5]), fmaxf(red[6], red[7])));
    float e0 = expf(v0 - bm), e1 = expf(v1 - bm), e2 = expf(v2 - bm);
    float s = e0 + e1 + e2;
#pragma unroll
    for (int o = 16; o > 0; o >>= 1) s += __shfl_xor_sync(0xffffffffu, s, o);
    if ((t & 31) == 0) red2[t >> 5] = s;
    __syncthreads();
    float bs = red2[0]+red2[1]+red2[2]+red2[3]+red2[4]+red2[5]+red2[6]+red2[7];
    float inv = 1.f / bs;
    r[t] = e0 * inv; r[t + 256] = e1 * inv; r[t + 512] = e2 * inv;
}

// ---------------- out_l = attn @ bv3 -> att ----------------
__global__ void __launch_bounds__(256) outl_kernel(
    const float* __restrict__ sc, const float* __restrict__ v, float* __restrict__ att)
{
    __shared__ __align__(16) float As[32][68];
    __shared__ __align__(16) float Vs[32][68];
    int bw = blockIdx.y; int bh = bw >> 5; int w = bw & 31;
    int b = bh >> 1, lh = bh & 1;
    int m0 = blockIdx.x * 64;
    int tid = threadIdx.x;
    int tx = tid & 15, ty = tid >> 4;
    float acc[4][4] = {};
    const float* sb = sc + ((size_t)bw * WINSZ + m0) * 768;
    const float* vb = v + (size_t)b * NN * DIMM + (GH + lh) * 64;
    for (int k0 = 0; k0 < 768; k0 += 32) {
#pragma unroll
        for (int i = 0; i < 2; i++) {
            int s1 = tid + i * 256;
            {
                int r = s1 >> 3, c4 = (s1 & 7) * 4;
                float4 a = *(const float4*)(sb + (size_t)r * 768 + k0 + c4);
                As[c4+0][r] = a.x; As[c4+1][r] = a.y; As[c4+2][r] = a.z; As[c4+3][r] = a.w;
            }
            {
                int kr = s1 >> 4, c4 = (s1 & 15) * 4;
                int kn = (w - 1) * WINSZ + k0 + kr;
                float4 vv = make_float4(0.f, 0.f, 0.f, 0.f);
                if ((unsigned)kn < (unsigned)NN)
                    vv = *(const float4*)(vb + (size_t)kn * DIMM + c4);
                *(float4*)&Vs[kr][c4] = vv;
            }
        }
        __syncthreads();
#pragma unroll
        for (int kk = 0; kk < 32; kk++) {
            float4 a  = *(const float4*)&As[kk][ty*4];
            float4 bv = *(const float4*)&Vs[kk][tx*4];
            float av[4] = {a.x,a.y,a.z,a.w}, bb[4] = {bv.x,bv.y,bv.z,bv.w};
#pragma unroll
            for (int i = 0; i < 4; i++)
#pragma unroll
                for (int j = 0; j < 4; j++) acc[i][j] += av[i] * bb[j];
        }
        __syncthreads();
    }
#pragma unroll
    for (int i = 0; i < 4; i++) {
        int n = w * WINSZ + m0 + ty * 4 + i;
        float4 o = {acc[i][0], acc[i][1], acc[i][2], acc[i][3]};
        *(float4*)(att + ((size_t)b * NN + n) * DIMM + (GH + lh) * 64 + tx * 4) = o;
    }
}

// ---------------- launcher ----------------
extern "C" void kernel_launch(void* const* d_in, const int* in_sizes, int n_in,
                              void* d_out, int out_size)
{
    (void)in_sizes; (void)n_in; (void)out_size;
    const float* x    = (const float*)d_in[0];
    const float* Wq   = (const float*)d_in[1];
    const float* Wk   = (const float*)d_in[2];
    const float* Wv   = (const float*)d_in[3];
    const float* Wo   = (const float*)d_in[4];
    const float* bo   = (const float*)d_in[5];
    const float* proj = (const float*)d_in[6];
    float* out = (float*)d_out;

    float *q, *k, *v, *qp, *kp, *kmp, *km, *part, *ctx, *dinv, *att, *sc, *rq, *rk;
    cudaGetSymbolAddress((void**)&q, g_q);
    cudaGetSymbolAddress((void**)&k, g_k);
    cudaGetSymbolAddress((void**)&v, g_v);
    cudaGetSymbolAddress((void**)&qp, g_qp);
    cudaGetSymbolAddress((void**)&kp, g_kp);
    cudaGetSymbolAddress((void**)&kmp, g_kmaxp);
    cudaGetSymbolAddress((void**)&km, g_kmax);
    cudaGetSymbolAddress((void**)&part, g_part);
    cudaGetSymbolAddress((void**)&ctx, g_ctx);
    cudaGetSymbolAddress((void**)&dinv, g_dinv);
    cudaGetSymbolAddress((void**)&att, g_att);
    cudaGetSymbolAddress((void**)&sc, g_sc);
    cudaGetSymbolAddress((void**)&rq, g_rq);
    cudaGetSymbolAddress((void**)&rk, g_rk);

    const int M = BB * NN; // 16384
    dim3 gt(DIMM / 64, M / 128);
    gemm_tc<<<gt, 256>>>(x, Wq, nullptr, q, M, DIMM, DIMM);
    gemm_tc<<<gt, 256>>>(x, Wk, nullptr, k, M, DIMM, DIMM);
    gemm_tc<<<gt, 256>>>(x, Wv, nullptr, v, M, DIMM, DIMM);

    dim3 gdd(NBF / 64, NN / 64, BHG);
    dd_kernel<<<gdd, 256>>>(q, proj, qp);
    dd_kernel<<<gdd, 256>>>(k, proj, kp);

    kmax_part_kernel<<<dim3(64, BHG), 256>>>(kp, kmp);
    kmax_final_kernel<<<BHG, 64>>>(kmp, km);

    qexp_kernel<<<BHG * NN / 8, 256>>>(q, qp);
    kexp_kernel<<<BHG * NN / 8, 256>>>(k, km, kp);

    ctx_partial_kernel<<<dim3(BHG, NSPLIT), 256>>>(kp, v, part);
    ctx_reduce_kernel<<<(BHG * 256 * 65 + 255) / 256, 256>>>(part, ctx);

    denom_kernel<<<BHG * NN / 8, 256>>>(qp, ctx, dinv);
    outg_kernel<<<dim3(NN / 64, BHG), 256>>>(qp, ctx, dinv, att);

    rope_kernel<<<BHL * NN * 32 / 256, 256>>>(q, k, rq, rk);
    lscore_kernel<<<dim3(12, 4, BHL * NWIN), 256>>>(rq, rk, sc);
    lsoftmax_kernel<<<BHL * NWIN * WINSZ, 256>>>(sc);
    outl_kernel<<<dim3(4, BHL * NWIN), 256>>>(sc, v, att);

    gemm_tc<<<gt, 256>>>(att, Wo, bo, out, M, DIMM, DIMM);
}

// round 9
// speedup vs baseline: 1.1487x; 1.0307x over previous
#include <cuda_runtime.h>
#include <math.h>
#include <stdint.h>

#define BB 2
#define NN 8192
#define DIMM 512
#define GH 6
#define DH 64
#define NBF 256
#define NWIN 32
#define WINSZ 256
#define BHG (BB*GH)      // 12
#define BHL 4            // B * LOCAL_HEADS
#define NSPLIT 32

// ---------------- scratch (device globals: alloc-free) ----------------
__device__ float g_q[BB*NN*DIMM];
__device__ float g_k[BB*NN*DIMM];
__device__ float g_v[BB*NN*DIMM];
__device__ float g_qp[BHG*NN*NBF];
__device__ float g_kp[BHG*NN*NBF];      // raw k dd scores
__device__ float g_kdiag[BHG*NN];
__device__ float g_kmaxp[BHG*128];
__device__ float g_kmax[BHG];
__device__ float g_part[BHG*NSPLIT*256*65];
__device__ float g_ctx[BHG*256*68];
__device__ float g_dinv[BHG*NN];
__device__ float g_att[BB*NN*DIMM];
__device__ float g_sc[(size_t)BHL*NWIN*WINSZ*768];
__device__ float g_rq[BHL*NN*DH];
__device__ float g_rk[BHL*NN*DH];
__device__ float g_rowm[BHL*NWIN*WINSZ];
__device__ float g_rows[BHL*NWIN*WINSZ];

// ================= 3xTF32 tensor-core GEMM (mma.sync m16n8k8) =================
__device__ __forceinline__ void split_tf32(float x, float& h, float& l) {
    uint32_t u;
    asm("cvt.rna.tf32.f32 %0, %1;" : "=r"(u) : "f"(x));
    h = __uint_as_float(u);
    l = x - h;
}
__device__ __forceinline__ void mma_tf32(float* c, const uint32_t* a, const uint32_t* b) {
    asm volatile(
        "mma.sync.aligned.m16n8k8.row.col.f32.tf32.tf32.f32 "
        "{%0,%1,%2,%3}, {%4,%5,%6,%7}, {%8,%9}, {%0,%1,%2,%3};"
        : "+f"(c[0]), "+f"(c[1]), "+f"(c[2]), "+f"(c[3])
        : "r"(a[0]), "r"(a[1]), "r"(a[2]), "r"(a[3]), "r"(b[0]), "r"(b[1]));
}

__global__ void __launch_bounds__(256) gemm_tc(
    const float* __restrict__ A, const float* __restrict__ Bm,
    const float* __restrict__ bias, float* __restrict__ C,
    int M, int Nn, int K)
{
    __shared__ float Ah[128][17], Al[128][17];
    __shared__ float Bh[16][72], Bl[16][72];
    int tid = threadIdx.x;
    int wid = tid >> 5, lane = tid & 31;
    int wm = wid >> 1, wn = wid & 1;       // warp grid 4(m) x 2(n)
    int m0 = blockIdx.y * 128, n0 = blockIdx.x * 64;
    float acc[2][4][4] = {};

    int ar = tid >> 1, ac = (tid & 1) * 8;
    int br = tid >> 4, bc = (tid & 15) * 4;
    int r = lane >> 2, cq = lane & 3;

    for (int k0 = 0; k0 < K; k0 += 16) {
        __syncthreads();
        {
            const float* ap = A + (size_t)(m0 + ar) * K + k0 + ac;
            float4 v0 = *(const float4*)ap;
            float4 v1 = *(const float4*)(ap + 4);
            float va[8] = {v0.x, v0.y, v0.z, v0.w, v1.x, v1.y, v1.z, v1.w};
#pragma unroll
            for (int i = 0; i < 8; i++) {
                float h, l;
                split_tf32(va[i], h, l);
                Ah[ar][ac + i] = h;
                Al[ar][ac + i] = l;
            }
            float4 vb = *(const float4*)(Bm + (size_t)(k0 + br) * Nn + n0 + bc);
            float vbb[4] = {vb.x, vb.y, vb.z, vb.w};
#pragma unroll
            for (int i = 0; i < 4; i++) {
                float h, l;
                split_tf32(vbb[i], h, l);
                Bh[br][bc + i] = h;
                Bl[br][bc + i] = l;
            }
        }
        __syncthreads();
#pragma unroll
        for (int k8 = 0; k8 < 16; k8 += 8) {
            uint32_t afh[2][4], afl[2][4], bfh[4][2], bfl[4][2];
#pragma unroll
            for (int mt = 0; mt < 2; mt++) {
                int base = wm * 32 + mt * 16;
                afh[mt][0] = __float_as_uint(Ah[base + r][k8 + cq]);
                afh[mt][1] = __float_as_uint(Ah[base + r + 8][k8 + cq]);
                afh[mt][2] = __float_as_uint(Ah[base + r][k8 + cq + 4]);
                afh[mt][3] = __float_as_uint(Ah[base + r + 8][k8 + cq + 4]);
                afl[mt][0] = __float_as_uint(Al[base + r][k8 + cq]);
                afl[mt][1] = __float_as_uint(Al[base + r + 8][k8 + cq]);
                afl[mt][2] = __float_as_uint(Al[base + r][k8 + cq + 4]);
                afl[mt][3] = __float_as_uint(Al[base + r + 8][k8 + cq + 4]);
            }
#pragma unroll
            for (int nt = 0; nt < 4; nt++) {
                int col = wn * 32 + nt * 8 + r;
                bfh[nt][0] = __float_as_uint(Bh[k8 + cq][col]);
                bfh[nt][1] = __float_as_uint(Bh[k8 + cq + 4][col]);
                bfl[nt][0] = __float_as_uint(Bl[k8 + cq][col]);
                bfl[nt][1] = __float_as_uint(Bl[k8 + cq + 4][col]);
            }
#pragma unroll
            for (int mt = 0; mt < 2; mt++)
#pragma unroll
                for (int nt = 0; nt < 4; nt++) {
                    mma_tf32(acc[mt][nt], afh[mt], bfh[nt]);
                    mma_tf32(acc[mt][nt], afh[mt], bfl[nt]);
                    mma_tf32(acc[mt][nt], afl[mt], bfh[nt]);
                }
        }
    }
#pragma unroll
    for (int mt = 0; mt < 2; mt++)
#pragma unroll
        for (int nt = 0; nt < 4; nt++) {
            int row = m0 + wm * 32 + mt * 16 + r;
            int col = n0 + wn * 32 + nt * 8 + 2 * cq;
            float2 v0 = make_float2(acc[mt][nt][0], acc[mt][nt][1]);
            float2 v1 = make_float2(acc[mt][nt][2], acc[mt][nt][3]);
            if (bias) {
                float2 bv = *(const float2*)(bias + col);
                v0.x += bv.x; v0.y += bv.y;
                v1.x += bv.x; v1.y += bv.y;
            }
            *(float2*)(C + (size_t)row * Nn + col) = v0;
            *(float2*)(C + (size_t)(row + 8) * Nn + col) = v1;
        }
}

// ============ ddq_fused: qp = ratio*(exp(dd - diag - rowmax) + eps) ============
// One CTA = 64 rows x 256 features. acc[4][16] per thread (ty:4 rows, tx:4 cols x 4 subtiles)
__global__ void __launch_bounds__(256) ddq_fused(
    const float* __restrict__ data, const float* __restrict__ proj, float* __restrict__ qp)
{
    __shared__ __align__(16) float As[64][68];
    __shared__ __align__(16) float Bs[64][68];
    int bh = blockIdx.y; int b = bh / GH, h = bh % GH;
    int n0 = blockIdx.x * 64;
    int tid = threadIdx.x;
    int tx = tid & 15, ty = tid >> 4;
    int lr = tid >> 2, lc4 = (tid & 3) * 4;
    const float NORM = 0.35355339059327373f;
    const float* db = data + ((size_t)b * NN + n0) * DIMM + h * 64;
#pragma unroll
    for (int i = 0; i < 4; i++) {
        int c = lc4 + i * 16;
        float4 va = *(const float4*)(db + (size_t)lr * DIMM + c);
        As[c+0][lr] = va.x * NORM; As[c+1][lr] = va.y * NORM;
        As[c+2][lr] = va.z * NORM; As[c+3][lr] = va.w * NORM;
    }
    float acc[4][16];
#pragma unroll
    for (int i = 0; i < 4; i++)
#pragma unroll
        for (int j = 0; j < 16; j++) acc[i][j] = 0.f;

    for (int sub = 0; sub < 4; sub++) {
        __syncthreads();
#pragma unroll
        for (int i = 0; i < 4; i++) {
            int c = lc4 + i * 16;
            float4 vb = *(const float4*)(proj + (size_t)(sub * 64 + lr) * 64 + c);
            Bs[c+0][lr] = vb.x; Bs[c+1][lr] = vb.y; Bs[c+2][lr] = vb.z; Bs[c+3][lr] = vb.w;
        }
        __syncthreads();
#pragma unroll
        for (int kk = 0; kk < 64; kk++) {
            float4 a  = *(const float4*)&As[kk][ty*4];
            float4 bv = *(const float4*)&Bs[kk][tx*4];
            float av[4] = {a.x,a.y,a.z,a.w}, bb[4] = {bv.x,bv.y,bv.z,bv.w};
#pragma unroll
            for (int i = 0; i < 4; i++)
#pragma unroll
                for (int j = 0; j < 4; j++) acc[i][sub*4+j] += av[i] * bb[j];
        }
    }
    // diag + rowmax per row (reduce over 16-thread tx group)
    float diag[4], rmax[4];
#pragma unroll
    for (int i = 0; i < 4; i++) {
        int r = ty * 4 + i;
        float s = 0.f;
#pragma unroll
        for (int c = 0; c < 4; c++) { float vv = As[tx*4+c][r]; s += vv * vv; }
#pragma unroll
        for (int o = 8; o > 0; o >>= 1) s += __shfl_xor_sync(0xffffffffu, s, o);
        diag[i] = 0.5f * s;
        float m = acc[i][0];
#pragma unroll
        for (int j = 1; j < 16; j++) m = fmaxf(m, acc[i][j]);
#pragma unroll
        for (int o = 8; o > 0; o >>= 1) m = fmaxf(m, __shfl_xor_sync(0xffffffffu, m, o));
        rmax[i] = m;
    }
    float* ob = qp + ((size_t)bh * NN + n0 + ty * 4) * NBF;
#pragma unroll
    for (int i = 0; i < 4; i++) {
        float base = diag[i] + rmax[i];
#pragma unroll
        for (int sub = 0; sub < 4; sub++) {
            float4 o;
            o.x = 0.0625f * (expf(acc[i][sub*4+0] - base) + 1e-4f);
            o.y = 0.0625f * (expf(acc[i][sub*4+1] - base) + 1e-4f);
            o.z = 0.0625f * (expf(acc[i][sub*4+2] - base) + 1e-4f);
            o.w = 0.0625f * (expf(acc[i][sub*4+3] - base) + 1e-4f);
            *(float4*)(ob + (size_t)i * NBF + sub * 64 + tx * 4) = o;
        }
    }
}

// ============ ddk_fused: raw dd + diag + per-block max partial ============
__global__ void __launch_bounds__(256) ddk_fused(
    const float* __restrict__ data, const float* __restrict__ proj,
    float* __restrict__ kdd, float* __restrict__ kdiag, float* __restrict__ kmaxp)
{
    __shared__ __align__(16) float As[64][68];
    __shared__ __align__(16) float Bs[64][68];
    __shared__ float red[8];
    int bh = blockIdx.y; int b = bh / GH, h = bh % GH;
    int n0 = blockIdx.x * 64;
    int tid = threadIdx.x;
    int tx = tid & 15, ty = tid >> 4;
    int lr = tid >> 2, lc4 = (tid & 3) * 4;
    const float NORM = 0.35355339059327373f;
    const float* db = data + ((size_t)b * NN + n0) * DIMM + h * 64;
#pragma unroll
    for (int i = 0; i < 4; i++) {
        int c = lc4 + i * 16;
        float4 va = *(const float4*)(db + (size_t)lr * DIMM + c);
        As[c+0][lr] = va.x * NORM; As[c+1][lr] = va.y * NORM;
        As[c+2][lr] = va.z * NORM; As[c+3][lr] = va.w * NORM;
    }
    float acc[4][16];
#pragma unroll
    for (int i = 0; i < 4; i++)
#pragma unroll
        for (int j = 0; j < 16; j++) acc[i][j] = 0.f;

    for (int sub = 0; sub < 4; sub++) {
        __syncthreads();
#pragma unroll
        for (int i = 0; i < 4; i++) {
            int c = lc4 + i * 16;
            float4 vb = *(const float4*)(proj + (size_t)(sub * 64 + lr) * 64 + c);
            Bs[c+0][lr] = vb.x; Bs[c+1][lr] = vb.y; Bs[c+2][lr] = vb.z; Bs[c+3][lr] = vb.w;
        }
        __syncthreads();
#pragma unroll
        for (int kk = 0; kk < 64; kk++) {
            float4 a  = *(const float4*)&As[kk][ty*4];
            float4 bv = *(const float4*)&Bs[kk][tx*4];
            float av[4] = {a.x,a.y,a.z,a.w}, bb[4] = {bv.x,bv.y,bv.z,bv.w};
#pragma unroll
            for (int i = 0; i < 4; i++)
#pragma unroll
                for (int j = 0; j < 4; j++) acc[i][sub*4+j] += av[i] * bb[j];
        }
    }
    // write raw scores + diag, compute block max
    float tmax = -1e30f;
    float* ob = kdd + ((size_t)bh * NN + n0 + ty * 4) * NBF;
#pragma unroll
    for (int i = 0; i < 4; i++) {
        int r = ty * 4 + i;
        float s = 0.f;
#pragma unroll
        for (int c = 0; c < 4; c++) { float vv = As[tx*4+c][r]; s += vv * vv; }
#pragma unroll
        for (int o = 8; o > 0; o >>= 1) s += __shfl_xor_sync(0xffffffffu, s, o);
        if (tx == 0) kdiag[(size_t)bh * NN + n0 + r] = 0.5f * s;
#pragma unroll
        for (int sub = 0; sub < 4; sub++) {
            float4 o;
            o.x = acc[i][sub*4+0]; o.y = acc[i][sub*4+1];
            o.z = acc[i][sub*4+2]; o.w = acc[i][sub*4+3];
            tmax = fmaxf(tmax, fmaxf(fmaxf(o.x, o.y), fmaxf(o.z, o.w)));
            *(float4*)(ob + (size_t)i * NBF + sub * 64 + tx * 4) = o;
        }
    }
#pragma unroll
    for (int o = 16; o > 0; o >>= 1) tmax = fmaxf(tmax, __shfl_xor_sync(0xffffffffu, tmax, o));
    if ((tid & 31) == 0) red[tid >> 5] = tmax;
    __syncthreads();
    if (tid == 0) {
        float z = red[0];
#pragma unroll
        for (int i = 1; i < 8; i++) z = fmaxf(z, red[i]);
        kmaxp[bh * 128 + blockIdx.x] = z;
    }
}

__global__ void kmax_final_kernel(const float* __restrict__ kpart, float* __restrict__ kmax)
{
    int bh = blockIdx.x;
    float m = kpart[bh * 128 + threadIdx.x];
#pragma unroll
    for (int o = 16; o > 0; o >>= 1) m = fmaxf(m, __shfl_xor_sync(0xffffffffu, m, o));
    __shared__ float red[4];
    if ((threadIdx.x & 31) == 0) red[threadIdx.x >> 5] = m;
    __syncthreads();
    if (threadIdx.x == 0)
        kmax[bh] = fmaxf(fmaxf(red[0], red[1]), fmaxf(red[2], red[3]));
}

// ---------------- ctx: exp applied inline on raw kdd ----------------
__global__ void __launch_bounds__(256) ctx_partial_kernel(
    const float* __restrict__ kdd, const float* __restrict__ kdiag,
    const float* __restrict__ kmax, const float* __restrict__ v, float* __restrict__ part)
{
    int bh = blockIdx.x, sp = blockIdx.y;
    int b = bh / GH, h = bh % GH;
    int j = threadIdx.x;
    float acc[65];
#pragma unroll
    for (int d = 0; d < 65; d++) acc[d] = 0.f;
    __shared__ __align__(16) float vs[16][68];
    float km = kmax[bh];
    const float* kpb = kdd + ((size_t)bh * NN + sp * 256) * NBF + j;
    const float* dgb = kdiag + (size_t)bh * NN + sp * 256;
    const float* vb = v + ((size_t)b * NN + sp * 256) * DIMM + h * 64;
    for (int n0 = 0; n0 < 256; n0 += 16) {
        __syncthreads();
        int r = threadIdx.x >> 4;
        int c = (threadIdx.x & 15) * 4;
        float4 vv = *(const float4*)(vb + (size_t)(n0 + r) * DIMM + c);
        *(float4*)&vs[r][c] = vv;
        if ((threadIdx.x & 15) == 0) vs[r][64] = 1.f;
        if ((threadIdx.x & 15) == 1) vs[r][65] = dgb[n0 + r];
        __syncthreads();
#pragma unroll 2
        for (int nn = 0; nn < 16; nn++) {
            float praw = kpb[(size_t)(n0 + nn) * NBF];
            float p = 0.0625f * (expf(praw - vs[nn][65] - km) + 1e-4f);
#pragma unroll
            for (int d = 0; d < 65; d++) acc[d] += p * vs[nn][d];
        }
    }
    float* o = part + (((size_t)bh * NSPLIT + sp) * 256 + j) * 65;
#pragma unroll
    for (int d = 0; d < 65; d++) o[d] = acc[d];
}
__global__ void ctx_reduce_kernel(const float* __restrict__ part, float* __restrict__ ctx)
{
    int idx = blockIdx.x * 256 + threadIdx.x;
    if (idx >= BHG * 256 * 65) return;
    int bh = idx / (256 * 65); int rem = idx - bh * 256 * 65;
    int j = rem / 65, d = rem % 65;
    float s = 0.f;
#pragma unroll
    for (int sp = 0; sp < NSPLIT; sp++)
        s += part[(((size_t)bh * NSPLIT + sp) * 256 + j) * 65 + d];
    ctx[((size_t)bh * 256 + j) * 68 + d] = s;
}

// ---------------- d_inv = 1 / (qp . k_sum) ----------------
__global__ void denom_kernel(const float* __restrict__ qp, const float* __restrict__ ctx,
                             float* __restrict__ dinv)
{
    int row = blockIdx.x * 8 + (threadIdx.x >> 5);
    int lane = threadIdx.x & 31;
    int bh = row >> 13;
    const float* q = qp + (size_t)row * NBF;
    const float* ks = ctx + (size_t)bh * 256 * 68 + 64;
    float s = 0.f;
#pragma unroll
    for (int i = 0; i < 8; i++) s += q[lane + i * 32] * ks[(size_t)(lane + i * 32) * 68];
#pragma unroll
    for (int o = 16; o > 0; o >>= 1) s += __shfl_xor_sync(0xffffffffu, s, o);
    if (lane == 0) dinv[row] = 1.f / s;
}

// ---------------- out_g = (qp @ ctx) * d_inv -> att ----------------
__global__ void __launch_bounds__(256) outg_kernel(
    const float* __restrict__ qp, const float* __restrict__ ctx,
    const float* __restrict__ dinv, float* __restrict__ att)
{
    __shared__ __align__(16) float Qs[32][68];
    __shared__ __align__(16) float Cs[32][68];
    int bh = blockIdx.y; int b = bh / GH, h = bh % GH;
    int n0 = blockIdx.x * 64;
    int tid = threadIdx.x;
    int tx = tid & 15, ty = tid >> 4;
    float acc[4][4] = {};
    const float* qbase = qp + ((size_t)bh * NN + n0) * NBF;
    const float* cbase = ctx + (size_t)bh * 256 * 68;
    for (int k0 = 0; k0 < 256; k0 += 32) {
        int r = tid >> 3, c4 = (tid & 7) * 4;
#pragma unroll
        for (int i = 0; i < 2; i++) {
            float4 v = *(const float4*)(qbase + (size_t)(r + i * 32) * NBF + k0 + c4);
            Qs[c4+0][r+i*32] = v.x; Qs[c4+1][r+i*32] = v.y;
            Qs[c4+2][r+i*32] = v.z; Qs[c4+3][r+i*32] = v.w;
        }
        int cr = tid >> 4, cc4 = (tid & 15) * 4;
#pragma unroll
        for (int i = 0; i < 2; i++) {
            float4 v = *(const float4*)(cbase + (size_t)(k0 + cr + i * 16) * 68 + cc4);
            *(float4*)&Cs[cr + i * 16][cc4] = v;
        }
        __syncthreads();
#pragma unroll
        for (int kk = 0; kk < 32; kk++) {
            float4 a  = *(const float4*)&Qs[kk][ty*4];
            float4 bv = *(const float4*)&Cs[kk][tx*4];
            float av[4] = {a.x,a.y,a.z,a.w}, bb[4] = {bv.x,bv.y,bv.z,bv.w};
#pragma unroll
            for (int i = 0; i < 4; i++)
#pragma unroll
                for (int j = 0; j < 4; j++) acc[i][j] += av[i] * bb[j];
        }
        __syncthreads();
    }
#pragma unroll
    for (int i = 0; i < 4; i++) {
        int n = n0 + ty * 4 + i;
        float di = dinv[(size_t)bh * NN + n];
        float4 o = {acc[i][0]*di, acc[i][1]*di, acc[i][2]*di, acc[i][3]*di};
        *(float4*)(att + ((size_t)b * NN + n) * DIMM + h * 64 + tx * 4) = o;
    }
}

// ---------------- RoPE for local heads ----------------
__global__ void rope_kernel(const float* __restrict__ q, const float* __restrict__ k,
                            float* __restrict__ rq, float* __restrict__ rk)
{
    int idx = blockIdx.x * blockDim.x + threadIdx.x;
    int i = idx & 31;
    int n = (idx >> 5) & (NN - 1);
    int bh = idx >> 18;
    int b = bh >> 1, lh = bh & 1;
    float invf = (float)exp(-(double)(2 * i) / 64.0 * 9.210340371976184);
    float ang = (float)n * invf;
    float s, c;
    sincosf(ang, &s, &c);
    size_t base = ((size_t)b * NN + n) * DIMM + (GH + lh) * 64;
    float q1 = q[base + i], q2 = q[base + 32 + i];
    float k1 = k[base + i], k2 = k[base + 32 + i];
    size_t ob = ((size_t)bh * NN + n) * DH;
    rq[ob + i]      = q1 * c - q2 * s;
    rq[ob + 32 + i] = q2 * c + q1 * s;
    rk[ob + i]      = k1 * c - k2 * s;
    rk[ob + 32 + i] = k2 * c + k1 * s;
}

// ---------------- local scores = 0.125 * bq @ bk3^T with masking ----------------
__global__ void __launch_bounds__(256) lscore_kernel(
    const float* __restrict__ rq, const float* __restrict__ rk, float* __restrict__ sc)
{
    __shared__ __align__(16) float Qs[64][68];
    __shared__ __align__(16) float Ks[64][68];
    int bw = blockIdx.z; int bh = bw >> 5; int w = bw & 31;
    int m0 = blockIdx.y * 64, c0 = blockIdx.x * 64;
    int tid = threadIdx.x;
    int lr = tid >> 2, lc4 = (tid & 3) * 4;
    const float* qb = rq + ((size_t)bh * NN + w * WINSZ + m0) * DH;
    const float* kb = rk + (size_t)bh * NN * DH;
    int knr = (w - 1) * WINSZ + c0 + lr;
    bool kvalid = (unsigned)knr < (unsigned)NN;
#pragma unroll
    for (int i = 0; i < 4; i++) {
        int c = lc4 + i * 16;
        float4 va = *(const float4*)(qb + (size_t)lr * DH + c);
        Qs[c+0][lr] = va.x; Qs[c+1][lr] = va.y; Qs[c+2][lr] = va.z; Qs[c+3][lr] = va.w;
        float4 vk = make_float4(0.f, 0.f, 0.f, 0.f);
        if (kvalid) vk = *(const float4*)(kb + (size_t)knr * DH + c);
        Ks[c+0][lr] = vk.x; Ks[c+1][lr] = vk.y; Ks[c+2][lr] = vk.z; Ks[c+3][lr] = vk.w;
    }
    __syncthreads();
    int tx = tid & 15, ty = tid >> 4;
    float acc[4][4] = {};
#pragma unroll
    for (int kk = 0; kk < 64; kk++) {
        float4 a  = *(const float4*)&Qs[kk][ty*4];
        float4 bv = *(const float4*)&Ks[kk][tx*4];
        float av[4] = {a.x,a.y,a.z,a.w}, bb[4] = {bv.x,bv.y,bv.z,bv.w};
#pragma unroll
        for (int i = 0; i < 4; i++)
#pragma unroll
            for (int j = 0; j < 4; j++) acc[i][j] += av[i] * bb[j];
    }
    int kn0 = (w - 1) * WINSZ + c0 + tx * 4;
    bool valid = (unsigned)kn0 < (unsigned)NN;
    float* ob = sc + ((size_t)bw * WINSZ + m0) * 768 + c0;
#pragma unroll
    for (int i = 0; i < 4; i++) {
        float4 o;
        o.x = valid ? acc[i][0] * 0.125f : -1e9f;
        o.y = valid ? acc[i][1] * 0.125f : -1e9f;
        o.z = valid ? acc[i][2] * 0.125f : -1e9f;
        o.w = valid ? acc[i][3] * 0.125f : -1e9f;
        *(float4*)(ob + (size_t)(ty * 4 + i) * 768 + tx * 4) = o;
    }
}

// ---------------- row stats: m and 1/sum(exp) per score row ----------------
__global__ void rowstats_kernel(const float* __restrict__ sc,
                                float* __restrict__ rm, float* __restrict__ rs)
{
    int row = blockIdx.x * 8 + (threadIdx.x >> 5);
    int lane = threadIdx.x & 31;
    const float* r = sc + (size_t)row * 768;
    float vals[24];
    float m = -1e30f;
#pragma unroll
    for (int i = 0; i < 24; i++) { vals[i] = r[lane + i * 32]; m = fmaxf(m, vals[i]); }
#pragma unroll
    for (int o = 16; o > 0; o >>= 1) m = fmaxf(m, __shfl_xor_sync(0xffffffffu, m, o));
    float s = 0.f;
#pragma unroll
    for (int i = 0; i < 24; i++) s += expf(vals[i] - m);
#pragma unroll
    for (int o = 16; o > 0; o >>= 1) s += __shfl_xor_sync(0xffffffffu, s, o);
    if (lane == 0) { rm[row] = m; rs[row] = 1.f / s; }
}

// ---------------- out_l = softmax(sc) @ bv3 -> att (exp fused in load) ----------------
__global__ void __launch_bounds__(256) outl_kernel(
    const float* __restrict__ sc, const float* __restrict__ rm, const float* __restrict__ rs,
    const float* __restrict__ v, float* __restrict__ att)
{
    __shared__ __align__(16) float As[32][68];
    __shared__ __align__(16) float Vs[32][68];
    __shared__ float sm_m[64], sm_is[64];
    int bw = blockIdx.y; int bh = bw >> 5; int w = bw & 31;
    int b = bh >> 1, lh = bh & 1;
    int m0 = blockIdx.x * 64;
    int tid = threadIdx.x;
    int tx = tid & 15, ty = tid >> 4;
    int rowbase = bw * WINSZ + m0;
    if (tid < 64) { sm_m[tid] = rm[rowbase + tid]; sm_is[tid] = rs[rowbase + tid]; }
    __syncthreads();
    float acc[4][4] = {};
    const float* sb = sc + (size_t)rowbase * 768;
    const float* vb = v + (size_t)b * NN * DIMM + (GH + lh) * 64;
    for (int k0 = 0; k0 < 768; k0 += 32) {
#pragma unroll
        for (int i = 0; i < 2; i++) {
            int s1 = tid + i * 256;
            {
                int r = s1 >> 3, c4 = (s1 & 7) * 4;
                float4 a = *(const float4*)(sb + (size_t)r * 768 + k0 + c4);
                float mm = sm_m[r], is = sm_is[r];
                As[c4+0][r] = expf(a.x - mm) * is;
                As[c4+1][r] = expf(a.y - mm) * is;
                As[c4+2][r] = expf(a.z - mm) * is;
                As[c4+3][r] = expf(a.w - mm) * is;
            }
            {
                int kr = s1 >> 4, c4 = (s1 & 15) * 4;
                int kn = (w - 1) * WINSZ + k0 + kr;
                float4 vv = make_float4(0.f, 0.f, 0.f, 0.f);
                if ((unsigned)kn < (unsigned)NN)
                    vv = *(const float4*)(vb + (size_t)kn * DIMM + c4);
                *(float4*)&Vs[kr][c4] = vv;
            }
        }
        __syncthreads();
#pragma unroll
        for (int kk = 0; kk < 32; kk++) {
            float4 a  = *(const float4*)&As[kk][ty*4];
            float4 bv = *(const float4*)&Vs[kk][tx*4];
            float av[4] = {a.x,a.y,a.z,a.w}, bb[4] = {bv.x,bv.y,bv.z,bv.w};
#pragma unroll
            for (int i = 0; i < 4; i++)
#pragma unroll
                for (int j = 0; j < 4; j++) acc[i][j] += av[i] * bb[j];
        }
        __syncthreads();
    }
#pragma unroll
    for (int i = 0; i < 4; i++) {
        int n = w * WINSZ + m0 + ty * 4 + i;
        float4 o = {acc[i][0], acc[i][1], acc[i][2], acc[i][3]};
        *(float4*)(att + ((size_t)b * NN + n) * DIMM + (GH + lh) * 64 + tx * 4) = o;
    }
}

// ---------------- launcher ----------------
extern "C" void kernel_launch(void* const* d_in, const int* in_sizes, int n_in,
                              void* d_out, int out_size)
{
    (void)in_sizes; (void)n_in; (void)out_size;
    const float* x    = (const float*)d_in[0];
    const float* Wq   = (const float*)d_in[1];
    const float* Wk   = (const float*)d_in[2];
    const float* Wv   = (const float*)d_in[3];
    const float* Wo   = (const float*)d_in[4];
    const float* bo   = (const float*)d_in[5];
    const float* proj = (const float*)d_in[6];
    float* out = (float*)d_out;

    float *q, *k, *v, *qp, *kp, *kdg, *kmp, *km, *part, *ctx, *dinv, *att, *sc, *rq, *rk, *rm, *rs;
    cudaGetSymbolAddress((void**)&q, g_q);
    cudaGetSymbolAddress((void**)&k, g_k);
    cudaGetSymbolAddress((void**)&v, g_v);
    cudaGetSymbolAddress((void**)&qp, g_qp);
    cudaGetSymbolAddress((void**)&kp, g_kp);
    cudaGetSymbolAddress((void**)&kdg, g_kdiag);
    cudaGetSymbolAddress((void**)&kmp, g_kmaxp);
    cudaGetSymbolAddress((void**)&km, g_kmax);
    cudaGetSymbolAddress((void**)&part, g_part);
    cudaGetSymbolAddress((void**)&ctx, g_ctx);
    cudaGetSymbolAddress((void**)&dinv, g_dinv);
    cudaGetSymbolAddress((void**)&att, g_att);
    cudaGetSymbolAddress((void**)&sc, g_sc);
    cudaGetSymbolAddress((void**)&rq, g_rq);
    cudaGetSymbolAddress((void**)&rk, g_rk);
    cudaGetSymbolAddress((void**)&rm, g_rowm);
    cudaGetSymbolAddress((void**)&rs, g_rows);

    const int M = BB * NN; // 16384
    dim3 gt(DIMM / 64, M / 128);
    gemm_tc<<<gt, 256>>>(x, Wq, nullptr, q, M, DIMM, DIMM);
    gemm_tc<<<gt, 256>>>(x, Wk, nullptr, k, M, DIMM, DIMM);
    gemm_tc<<<gt, 256>>>(x, Wv, nullptr, v, M, DIMM, DIMM);

    dim3 gdd(NN / 64, BHG);
    ddq_fused<<<gdd, 256>>>(q, proj, qp);
    ddk_fused<<<gdd, 256>>>(k, proj, kp, kdg, kmp);
    kmax_final_kernel<<<BHG, 128>>>(kmp, km);

    ctx_partial_kernel<<<dim3(BHG, NSPLIT), 256>>>(kp, kdg, km, v, part);
    ctx_reduce_kernel<<<(BHG * 256 * 65 + 255) / 256, 256>>>(part, ctx);

    denom_kernel<<<BHG * NN / 8, 256>>>(qp, ctx, dinv);
    outg_kernel<<<dim3(NN / 64, BHG), 256>>>(qp, ctx, dinv, att);

    rope_kernel<<<BHL * NN * 32 / 256, 256>>>(q, k, rq, rk);
    lscore_kernel<<<dim3(12, 4, BHL * NWIN), 256>>>(rq, rk, sc);
    rowstats_kernel<<<BHL * NWIN * WINSZ / 8, 256>>>(sc, rm, rs);
    outl_kernel<<<dim3(4, BHL * NWIN), 256>>>(sc, rm, rs, v, att);

    gemm_tc<<<gt, 256>>>(att, Wo, bo, out, M, DIMM, DIMM);
}

// round 10
// speedup vs baseline: 1.4370x; 1.2509x over previous
#include <cuda_runtime.h>
#include <cuda_bf16.h>
#include <math.h>
#include <stdint.h>

#define BB 2
#define NN 8192
#define DIMM 512
#define GH 6
#define DH 64
#define NBF 256
#define NWIN 32
#define WINSZ 256
#define BHG (BB*GH)      // 12
#define BHL 4            // B * LOCAL_HEADS
#define NSPLIT 32

// ---------------- scratch (device globals: alloc-free) ----------------
__device__ float g_q[BB*NN*DIMM];
__device__ float g_k[BB*NN*DIMM];
__device__ float g_v[BB*NN*DIMM];
__device__ float g_qp[BHG*NN*NBF];
__device__ float g_kp[BHG*NN*NBF];      // raw k dd scores
__device__ float g_kdiag[BHG*NN];
__device__ float g_kmaxp[BHG*128];
__device__ float g_kmax[BHG];
__device__ float g_part[BHG*NSPLIT*256*65];
__device__ float g_ctx[BHG*256*68];
__device__ float g_dinv[BHG*NN];
__device__ float g_att[BB*NN*DIMM];
__device__ float g_sc[(size_t)BHL*NWIN*WINSZ*768];
__device__ float g_rq[BHL*NN*DH];
__device__ float g_rk[BHL*NN*DH];
__device__ float g_rowm[BHL*NWIN*WINSZ];
__device__ float g_rows[BHL*NWIN*WINSZ];
__device__ float g_bt[3*512*512];   // Wq/Wk/Wv transposed: [n][k]
__device__ float g_wot[512*512];    // Wo transposed: [n][k]

// ================= weight transpose: out[n][k] = W[k][n], 512x512 =================
__global__ void wtrans(const float* __restrict__ W, float* __restrict__ out)
{
    __shared__ float t[32][33];
    int n0 = blockIdx.x * 32, k0 = blockIdx.y * 32;
    int tx = threadIdx.x, ty = threadIdx.y;
#pragma unroll
    for (int i = ty; i < 32; i += 8) t[i][tx] = W[(size_t)(k0 + i) * 512 + n0 + tx];
    __syncthreads();
#pragma unroll
    for (int i = ty; i < 32; i += 8) out[(size_t)(n0 + i) * 512 + k0 + tx] = t[tx][i];
}

// ================= bf16x3 tensor-core GEMM (mma.sync m16n8k16) =================
// C[M][Nn] = A[M][K] @ Bt[n][k]^T (+bias). CTA tile 128x64, K-chunk 32, double-buffered.
__device__ __forceinline__ void cvt_hl(float f0, float f1, uint32_t& hi, uint32_t& lo) {
    __nv_bfloat16 h0 = __float2bfloat16_rn(f0), h1 = __float2bfloat16_rn(f1);
    float r0 = f0 - __bfloat162float(h0), r1 = f1 - __bfloat162float(h1);
    __nv_bfloat162 hh; hh.x = h0; hh.y = h1;
    __nv_bfloat162 ll = __floats2bfloat162_rn(r0, r1);
    hi = *reinterpret_cast<uint32_t*>(&hh);
    lo = *reinterpret_cast<uint32_t*>(&ll);
}
__device__ __forceinline__ void mma_bf16(float* c, const uint32_t* a, const uint32_t* b) {
    asm volatile(
        "mma.sync.aligned.m16n8k16.row.col.f32.bf16.bf16.f32 "
        "{%0,%1,%2,%3}, {%4,%5,%6,%7}, {%8,%9}, {%0,%1,%2,%3};"
        : "+f"(c[0]), "+f"(c[1]), "+f"(c[2]), "+f"(c[3])
        : "r"(a[0]), "r"(a[1]), "r"(a[2]), "r"(a[3]), "r"(b[0]), "r"(b[1]));
}

#define STW 20            // smem row stride in words (16 data + 4 pad, 16B-aligned)
#define STAGE_W 7680      // Ah 2560 + Al 2560 + Bh 1280 + Bl 1280
#define GSMEM_BYTES (2*STAGE_W*4)

__global__ void __launch_bounds__(256, 2) gemm_bf3(
    const float* __restrict__ A, const float* __restrict__ Bt,
    const float* __restrict__ bias, float* __restrict__ C,
    int M, int Nn, int K)
{
    extern __shared__ uint32_t smw[];
    int tid = threadIdx.x;
    int wid = tid >> 5, lane = tid & 31;
    int wm = wid >> 1, wn = wid & 1;       // warp grid 4(m) x 2(n), warp tile 32x32
    int m0 = blockIdx.y * 128, n0 = blockIdx.x * 64;
    int r = lane >> 2, cq = lane & 3;
    float acc[2][4][4] = {};

    int arow = tid >> 1, akq = (tid & 1) * 16;   // A: 128 rows x 32 k, 16 floats/thread
    int brow = tid >> 2, bkq = (tid & 3) * 8;    // B: 64 rows x 32 k, 8 floats/thread
    const float* aptr = A + (size_t)(m0 + arow) * K + akq;
    const float* bptr = Bt + (size_t)(n0 + brow) * K + bkq;

    float4 pa[4], pb[2];

#define LOAD_REGS(k0) do { \
    pa[0] = *(const float4*)(aptr + (k0)); \
    pa[1] = *(const float4*)(aptr + (k0) + 4); \
    pa[2] = *(const float4*)(aptr + (k0) + 8); \
    pa[3] = *(const float4*)(aptr + (k0) + 12); \
    pb[0] = *(const float4*)(bptr + (k0)); \
    pb[1] = *(const float4*)(bptr + (k0) + 4); \
} while (0)

#define STORE_STAGE(s) do { \
    uint32_t* Ah = smw + (s) * STAGE_W; \
    uint32_t* Al = Ah + 2560; \
    uint32_t* Bh = Ah + 5120; \
    uint32_t* Bl = Ah + 6400; \
    float av[16] = {pa[0].x,pa[0].y,pa[0].z,pa[0].w, pa[1].x,pa[1].y,pa[1].z,pa[1].w, \
                    pa[2].x,pa[2].y,pa[2].z,pa[2].w, pa[3].x,pa[3].y,pa[3].z,pa[3].w}; \
    uint32_t ahv[8], alv[8]; \
    _Pragma("unroll") \
    for (int i = 0; i < 8; i++) cvt_hl(av[2*i], av[2*i+1], ahv[i], alv[i]); \
    int aoff = arow * STW + (akq >> 1); \
    *(uint4*)(Ah + aoff)     = make_uint4(ahv[0], ahv[1], ahv[2], ahv[3]); \
    *(uint4*)(Ah + aoff + 4) = make_uint4(ahv[4], ahv[5], ahv[6], ahv[7]); \
    *(uint4*)(Al + aoff)     = make_uint4(alv[0], alv[1], alv[2], alv[3]); \
    *(uint4*)(Al + aoff + 4) = make_uint4(alv[4], alv[5], alv[6], alv[7]); \
    float bv[8] = {pb[0].x,pb[0].y,pb[0].z,pb[0].w, pb[1].x,pb[1].y,pb[1].z,pb[1].w}; \
    uint32_t bhv[4], blv[4]; \
    _Pragma("unroll") \
    for (int i = 0; i < 4; i++) cvt_hl(bv[2*i], bv[2*i+1], bhv[i], blv[i]); \
    int boff = brow * STW + (bkq >> 1); \
    *(uint4*)(Bh + boff) = make_uint4(bhv[0], bhv[1], bhv[2], bhv[3]); \
    *(uint4*)(Bl + boff) = make_uint4(blv[0], blv[1], blv[2], blv[3]); \
} while (0)

#define DO_MMA(s) do { \
    const uint32_t* Ah = smw + (s) * STAGE_W; \
    const uint32_t* Al = Ah + 2560; \
    const uint32_t* Bh = Ah + 5120; \
    const uint32_t* Bl = Ah + 6400; \
    _Pragma("unroll") \
    for (int ks = 0; ks < 2; ks++) { \
        int ko = ks * 8; \
        uint32_t ah[2][4], al[2][4], bh[4][2], bl[4][2]; \
        _Pragma("unroll") \
        for (int mt = 0; mt < 2; mt++) { \
            int mr = (wm * 32 + mt * 16 + r) * STW + ko + cq; \
            ah[mt][0] = Ah[mr];           ah[mt][1] = Ah[mr + 8 * STW]; \
            ah[mt][2] = Ah[mr + 4];       ah[mt][3] = Ah[mr + 8 * STW + 4]; \
            al[mt][0] = Al[mr];           al[mt][1] = Al[mr + 8 * STW]; \
            al[mt][2] = Al[mr + 4];       al[mt][3] = Al[mr + 8 * STW + 4]; \
        } \
        _Pragma("unroll") \
        for (int nt = 0; nt < 4; nt++) { \
            int nr = (wn * 32 + nt * 8 + r) * STW + ko + cq; \
            bh[nt][0] = Bh[nr]; bh[nt][1] = Bh[nr + 4]; \
            bl[nt][0] = Bl[nr]; bl[nt][1] = Bl[nr + 4]; \
        } \
        _Pragma("unroll") \
        for (int mt = 0; mt < 2; mt++) \
            _Pragma("unroll") \
            for (int nt = 0; nt < 4; nt++) { \
                mma_bf16(acc[mt][nt], ah[mt], bh[nt]); \
                mma_bf16(acc[mt][nt], ah[mt], bl[nt]); \
                mma_bf16(acc[mt][nt], al[mt], bh[nt]); \
            } \
    } \
} while (0)

    const int NC = K / 32;
    LOAD_REGS(0);
    STORE_STAGE(0);
    __syncthreads();
    for (int it = 0; it < NC; ++it) {
        if (it + 1 < NC) LOAD_REGS((it + 1) * 32);
        DO_MMA(it & 1);
        if (it + 1 < NC) {
            __syncthreads();
            STORE_STAGE((it + 1) & 1);
            __syncthreads();
        }
    }

#pragma unroll
    for (int mt = 0; mt < 2; mt++)
#pragma unroll
        for (int nt = 0; nt < 4; nt++) {
            int row = m0 + wm * 32 + mt * 16 + r;
            int col = n0 + wn * 32 + nt * 8 + 2 * cq;
            float2 v0 = make_float2(acc[mt][nt][0], acc[mt][nt][1]);
            float2 v1 = make_float2(acc[mt][nt][2], acc[mt][nt][3]);
            if (bias) {
                float2 bv = *(const float2*)(bias + col);
                v0.x += bv.x; v0.y += bv.y;
                v1.x += bv.x; v1.y += bv.y;
            }
            *(float2*)(C + (size_t)row * Nn + col) = v0;
            *(float2*)(C + (size_t)(row + 8) * Nn + col) = v1;
        }
#undef LOAD_REGS
#undef STORE_STAGE
#undef DO_MMA
}

// ============ ddq_fused: qp = ratio*(exp(dd - diag - rowmax) + eps) ============
__global__ void __launch_bounds__(256) ddq_fused(
    const float* __restrict__ data, const float* __restrict__ proj, float* __restrict__ qp)
{
    __shared__ __align__(16) float As[64][68];
    __shared__ __align__(16) float Bs[64][68];
    int bh = blockIdx.y; int b = bh / GH, h = bh % GH;
    int n0 = blockIdx.x * 64;
    int tid = threadIdx.x;
    int tx = tid & 15, ty = tid >> 4;
    int lr = tid >> 2, lc4 = (tid & 3) * 4;
    const float NORM = 0.35355339059327373f;
    const float* db = data + ((size_t)b * NN + n0) * DIMM + h * 64;
#pragma unroll
    for (int i = 0; i < 4; i++) {
        int c = lc4 + i * 16;
        float4 va = *(const float4*)(db + (size_t)lr * DIMM + c);
        As[c+0][lr] = va.x * NORM; As[c+1][lr] = va.y * NORM;
        As[c+2][lr] = va.z * NORM; As[c+3][lr] = va.w * NORM;
    }
    float acc[4][16];
#pragma unroll
    for (int i = 0; i < 4; i++)
#pragma unroll
        for (int j = 0; j < 16; j++) acc[i][j] = 0.f;

    for (int sub = 0; sub < 4; sub++) {
        __syncthreads();
#pragma unroll
        for (int i = 0; i < 4; i++) {
            int c = lc4 + i * 16;
            float4 vb = *(const float4*)(proj + (size_t)(sub * 64 + lr) * 64 + c);
            Bs[c+0][lr] = vb.x; Bs[c+1][lr] = vb.y; Bs[c+2][lr] = vb.z; Bs[c+3][lr] = vb.w;
        }
        __syncthreads();
#pragma unroll
        for (int kk = 0; kk < 64; kk++) {
            float4 a  = *(const float4*)&As[kk][ty*4];
            float4 bv = *(const float4*)&Bs[kk][tx*4];
            float av[4] = {a.x,a.y,a.z,a.w}, bb[4] = {bv.x,bv.y,bv.z,bv.w};
#pragma unroll
            for (int i = 0; i < 4; i++)
#pragma unroll
                for (int j = 0; j < 4; j++) acc[i][sub*4+j] += av[i] * bb[j];
        }
    }
    float diag[4], rmax[4];
#pragma unroll
    for (int i = 0; i < 4; i++) {
        int r = ty * 4 + i;
        float s = 0.f;
#pragma unroll
        for (int c = 0; c < 4; c++) { float vv = As[tx*4+c][r]; s += vv * vv; }
#pragma unroll
        for (int o = 8; o > 0; o >>= 1) s += __shfl_xor_sync(0xffffffffu, s, o);
        diag[i] = 0.5f * s;
        float m = acc[i][0];
#pragma unroll
        for (int j = 1; j < 16; j++) m = fmaxf(m, acc[i][j]);
#pragma unroll
        for (int o = 8; o > 0; o >>= 1) m = fmaxf(m, __shfl_xor_sync(0xffffffffu, m, o));
        rmax[i] = m;
    }
    float* ob = qp + ((size_t)bh * NN + n0 + ty * 4) * NBF;
#pragma unroll
    for (int i = 0; i < 4; i++) {
        float base = diag[i] + rmax[i];
#pragma unroll
        for (int sub = 0; sub < 4; sub++) {
            float4 o;
            o.x = 0.0625f * (expf(acc[i][sub*4+0] - base) + 1e-4f);
            o.y = 0.0625f * (expf(acc[i][sub*4+1] - base) + 1e-4f);
            o.z = 0.0625f * (expf(acc[i][sub*4+2] - base) + 1e-4f);
            o.w = 0.0625f * (expf(acc[i][sub*4+3] - base) + 1e-4f);
            *(float4*)(ob + (size_t)i * NBF + sub * 64 + tx * 4) = o;
        }
    }
}

// ============ ddk_fused: raw dd + diag + per-block max partial ============
__global__ void __launch_bounds__(256) ddk_fused(
    const float* __restrict__ data, const float* __restrict__ proj,
    float* __restrict__ kdd, float* __restrict__ kdiag, float* __restrict__ kmaxp)
{
    __shared__ __align__(16) float As[64][68];
    __shared__ __align__(16) float Bs[64][68];
    __shared__ float red[8];
    int bh = blockIdx.y; int b = bh / GH, h = bh % GH;
    int n0 = blockIdx.x * 64;
    int tid = threadIdx.x;
    int tx = tid & 15, ty = tid >> 4;
    int lr = tid >> 2, lc4 = (tid & 3) * 4;
    const float NORM = 0.35355339059327373f;
    const float* db = data + ((size_t)b * NN + n0) * DIMM + h * 64;
#pragma unroll
    for (int i = 0; i < 4; i++) {
        int c = lc4 + i * 16;
        float4 va = *(const float4*)(db + (size_t)lr * DIMM + c);
        As[c+0][lr] = va.x * NORM; As[c+1][lr] = va.y * NORM;
        As[c+2][lr] = va.z * NORM; As[c+3][lr] = va.w * NORM;
    }
    float acc[4][16];
#pragma unroll
    for (int i = 0; i < 4; i++)
#pragma unroll
        for (int j = 0; j < 16; j++) acc[i][j] = 0.f;

    for (int sub = 0; sub < 4; sub++) {
        __syncthreads();
#pragma unroll
        for (int i = 0; i < 4; i++) {
            int c = lc4 + i * 16;
            float4 vb = *(const float4*)(proj + (size_t)(sub * 64 + lr) * 64 + c);
            Bs[c+0][lr] = vb.x; Bs[c+1][lr] = vb.y; Bs[c+2][lr] = vb.z; Bs[c+3][lr] = vb.w;
        }
        __syncthreads();
#pragma unroll
        for (int kk = 0; kk < 64; kk++) {
            float4 a  = *(const float4*)&As[kk][ty*4];
            float4 bv = *(const float4*)&Bs[kk][tx*4];
            float av[4] = {a.x,a.y,a.z,a.w}, bb[4] = {bv.x,bv.y,bv.z,bv.w};
#pragma unroll
            for (int i = 0; i < 4; i++)
#pragma unroll
                for (int j = 0; j < 4; j++) acc[i][sub*4+j] += av[i] * bb[j];
        }
    }
    float tmax = -1e30f;
    float* ob = kdd + ((size_t)bh * NN + n0 + ty * 4) * NBF;
#pragma unroll
    for (int i = 0; i < 4; i++) {
        int r = ty * 4 + i;
        float s = 0.f;
#pragma unroll
        for (int c = 0; c < 4; c++) { float vv = As[tx*4+c][r]; s += vv * vv; }
#pragma unroll
        for (int o = 8; o > 0; o >>= 1) s += __shfl_xor_sync(0xffffffffu, s, o);
        if (tx == 0) kdiag[(size_t)bh * NN + n0 + r] = 0.5f * s;
#pragma unroll
        for (int sub = 0; sub < 4; sub++) {
            float4 o;
            o.x = acc[i][sub*4+0]; o.y = acc[i][sub*4+1];
            o.z = acc[i][sub*4+2]; o.w = acc[i][sub*4+3];
            tmax = fmaxf(tmax, fmaxf(fmaxf(o.x, o.y), fmaxf(o.z, o.w)));
            *(float4*)(ob + (size_t)i * NBF + sub * 64 + tx * 4) = o;
        }
    }
#pragma unroll
    for (int o = 16; o > 0; o >>= 1) tmax = fmaxf(tmax, __shfl_xor_sync(0xffffffffu, tmax, o));
    if ((tid & 31) == 0) red[tid >> 5] = tmax;
    __syncthreads();
    if (tid == 0) {
        float z = red[0];
#pragma unroll
        for (int i = 1; i < 8; i++) z = fmaxf(z, red[i]);
        kmaxp[bh * 128 + blockIdx.x] = z;
    }
}

__global__ void kmax_final_kernel(const float* __restrict__ kpart, float* __restrict__ kmax)
{
    int bh = blockIdx.x;
    float m = kpart[bh * 128 + threadIdx.x];
#pragma unroll
    for (int o = 16; o > 0; o >>= 1) m = fmaxf(m, __shfl_xor_sync(0xffffffffu, m, o));
    __shared__ float red[4];
    if ((threadIdx.x & 31) == 0) red[threadIdx.x >> 5] = m;
    __syncthreads();
    if (threadIdx.x == 0)
        kmax[bh] = fmaxf(fmaxf(red[0], red[1]), fmaxf(red[2], red[3]));
}

// ---------------- ctx: exp applied inline on raw kdd ----------------
__global__ void __launch_bounds__(256) ctx_partial_kernel(
    const float* __restrict__ kdd, const float* __restrict__ kdiag,
    const float* __restrict__ kmax, const float* __restrict__ v, float* __restrict__ part)
{
    int bh = blockIdx.x, sp = blockIdx.y;
    int b = bh / GH, h = bh % GH;
    int j = threadIdx.x;
    float acc[65];
#pragma unroll
    for (int d = 0; d < 65; d++) acc[d] = 0.f;
    __shared__ __align__(16) float vs[16][68];
    float km = kmax[bh];
    const float* kpb = kdd + ((size_t)bh * NN + sp * 256) * NBF + j;
    const float* dgb = kdiag + (size_t)bh * NN + sp * 256;
    const float* vb = v + ((size_t)b * NN + sp * 256) * DIMM + h * 64;
    for (int n0 = 0; n0 < 256; n0 += 16) {
        __syncthreads();
        int r = threadIdx.x >> 4;
        int c = (threadIdx.x & 15) * 4;
        float4 vv = *(const float4*)(vb + (size_t)(n0 + r) * DIMM + c);
        *(float4*)&vs[r][c] = vv;
        if ((threadIdx.x & 15) == 0) vs[r][64] = 1.f;
        if ((threadIdx.x & 15) == 1) vs[r][65] = dgb[n0 + r];
        __syncthreads();
#pragma unroll 2
        for (int nn = 0; nn < 16; nn++) {
            float praw = kpb[(size_t)(n0 + nn) * NBF];
            float p = 0.0625f * (expf(praw - vs[nn][65] - km) + 1e-4f);
#pragma unroll
            for (int d = 0; d < 65; d++) acc[d] += p * vs[nn][d];
        }
    }
    float* o = part + (((size_t)bh * NSPLIT + sp) * 256 + j) * 65;
#pragma unroll
    for (int d = 0; d < 65; d++) o[d] = acc[d];
}
__global__ void ctx_reduce_kernel(const float* __restrict__ part, float* __restrict__ ctx)
{
    int idx = blockIdx.x * 256 + threadIdx.x;
    if (idx >= BHG * 256 * 65) return;
    int bh = idx / (256 * 65); int rem = idx - bh * 256 * 65;
    int j = rem / 65, d = rem % 65;
    float s = 0.f;
#pragma unroll
    for (int sp = 0; sp < NSPLIT; sp++)
        s += part[(((size_t)bh * NSPLIT + sp) * 256 + j) * 65 + d];
    ctx[((size_t)bh * 256 + j) * 68 + d] = s;
}

// ---------------- d_inv = 1 / (qp . k_sum) ----------------
__global__ void denom_kernel(const float* __restrict__ qp, const float* __restrict__ ctx,
                             float* __restrict__ dinv)
{
    int row = blockIdx.x * 8 + (threadIdx.x >> 5);
    int lane = threadIdx.x & 31;
    int bh = row >> 13;
    const float* q = qp + (size_t)row * NBF;
    const float* ks = ctx + (size_t)bh * 256 * 68 + 64;
    float s = 0.f;
#pragma unroll
    for (int i = 0; i < 8; i++) s += q[lane + i * 32] * ks[(size_t)(lane + i * 32) * 68];
#pragma unroll
    for (int o = 16; o > 0; o >>= 1) s += __shfl_xor_sync(0xffffffffu, s, o);
    if (lane == 0) dinv[row] = 1.f / s;
}

// ---------------- out_g = (qp @ ctx) * d_inv -> att ----------------
__global__ void __launch_bounds__(256) outg_kernel(
    const float* __restrict__ qp, const float* __restrict__ ctx,
    const float* __restrict__ dinv, float* __restrict__ att)
{
    __shared__ __align__(16) float Qs[32][68];
    __shared__ __align__(16) float Cs[32][68];
    int bh = blockIdx.y; int b = bh / GH, h = bh % GH;
    int n0 = blockIdx.x * 64;
    int tid = threadIdx.x;
    int tx = tid & 15, ty = tid >> 4;
    float acc[4][4] = {};
    const float* qbase = qp + ((size_t)bh * NN + n0) * NBF;
    const float* cbase = ctx + (size_t)bh * 256 * 68;
    for (int k0 = 0; k0 < 256; k0 += 32) {
        int r = tid >> 3, c4 = (tid & 7) * 4;
#pragma unroll
        for (int i = 0; i < 2; i++) {
            float4 v = *(const float4*)(qbase + (size_t)(r + i * 32) * NBF + k0 + c4);
            Qs[c4+0][r+i*32] = v.x; Qs[c4+1][r+i*32] = v.y;
            Qs[c4+2][r+i*32] = v.z; Qs[c4+3][r+i*32] = v.w;
        }
        int cr = tid >> 4, cc4 = (tid & 15) * 4;
#pragma unroll
        for (int i = 0; i < 2; i++) {
            float4 v = *(const float4*)(cbase + (size_t)(k0 + cr + i * 16) * 68 + cc4);
            *(float4*)&Cs[cr + i * 16][cc4] = v;
        }
        __syncthreads();
#pragma unroll
        for (int kk = 0; kk < 32; kk++) {
            float4 a  = *(const float4*)&Qs[kk][ty*4];
            float4 bv = *(const float4*)&Cs[kk][tx*4];
            float av[4] = {a.x,a.y,a.z,a.w}, bb[4] = {bv.x,bv.y,bv.z,bv.w};
#pragma unroll
            for (int i = 0; i < 4; i++)
#pragma unroll
                for (int j = 0; j < 4; j++) acc[i][j] += av[i] * bb[j];
        }
        __syncthreads();
    }
#pragma unroll
    for (int i = 0; i < 4; i++) {
        int n = n0 + ty * 4 + i;
        float di = dinv[(size_t)bh * NN + n];
        float4 o = {acc[i][0]*di, acc[i][1]*di, acc[i][2]*di, acc[i][3]*di};
        *(float4*)(att + ((size_t)b * NN + n) * DIMM + h * 64 + tx * 4) = o;
    }
}

// ---------------- RoPE for local heads ----------------
__global__ void rope_kernel(const float* __restrict__ q, const float* __restrict__ k,
                            float* __restrict__ rq, float* __restrict__ rk)
{
    int idx = blockIdx.x * blockDim.x + threadIdx.x;
    int i = idx & 31;
    int n = (idx >> 5) & (NN - 1);
    int bh = idx >> 18;
    int b = bh >> 1, lh = bh & 1;
    float invf = (float)exp(-(double)(2 * i) / 64.0 * 9.210340371976184);
    float ang = (float)n * invf;
    float s, c;
    sincosf(ang, &s, &c);
    size_t base = ((size_t)b * NN + n) * DIMM + (GH + lh) * 64;
    float q1 = q[base + i], q2 = q[base + 32 + i];
    float k1 = k[base + i], k2 = k[base + 32 + i];
    size_t ob = ((size_t)bh * NN + n) * DH;
    rq[ob + i]      = q1 * c - q2 * s;
    rq[ob + 32 + i] = q2 * c + q1 * s;
    rk[ob + i]      = k1 * c - k2 * s;
    rk[ob + 32 + i] = k2 * c + k1 * s;
}

// ---------------- local scores = 0.125 * bq @ bk3^T with masking ----------------
__global__ void __launch_bounds__(256) lscore_kernel(
    const float* __restrict__ rq, const float* __restrict__ rk, float* __restrict__ sc)
{
    __shared__ __align__(16) float Qs[64][68];
    __shared__ __align__(16) float Ks[64][68];
    int bw = blockIdx.z; int bh = bw >> 5; int w = bw & 31;
    int m0 = blockIdx.y * 64, c0 = blockIdx.x * 64;
    int tid = threadIdx.x;
    int lr = tid >> 2, lc4 = (tid & 3) * 4;
    const float* qb = rq + ((size_t)bh * NN + w * WINSZ + m0) * DH;
    const float* kb = rk + (size_t)bh * NN * DH;
    int knr = (w - 1) * WINSZ + c0 + lr;
    bool kvalid = (unsigned)knr < (unsigned)NN;
#pragma unroll
    for (int i = 0; i < 4; i++) {
        int c = lc4 + i * 16;
        float4 va = *(const float4*)(qb + (size_t)lr * DH + c);
        Qs[c+0][lr] = va.x; Qs[c+1][lr] = va.y; Qs[c+2][lr] = va.z; Qs[c+3][lr] = va.w;
        float4 vk = make_float4(0.f, 0.f, 0.f, 0.f);
        if (kvalid) vk = *(const float4*)(kb + (size_t)knr * DH + c);
        Ks[c+0][lr] = vk.x; Ks[c+1][lr] = vk.y; Ks[c+2][lr] = vk.z; Ks[c+3][lr] = vk.w;
    }
    __syncthreads();
    int tx = tid & 15, ty = tid >> 4;
    float acc[4][4] = {};
#pragma unroll
    for (int kk = 0; kk < 64; kk++) {
        float4 a  = *(const float4*)&Qs[kk][ty*4];
        float4 bv = *(const float4*)&Ks[kk][tx*4];
        float av[4] = {a.x,a.y,a.z,a.w}, bb[4] = {bv.x,bv.y,bv.z,bv.w};
#pragma unroll
        for (int i = 0; i < 4; i++)
#pragma unroll
            for (int j = 0; j < 4; j++) acc[i][j] += av[i] * bb[j];
    }
    int kn0 = (w - 1) * WINSZ + c0 + tx * 4;
    bool valid = (unsigned)kn0 < (unsigned)NN;
    float* ob = sc + ((size_t)bw * WINSZ + m0) * 768 + c0;
#pragma unroll
    for (int i = 0; i < 4; i++) {
        float4 o;
        o.x = valid ? acc[i][0] * 0.125f : -1e9f;
        o.y = valid ? acc[i][1] * 0.125f : -1e9f;
        o.z = valid ? acc[i][2] * 0.125f : -1e9f;
        o.w = valid ? acc[i][3] * 0.125f : -1e9f;
        *(float4*)(ob + (size_t)(ty * 4 + i) * 768 + tx * 4) = o;
    }
}

// ---------------- row stats: m and 1/sum(exp) per score row ----------------
__global__ void rowstats_kernel(const float* __restrict__ sc,
                                float* __restrict__ rm, float* __restrict__ rs)
{
    int row = blockIdx.x * 8 + (threadIdx.x >> 5);
    int lane = threadIdx.x & 31;
    const float* r = sc + (size_t)row * 768;
    float vals[24];
    float m = -1e30f;
#pragma unroll
    for (int i = 0; i < 24; i++) { vals[i] = r[lane + i * 32]; m = fmaxf(m, vals[i]); }
#pragma unroll
    for (int o = 16; o > 0; o >>= 1) m = fmaxf(m, __shfl_xor_sync(0xffffffffu, m, o));
    float s = 0.f;
#pragma unroll
    for (int i = 0; i < 24; i++) s += expf(vals[i] - m);
#pragma unroll
    for (int o = 16; o > 0; o >>= 1) s += __shfl_xor_sync(0xffffffffu, s, o);
    if (lane == 0) { rm[row] = m; rs[row] = 1.f / s; }
}

// ---------------- out_l = softmax(sc) @ bv3 -> att (exp fused in load) ----------------
__global__ void __launch_bounds__(256) outl_kernel(
    const float* __restrict__ sc, const float* __restrict__ rm, const float* __restrict__ rs,
    const float* __restrict__ v, float* __restrict__ att)
{
    __shared__ __align__(16) float As[32][68];
    __shared__ __align__(16) float Vs[32][68];
    __shared__ float sm_m[64], sm_is[64];
    int bw = blockIdx.y; int bh = bw >> 5; int w = bw & 31;
    int b = bh >> 1, lh = bh & 1;
    int m0 = blockIdx.x * 64;
    int tid = threadIdx.x;
    int tx = tid & 15, ty = tid >> 4;
    int rowbase = bw * WINSZ + m0;
    if (tid < 64) { sm_m[tid] = rm[rowbase + tid]; sm_is[tid] = rs[rowbase + tid]; }
    __syncthreads();
    float acc[4][4] = {};
    const float* sb = sc + (size_t)rowbase * 768;
    const float* vb = v + (size_t)b * NN * DIMM + (GH + lh) * 64;
    for (int k0 = 0; k0 < 768; k0 += 32) {
#pragma unroll
        for (int i = 0; i < 2; i++) {
            int s1 = tid + i * 256;
            {
                int r = s1 >> 3, c4 = (s1 & 7) * 4;
                float4 a = *(const float4*)(sb + (size_t)r * 768 + k0 + c4);
                float mm = sm_m[r], is = sm_is[r];
                As[c4+0][r] = expf(a.x - mm) * is;
                As[c4+1][r] = expf(a.y - mm) * is;
                As[c4+2][r] = expf(a.z - mm) * is;
                As[c4+3][r] = expf(a.w - mm) * is;
            }
            {
                int kr = s1 >> 4, c4 = (s1 & 15) * 4;
                int kn = (w - 1) * WINSZ + k0 + kr;
                float4 vv = make_float4(0.f, 0.f, 0.f, 0.f);
                if ((unsigned)kn < (unsigned)NN)
                    vv = *(const float4*)(vb + (size_t)kn * DIMM + c4);
                *(float4*)&Vs[kr][c4] = vv;
            }
        }
        __syncthreads();
#pragma unroll
        for (int kk = 0; kk < 32; kk++) {
            float4 a  = *(const float4*)&As[kk][ty*4];
            float4 bv = *(const float4*)&Vs[kk][tx*4];
            float av[4] = {a.x,a.y,a.z,a.w}, bb[4] = {bv.x,bv.y,bv.z,bv.w};
#pragma unroll
            for (int i = 0; i < 4; i++)
#pragma unroll
                for (int j = 0; j < 4; j++) acc[i][j] += av[i] * bb[j];
        }
        __syncthreads();
    }
#pragma unroll
    for (int i = 0; i < 4; i++) {
        int n = w * WINSZ + m0 + ty * 4 + i;
        float4 o = {acc[i][0], acc[i][1], acc[i][2], acc[i][3]};
        *(float4*)(att + ((size_t)b * NN + n) * DIMM + (GH + lh) * 64 + tx * 4) = o;
    }
}

// ---------------- launcher ----------------
extern "C" void kernel_launch(void* const* d_in, const int* in_sizes, int n_in,
                              void* d_out, int out_size)
{
    (void)in_sizes; (void)n_in; (void)out_size;
    const float* x    = (const float*)d_in[0];
    const float* Wq   = (const float*)d_in[1];
    const float* Wk   = (const float*)d_in[2];
    const float* Wv   = (const float*)d_in[3];
    const float* Wo   = (const float*)d_in[4];
    const float* bo   = (const float*)d_in[5];
    const float* proj = (const float*)d_in[6];
    float* out = (float*)d_out;

    float *q, *k, *v, *qp, *kp, *kdg, *kmp, *km, *part, *ctx, *dinv, *att, *sc, *rq, *rk, *rm, *rs, *bt, *wot;
    cudaGetSymbolAddress((void**)&q, g_q);
    cudaGetSymbolAddress((void**)&k, g_k);
    cudaGetSymbolAddress((void**)&v, g_v);
    cudaGetSymbolAddress((void**)&qp, g_qp);
    cudaGetSymbolAddress((void**)&kp, g_kp);
    cudaGetSymbolAddress((void**)&kdg, g_kdiag);
    cudaGetSymbolAddress((void**)&kmp, g_kmaxp);
    cudaGetSymbolAddress((void**)&km, g_kmax);
    cudaGetSymbolAddress((void**)&part, g_part);
    cudaGetSymbolAddress((void**)&ctx, g_ctx);
    cudaGetSymbolAddress((void**)&dinv, g_dinv);
    cudaGetSymbolAddress((void**)&att, g_att);
    cudaGetSymbolAddress((void**)&sc, g_sc);
    cudaGetSymbolAddress((void**)&rq, g_rq);
    cudaGetSymbolAddress((void**)&rk, g_rk);
    cudaGetSymbolAddress((void**)&rm, g_rowm);
    cudaGetSymbolAddress((void**)&rs, g_rows);
    cudaGetSymbolAddress((void**)&bt, g_bt);
    cudaGetSymbolAddress((void**)&wot, g_wot);

    cudaFuncSetAttribute(gemm_bf3, cudaFuncAttributeMaxDynamicSharedMemorySize, GSMEM_BYTES);

    const int M = BB * NN; // 16384

    // Transpose weights to [n][k] once
    dim3 tb(32, 8), tg(16, 16);
    wtrans<<<tg, tb>>>(Wq, bt);
    wtrans<<<tg, tb>>>(Wk, bt + 512 * 512);
    wtrans<<<tg, tb>>>(Wv, bt + 1024 * 512);
    wtrans<<<tg, tb>>>(Wo, wot);

    dim3 gt(DIMM / 64, M / 128);
    gemm_bf3<<<gt, 256, GSMEM_BYTES>>>(x, bt, nullptr, q, M, DIMM, DIMM);
    gemm_bf3<<<gt, 256, GSMEM_BYTES>>>(x, bt + 512 * 512, nullptr, k, M, DIMM, DIMM);
    gemm_bf3<<<gt, 256, GSMEM_BYTES>>>(x, bt + 1024 * 512, nullptr, v, M, DIMM, DIMM);

    dim3 gdd(NN / 64, BHG);
    ddq_fused<<<gdd, 256>>>(q, proj, qp);
    ddk_fused<<<gdd, 256>>>(k, proj, kp, kdg, kmp);
    kmax_final_kernel<<<BHG, 128>>>(kmp, km);

    ctx_partial_kernel<<<dim3(BHG, NSPLIT), 256>>>(kp, kdg, km, v, part);
    ctx_reduce_kernel<<<(BHG * 256 * 65 + 255) / 256, 256>>>(part, ctx);

    denom_kernel<<<BHG * NN / 8, 256>>>(qp, ctx, dinv);
    outg_kernel<<<dim3(NN / 64, BHG), 256>>>(qp, ctx, dinv, att);

    rope_kernel<<<BHL * NN * 32 / 256, 256>>>(q, k, rq, rk);
    lscore_kernel<<<dim3(12, 4, BHL * NWIN), 256>>>(rq, rk, sc);
    rowstats_kernel<<<BHL * NWIN * WINSZ / 8, 256>>>(sc, rm, rs);
    outl_kernel<<<dim3(4, BHL * NWIN), 256>>>(sc, rm, rs, v, att);

    gemm_bf3<<<gt, 256, GSMEM_BYTES>>>(att, wot, bo, out, M, DIMM, DIMM);
}

// round 11
// speedup vs baseline: 1.5510x; 1.0794x over previous
#include <cuda_runtime.h>
#include <cuda_bf16.h>
#include <math.h>
#include <stdint.h>

#define BB 2
#define NN 8192
#define DIMM 512
#define GH 6
#define DH 64
#define NBF 256
#define NWIN 32
#define WINSZ 256
#define BHG (BB*GH)      // 12
#define BHL 4            // B * LOCAL_HEADS
#define NSPLIT 32

// ---------------- scratch (device globals: alloc-free) ----------------
__device__ float g_q[BB*NN*DIMM];
__device__ float g_k[BB*NN*DIMM];
__device__ float g_v[BB*NN*DIMM];
__device__ float g_qp[BHG*NN*NBF];
__device__ float g_kp[BHG*NN*NBF];      // raw k dd scores
__device__ float g_kdiag[BHG*NN];
__device__ float g_kmaxp[BHG*128];
__device__ float g_kmax[BHG];
__device__ float g_part[BHG*NSPLIT*256*65];
__device__ float g_ctx[BHG*256*68];
__device__ float g_dinv[BHG*NN];
__device__ float g_att[BB*NN*DIMM];
__device__ float g_sc[(size_t)BHL*NWIN*WINSZ*768];
__device__ float g_rq[BHL*NN*DH];
__device__ float g_rk[BHL*NN*DH];
__device__ float g_rowm[BHL*NWIN*WINSZ];
__device__ float g_rows[BHL*NWIN*WINSZ];
__device__ float g_bt[3*512*512];   // Wq/Wk/Wv transposed: [n][k]
__device__ float g_wot[512*512];    // Wo transposed: [n][k]

// ================= bf16 hi/lo split helpers =================
__device__ __forceinline__ void cvt_hl(float f0, float f1, uint32_t& hi, uint32_t& lo) {
    __nv_bfloat16 h0 = __float2bfloat16_rn(f0), h1 = __float2bfloat16_rn(f1);
    float r0 = f0 - __bfloat162float(h0), r1 = f1 - __bfloat162float(h1);
    __nv_bfloat162 hh; hh.x = h0; hh.y = h1;
    __nv_bfloat162 ll = __floats2bfloat162_rn(r0, r1);
    hi = *reinterpret_cast<uint32_t*>(&hh);
    lo = *reinterpret_cast<uint32_t*>(&ll);
}
__device__ __forceinline__ void mma_bf16(float* c, const uint32_t* a, const uint32_t* b) {
    asm volatile(
        "mma.sync.aligned.m16n8k16.row.col.f32.bf16.bf16.f32 "
        "{%0,%1,%2,%3}, {%4,%5,%6,%7}, {%8,%9}, {%0,%1,%2,%3};"
        : "+f"(c[0]), "+f"(c[1]), "+f"(c[2]), "+f"(c[3])
        : "r"(a[0]), "r"(a[1]), "r"(a[2]), "r"(a[3]), "r"(b[0]), "r"(b[1]));
}

// ================= weight transpose (all 4 in one launch) =================
__global__ void wtrans4(const float* __restrict__ W0, const float* __restrict__ W1,
                        const float* __restrict__ W2, const float* __restrict__ W3,
                        float* __restrict__ o0, float* __restrict__ o1,
                        float* __restrict__ o2, float* __restrict__ o3)
{
    __shared__ float t[32][33];
    const float* W = (blockIdx.z == 0) ? W0 : (blockIdx.z == 1) ? W1 : (blockIdx.z == 2) ? W2 : W3;
    float* out = (blockIdx.z == 0) ? o0 : (blockIdx.z == 1) ? o1 : (blockIdx.z == 2) ? o2 : o3;
    int n0 = blockIdx.x * 32, k0 = blockIdx.y * 32;
    int tx = threadIdx.x, ty = threadIdx.y;
#pragma unroll
    for (int i = ty; i < 32; i += 8) t[i][tx] = W[(size_t)(k0 + i) * 512 + n0 + tx];
    __syncthreads();
#pragma unroll
    for (int i = ty; i < 32; i += 8) out[(size_t)(n0 + i) * 512 + k0 + tx] = t[tx][i];
}

// ================= bf16x3 tensor-core GEMM (mma.sync m16n8k16) =================
#define STW 20
#define STAGE_W 7680
#define GSMEM_BYTES (2*STAGE_W*4)

__global__ void __launch_bounds__(256, 2) gemm_bf3(
    const float* __restrict__ A, const float* __restrict__ Bt,
    const float* __restrict__ bias, float* __restrict__ C,
    int M, int Nn, int K)
{
    extern __shared__ uint32_t smw[];
    int tid = threadIdx.x;
    int wid = tid >> 5, lane = tid & 31;
    int wm = wid >> 1, wn = wid & 1;
    int m0 = blockIdx.y * 128, n0 = blockIdx.x * 64;
    int r = lane >> 2, cq = lane & 3;
    float acc[2][4][4] = {};

    int arow = tid >> 1, akq = (tid & 1) * 16;
    int brow = tid >> 2, bkq = (tid & 3) * 8;
    const float* aptr = A + (size_t)(m0 + arow) * K + akq;
    const float* bptr = Bt + (size_t)(n0 + brow) * K + bkq;

    float4 pa[4], pb[2];

#define LOAD_REGS(k0) do { \
    pa[0] = *(const float4*)(aptr + (k0)); \
    pa[1] = *(const float4*)(aptr + (k0) + 4); \
    pa[2] = *(const float4*)(aptr + (k0) + 8); \
    pa[3] = *(const float4*)(aptr + (k0) + 12); \
    pb[0] = *(const float4*)(bptr + (k0)); \
    pb[1] = *(const float4*)(bptr + (k0) + 4); \
} while (0)

#define STORE_STAGE(s) do { \
    uint32_t* Ah = smw + (s) * STAGE_W; \
    uint32_t* Al = Ah + 2560; \
    uint32_t* Bh = Ah + 5120; \
    uint32_t* Bl = Ah + 6400; \
    float av[16] = {pa[0].x,pa[0].y,pa[0].z,pa[0].w, pa[1].x,pa[1].y,pa[1].z,pa[1].w, \
                    pa[2].x,pa[2].y,pa[2].z,pa[2].w, pa[3].x,pa[3].y,pa[3].z,pa[3].w}; \
    uint32_t ahv[8], alv[8]; \
    _Pragma("unroll") \
    for (int i = 0; i < 8; i++) cvt_hl(av[2*i], av[2*i+1], ahv[i], alv[i]); \
    int aoff = arow * STW + (akq >> 1); \
    *(uint4*)(Ah + aoff)     = make_uint4(ahv[0], ahv[1], ahv[2], ahv[3]); \
    *(uint4*)(Ah + aoff + 4) = make_uint4(ahv[4], ahv[5], ahv[6], ahv[7]); \
    *(uint4*)(Al + aoff)     = make_uint4(alv[0], alv[1], alv[2], alv[3]); \
    *(uint4*)(Al + aoff + 4) = make_uint4(alv[4], alv[5], alv[6], alv[7]); \
    float bv[8] = {pb[0].x,pb[0].y,pb[0].z,pb[0].w, pb[1].x,pb[1].y,pb[1].z,pb[1].w}; \
    uint32_t bhv[4], blv[4]; \
    _Pragma("unroll") \
    for (int i = 0; i < 4; i++) cvt_hl(bv[2*i], bv[2*i+1], bhv[i], blv[i]); \
    int boff = brow * STW + (bkq >> 1); \
    *(uint4*)(Bh + boff) = make_uint4(bhv[0], bhv[1], bhv[2], bhv[3]); \
    *(uint4*)(Bl + boff) = make_uint4(blv[0], blv[1], blv[2], blv[3]); \
} while (0)

#define DO_MMA(s) do { \
    const uint32_t* Ah = smw + (s) * STAGE_W; \
    const uint32_t* Al = Ah + 2560; \
    const uint32_t* Bh = Ah + 5120; \
    const uint32_t* Bl = Ah + 6400; \
    _Pragma("unroll") \
    for (int ks = 0; ks < 2; ks++) { \
        int ko = ks * 8; \
        uint32_t ah[2][4], al[2][4], bh[4][2], bl[4][2]; \
        _Pragma("unroll") \
        for (int mt = 0; mt < 2; mt++) { \
            int mr = (wm * 32 + mt * 16 + r) * STW + ko + cq; \
            ah[mt][0] = Ah[mr];           ah[mt][1] = Ah[mr + 8 * STW]; \
            ah[mt][2] = Ah[mr + 4];       ah[mt][3] = Ah[mr + 8 * STW + 4]; \
            al[mt][0] = Al[mr];           al[mt][1] = Al[mr + 8 * STW]; \
            al[mt][2] = Al[mr + 4];       al[mt][3] = Al[mr + 8 * STW + 4]; \
        } \
        _Pragma("unroll") \
        for (int nt = 0; nt < 4; nt++) { \
            int nr = (wn * 32 + nt * 8 + r) * STW + ko + cq; \
            bh[nt][0] = Bh[nr]; bh[nt][1] = Bh[nr + 4]; \
            bl[nt][0] = Bl[nr]; bl[nt][1] = Bl[nr + 4]; \
        } \
        _Pragma("unroll") \
        for (int mt = 0; mt < 2; mt++) \
            _Pragma("unroll") \
            for (int nt = 0; nt < 4; nt++) { \
                mma_bf16(acc[mt][nt], ah[mt], bh[nt]); \
                mma_bf16(acc[mt][nt], ah[mt], bl[nt]); \
                mma_bf16(acc[mt][nt], al[mt], bh[nt]); \
            } \
    } \
} while (0)

    const int NC = K / 32;
    LOAD_REGS(0);
    STORE_STAGE(0);
    __syncthreads();
    for (int it = 0; it < NC; ++it) {
        if (it + 1 < NC) LOAD_REGS((it + 1) * 32);
        DO_MMA(it & 1);
        if (it + 1 < NC) {
            __syncthreads();
            STORE_STAGE((it + 1) & 1);
            __syncthreads();
        }
    }

#pragma unroll
    for (int mt = 0; mt < 2; mt++)
#pragma unroll
        for (int nt = 0; nt < 4; nt++) {
            int row = m0 + wm * 32 + mt * 16 + r;
            int col = n0 + wn * 32 + nt * 8 + 2 * cq;
            float2 v0 = make_float2(acc[mt][nt][0], acc[mt][nt][1]);
            float2 v1 = make_float2(acc[mt][nt][2], acc[mt][nt][3]);
            if (bias) {
                float2 bv = *(const float2*)(bias + col);
                v0.x += bv.x; v0.y += bv.y;
                v1.x += bv.x; v1.y += bv.y;
            }
            *(float2*)(C + (size_t)row * Nn + col) = v0;
            *(float2*)(C + (size_t)(row + 8) * Nn + col) = v1;
        }
#undef LOAD_REGS
#undef STORE_STAGE
#undef DO_MMA
}

// ================= dd via bf16x3 mma: CTA = 64 rows x 256 features, K=64 =================
// Warp grid 2(m) x 4(n); warp tile 32 rows x 64 cols; acc[2][8][4].
// A smem: 64 rows x 8 words (stride 12); B smem: 256 rows x 8 words (stride 12).
#define DSTW 12

// common mainloop producing acc + sumsq (of normed A row elems handled by this loader thread)
#define DD_MAINLOOP() \
    float acc[2][8][4]; \
    _Pragma("unroll") \
    for (int i = 0; i < 2; i++) _Pragma("unroll") for (int j = 0; j < 8; j++) \
        _Pragma("unroll") for (int t = 0; t < 4; t++) acc[i][j][t] = 0.f; \
    int ar = tid >> 2, akq = (tid & 3) * 4; \
    const float* ab = data + ((size_t)b * NN + n0 + ar) * DIMM + h * 64 + akq; \
    const float* pbb = proj + (size_t)tid * 64; \
    float sumsq = 0.f; \
    for (int kc = 0; kc < 4; kc++) { \
        float4 va = *(const float4*)(ab + kc * 16); \
        float x0 = va.x * NORM, x1 = va.y * NORM, x2 = va.z * NORM, x3 = va.w * NORM; \
        sumsq += x0 * x0 + x1 * x1 + x2 * x2 + x3 * x3; \
        uint32_t ah0, al0, ah1, al1; \
        cvt_hl(x0, x1, ah0, al0); cvt_hl(x2, x3, ah1, al1); \
        float4 vb0 = *(const float4*)(pbb + kc * 16); \
        float4 vb1 = *(const float4*)(pbb + kc * 16 + 4); \
        float4 vb2 = *(const float4*)(pbb + kc * 16 + 8); \
        float4 vb3 = *(const float4*)(pbb + kc * 16 + 12); \
        float bvv[16] = {vb0.x,vb0.y,vb0.z,vb0.w, vb1.x,vb1.y,vb1.z,vb1.w, \
                         vb2.x,vb2.y,vb2.z,vb2.w, vb3.x,vb3.y,vb3.z,vb3.w}; \
        uint32_t bhv[8], blv[8]; \
        _Pragma("unroll") \
        for (int i = 0; i < 8; i++) cvt_hl(bvv[2*i], bvv[2*i+1], bhv[i], blv[i]); \
        __syncthreads(); \
        *(uint2*)(Ahs + ar * DSTW + (akq >> 1)) = make_uint2(ah0, ah1); \
        *(uint2*)(Als + ar * DSTW + (akq >> 1)) = make_uint2(al0, al1); \
        *(uint4*)(Bhs + tid * DSTW)     = make_uint4(bhv[0], bhv[1], bhv[2], bhv[3]); \
        *(uint4*)(Bhs + tid * DSTW + 4) = make_uint4(bhv[4], bhv[5], bhv[6], bhv[7]); \
        *(uint4*)(Bls + tid * DSTW)     = make_uint4(blv[0], blv[1], blv[2], blv[3]); \
        *(uint4*)(Bls + tid * DSTW + 4) = make_uint4(blv[4], blv[5], blv[6], blv[7]); \
        __syncthreads(); \
        uint32_t afh[2][4], afl[2][4]; \
        _Pragma("unroll") \
        for (int mt = 0; mt < 2; mt++) { \
            int mr = (wm * 32 + mt * 16 + r) * DSTW + cq; \
            afh[mt][0] = Ahs[mr];       afh[mt][1] = Ahs[mr + 8 * DSTW]; \
            afh[mt][2] = Ahs[mr + 4];   afh[mt][3] = Ahs[mr + 8 * DSTW + 4]; \
            afl[mt][0] = Als[mr];       afl[mt][1] = Als[mr + 8 * DSTW]; \
            afl[mt][2] = Als[mr + 4];   afl[mt][3] = Als[mr + 8 * DSTW + 4]; \
        } \
        _Pragma("unroll") \
        for (int nt = 0; nt < 8; nt++) { \
            int nr = (wn * 64 + nt * 8 + r) * DSTW + cq; \
            uint32_t bf[2] = {Bhs[nr], Bhs[nr + 4]}; \
            uint32_t bg[2] = {Bls[nr], Bls[nr + 4]}; \
            _Pragma("unroll") \
            for (int mt = 0; mt < 2; mt++) { \
                mma_bf16(acc[mt][nt], afh[mt], bf); \
                mma_bf16(acc[mt][nt], afh[mt], bg); \
                mma_bf16(acc[mt][nt], afl[mt], bf); \
            } \
        } \
    }

__global__ void __launch_bounds__(256, 2) ddq_mma(
    const float* __restrict__ data, const float* __restrict__ proj, float* __restrict__ qp)
{
    __shared__ uint32_t Ahs[64*DSTW], Als[64*DSTW], Bhs[256*DSTW], Bls[256*DSTW];
    __shared__ float ssq[64][4];
    __shared__ float wred[64][4];
    __shared__ float rowbase[64];
    int bh = blockIdx.y; int b = bh / GH, h = bh % GH;
    int n0 = blockIdx.x * 64;
    int tid = threadIdx.x;
    int wid = tid >> 5, lane = tid & 31;
    int wm = wid >> 2, wn = wid & 3;
    int r = lane >> 2, cq = lane & 3;
    const float NORM = 0.35355339059327373f;

    DD_MAINLOOP();

    ssq[ar][tid & 3] = sumsq;
    // per-thread row maxes: [mt][half]
    float mx[2][2];
#pragma unroll
    for (int mt = 0; mt < 2; mt++)
#pragma unroll
        for (int hf = 0; hf < 2; hf++) {
            float m = -1e30f;
#pragma unroll
            for (int nt = 0; nt < 8; nt++)
                m = fmaxf(m, fmaxf(acc[mt][nt][hf*2], acc[mt][nt][hf*2+1]));
            m = fmaxf(m, __shfl_xor_sync(0xffffffffu, m, 1));
            m = fmaxf(m, __shfl_xor_sync(0xffffffffu, m, 2));
            mx[mt][hf] = m;
        }
    if (cq == 0) {
#pragma unroll
        for (int mt = 0; mt < 2; mt++)
#pragma unroll
            for (int hf = 0; hf < 2; hf++)
                wred[wm * 32 + mt * 16 + hf * 8 + r][wn] = mx[mt][hf];
    }
    __syncthreads();
    if (tid < 64) {
        float mm = fmaxf(fmaxf(wred[tid][0], wred[tid][1]), fmaxf(wred[tid][2], wred[tid][3]));
        float dg = 0.5f * (ssq[tid][0] + ssq[tid][1] + ssq[tid][2] + ssq[tid][3]);
        rowbase[tid] = dg + mm;
    }
    __syncthreads();
#pragma unroll
    for (int mt = 0; mt < 2; mt++) {
        int row_a = wm * 32 + mt * 16 + r, row_b = row_a + 8;
        float ba = rowbase[row_a], bb2 = rowbase[row_b];
        float* oa = qp + ((size_t)bh * NN + n0 + row_a) * NBF;
        float* ob = qp + ((size_t)bh * NN + n0 + row_b) * NBF;
#pragma unroll
        for (int nt = 0; nt < 8; nt++) {
            int col = wn * 64 + nt * 8 + 2 * cq;
            float2 o1, o2;
            o1.x = 0.0625f * (expf(acc[mt][nt][0] - ba) + 1e-4f);
            o1.y = 0.0625f * (expf(acc[mt][nt][1] - ba) + 1e-4f);
            o2.x = 0.0625f * (expf(acc[mt][nt][2] - bb2) + 1e-4f);
            o2.y = 0.0625f * (expf(acc[mt][nt][3] - bb2) + 1e-4f);
            *(float2*)(oa + col) = o1;
            *(float2*)(ob + col) = o2;
        }
    }
}

__global__ void __launch_bounds__(256, 2) ddk_mma(
    const float* __restrict__ data, const float* __restrict__ proj,
    float* __restrict__ kdd, float* __restrict__ kdiag, float* __restrict__ kmaxp)
{
    __shared__ uint32_t Ahs[64*DSTW], Als[64*DSTW], Bhs[256*DSTW], Bls[256*DSTW];
    __shared__ float ssq[64][4];
    __shared__ float red[8];
    int bh = blockIdx.y; int b = bh / GH, h = bh % GH;
    int n0 = blockIdx.x * 64;
    int tid = threadIdx.x;
    int wid = tid >> 5, lane = tid & 31;
    int wm = wid >> 2, wn = wid & 3;
    int r = lane >> 2, cq = lane & 3;
    const float NORM = 0.35355339059327373f;

    DD_MAINLOOP();

    ssq[ar][tid & 3] = sumsq;
    __syncthreads();
    if (tid < 64)
        kdiag[(size_t)bh * NN + n0 + tid] =
            0.5f * (ssq[tid][0] + ssq[tid][1] + ssq[tid][2] + ssq[tid][3]);
    // block max + raw writes
    float tmax = -1e30f;
#pragma unroll
    for (int mt = 0; mt < 2; mt++) {
        int row_a = wm * 32 + mt * 16 + r, row_b = row_a + 8;
        float* oa = kdd + ((size_t)bh * NN + n0 + row_a) * NBF;
        float* ob = kdd + ((size_t)bh * NN + n0 + row_b) * NBF;
#pragma unroll
        for (int nt = 0; nt < 8; nt++) {
            int col = wn * 64 + nt * 8 + 2 * cq;
            float2 o1 = make_float2(acc[mt][nt][0], acc[mt][nt][1]);
            float2 o2 = make_float2(acc[mt][nt][2], acc[mt][nt][3]);
            tmax = fmaxf(tmax, fmaxf(fmaxf(o1.x, o1.y), fmaxf(o2.x, o2.y)));
            *(float2*)(oa + col) = o1;
            *(float2*)(ob + col) = o2;
        }
    }
#pragma unroll
    for (int o = 16; o > 0; o >>= 1) tmax = fmaxf(tmax, __shfl_xor_sync(0xffffffffu, tmax, o));
    if (lane == 0) red[wid] = tmax;
    __syncthreads();
    if (tid == 0) {
        float z = red[0];
#pragma unroll
        for (int i = 1; i < 8; i++) z = fmaxf(z, red[i]);
        kmaxp[bh * 128 + blockIdx.x] = z;
    }
}

__global__ void kmax_final_kernel(const float* __restrict__ kpart, float* __restrict__ kmax)
{
    int bh = blockIdx.x;
    float m = kpart[bh * 128 + threadIdx.x];
#pragma unroll
    for (int o = 16; o > 0; o >>= 1) m = fmaxf(m, __shfl_xor_sync(0xffffffffu, m, o));
    __shared__ float red[4];
    if ((threadIdx.x & 31) == 0) red[threadIdx.x >> 5] = m;
    __syncthreads();
    if (threadIdx.x == 0)
        kmax[bh] = fmaxf(fmaxf(red[0], red[1]), fmaxf(red[2], red[3]));
}

// ---------------- ctx: exp applied inline on raw kdd ----------------
__global__ void __launch_bounds__(256) ctx_partial_kernel(
    const float* __restrict__ kdd, const float* __restrict__ kdiag,
    const float* __restrict__ kmax, const float* __restrict__ v, float* __restrict__ part)
{
    int bh = blockIdx.x, sp = blockIdx.y;
    int b = bh / GH, h = bh % GH;
    int j = threadIdx.x;
    float acc[65];
#pragma unroll
    for (int d = 0; d < 65; d++) acc[d] = 0.f;
    __shared__ __align__(16) float vs[16][68];
    float km = kmax[bh];
    const float* kpb = kdd + ((size_t)bh * NN + sp * 256) * NBF + j;
    const float* dgb = kdiag + (size_t)bh * NN + sp * 256;
    const float* vb = v + ((size_t)b * NN + sp * 256) * DIMM + h * 64;
    for (int n0 = 0; n0 < 256; n0 += 16) {
        __syncthreads();
        int r = threadIdx.x >> 4;
        int c = (threadIdx.x & 15) * 4;
        float4 vv = *(const float4*)(vb + (size_t)(n0 + r) * DIMM + c);
        *(float4*)&vs[r][c] = vv;
        if ((threadIdx.x & 15) == 0) vs[r][64] = 1.f;
        if ((threadIdx.x & 15) == 1) vs[r][65] = dgb[n0 + r];
        __syncthreads();
#pragma unroll 2
        for (int nn = 0; nn < 16; nn++) {
            float praw = kpb[(size_t)(n0 + nn) * NBF];
            float p = 0.0625f * (expf(praw - vs[nn][65] - km) + 1e-4f);
#pragma unroll
            for (int d = 0; d < 65; d++) acc[d] += p * vs[nn][d];
        }
    }
    float* o = part + (((size_t)bh * NSPLIT + sp) * 256 + j) * 65;
#pragma unroll
    for (int d = 0; d < 65; d++) o[d] = acc[d];
}
__global__ void ctx_reduce_kernel(const float* __restrict__ part, float* __restrict__ ctx)
{
    int idx = blockIdx.x * 256 + threadIdx.x;
    if (idx >= BHG * 256 * 65) return;
    int bh = idx / (256 * 65); int rem = idx - bh * 256 * 65;
    int j = rem / 65, d = rem % 65;
    float s = 0.f;
#pragma unroll
    for (int sp = 0; sp < NSPLIT; sp++)
        s += part[(((size_t)bh * NSPLIT + sp) * 256 + j) * 65 + d];
    ctx[((size_t)bh * 256 + j) * 68 + d] = s;
}

// ---------------- d_inv = 1 / (qp . k_sum) ----------------
__global__ void denom_kernel(const float* __restrict__ qp, const float* __restrict__ ctx,
                             float* __restrict__ dinv)
{
    int row = blockIdx.x * 8 + (threadIdx.x >> 5);
    int lane = threadIdx.x & 31;
    int bh = row >> 13;
    const float* q = qp + (size_t)row * NBF;
    const float* ks = ctx + (size_t)bh * 256 * 68 + 64;
    float s = 0.f;
#pragma unroll
    for (int i = 0; i < 8; i++) s += q[lane + i * 32] * ks[(size_t)(lane + i * 32) * 68];
#pragma unroll
    for (int o = 16; o > 0; o >>= 1) s += __shfl_xor_sync(0xffffffffu, s, o);
    if (lane == 0) dinv[row] = 1.f / s;
}

// ---------------- out_g = (qp @ ctx) * d_inv -> att ----------------
__global__ void __launch_bounds__(256) outg_kernel(
    const float* __restrict__ qp, const float* __restrict__ ctx,
    const float* __restrict__ dinv, float* __restrict__ att)
{
    __shared__ __align__(16) float Qs[32][68];
    __shared__ __align__(16) float Cs[32][68];
    int bh = blockIdx.y; int b = bh / GH, h = bh % GH;
    int n0 = blockIdx.x * 64;
    int tid = threadIdx.x;
    int tx = tid & 15, ty = tid >> 4;
    float acc[4][4] = {};
    const float* qbase = qp + ((size_t)bh * NN + n0) * NBF;
    const float* cbase = ctx + (size_t)bh * 256 * 68;
    for (int k0 = 0; k0 < 256; k0 += 32) {
        int r = tid >> 3, c4 = (tid & 7) * 4;
#pragma unroll
        for (int i = 0; i < 2; i++) {
            float4 v = *(const float4*)(qbase + (size_t)(r + i * 32) * NBF + k0 + c4);
            Qs[c4+0][r+i*32] = v.x; Qs[c4+1][r+i*32] = v.y;
            Qs[c4+2][r+i*32] = v.z; Qs[c4+3][r+i*32] = v.w;
        }
        int cr = tid >> 4, cc4 = (tid & 15) * 4;
#pragma unroll
        for (int i = 0; i < 2; i++) {
            float4 v = *(const float4*)(cbase + (size_t)(k0 + cr + i * 16) * 68 + cc4);
            *(float4*)&Cs[cr + i * 16][cc4] = v;
        }
        __syncthreads();
#pragma unroll
        for (int kk = 0; kk < 32; kk++) {
            float4 a  = *(const float4*)&Qs[kk][ty*4];
            float4 bv = *(const float4*)&Cs[kk][tx*4];
            float av[4] = {a.x,a.y,a.z,a.w}, bb[4] = {bv.x,bv.y,bv.z,bv.w};
#pragma unroll
            for (int i = 0; i < 4; i++)
#pragma unroll
                for (int j = 0; j < 4; j++) acc[i][j] += av[i] * bb[j];
        }
        __syncthreads();
    }
#pragma unroll
    for (int i = 0; i < 4; i++) {
        int n = n0 + ty * 4 + i;
        float di = dinv[(size_t)bh * NN + n];
        float4 o = {acc[i][0]*di, acc[i][1]*di, acc[i][2]*di, acc[i][3]*di};
        *(float4*)(att + ((size_t)b * NN + n) * DIMM + h * 64 + tx * 4) = o;
    }
}

// ---------------- RoPE for local heads ----------------
__global__ void rope_kernel(const float* __restrict__ q, const float* __restrict__ k,
                            float* __restrict__ rq, float* __restrict__ rk)
{
    int idx = blockIdx.x * blockDim.x + threadIdx.x;
    int i = idx & 31;
    int n = (idx >> 5) & (NN - 1);
    int bh = idx >> 18;
    int b = bh >> 1, lh = bh & 1;
    float invf = (float)exp(-(double)(2 * i) / 64.0 * 9.210340371976184);
    float ang = (float)n * invf;
    float s, c;
    sincosf(ang, &s, &c);
    size_t base = ((size_t)b * NN + n) * DIMM + (GH + lh) * 64;
    float q1 = q[base + i], q2 = q[base + 32 + i];
    float k1 = k[base + i], k2 = k[base + 32 + i];
    size_t ob = ((size_t)bh * NN + n) * DH;
    rq[ob + i]      = q1 * c - q2 * s;
    rq[ob + 32 + i] = q2 * c + q1 * s;
    rk[ob + i]      = k1 * c - k2 * s;
    rk[ob + 32 + i] = k2 * c + k1 * s;
}

// ---------------- local scores = 0.125 * bq @ bk3^T with masking ----------------
__global__ void __launch_bounds__(256) lscore_kernel(
    const float* __restrict__ rq, const float* __restrict__ rk, float* __restrict__ sc)
{
    __shared__ __align__(16) float Qs[64][68];
    __shared__ __align__(16) float Ks[64][68];
    int bw = blockIdx.z; int bh = bw >> 5; int w = bw & 31;
    int m0 = blockIdx.y * 64, c0 = blockIdx.x * 64;
    int tid = threadIdx.x;
    int lr = tid >> 2, lc4 = (tid & 3) * 4;
    const float* qb = rq + ((size_t)bh * NN + w * WINSZ + m0) * DH;
    const float* kb = rk + (size_t)bh * NN * DH;
    int knr = (w - 1) * WINSZ + c0 + lr;
    bool kvalid = (unsigned)knr < (unsigned)NN;
#pragma unroll
    for (int i = 0; i < 4; i++) {
        int c = lc4 + i * 16;
        float4 va = *(const float4*)(qb + (size_t)lr * DH + c);
        Qs[c+0][lr] = va.x; Qs[c+1][lr] = va.y; Qs[c+2][lr] = va.z; Qs[c+3][lr] = va.w;
        float4 vk = make_float4(0.f, 0.f, 0.f, 0.f);
        if (kvalid) vk = *(const float4*)(kb + (size_t)knr * DH + c);
        Ks[c+0][lr] = vk.x; Ks[c+1][lr] = vk.y; Ks[c+2][lr] = vk.z; Ks[c+3][lr] = vk.w;
    }
    __syncthreads();
    int tx = tid & 15, ty = tid >> 4;
    float acc[4][4] = {};
#pragma unroll
    for (int kk = 0; kk < 64; kk++) {
        float4 a  = *(const float4*)&Qs[kk][ty*4];
        float4 bv = *(const float4*)&Ks[kk][tx*4];
        float av[4] = {a.x,a.y,a.z,a.w}, bb[4] = {bv.x,bv.y,bv.z,bv.w};
#pragma unroll
        for (int i = 0; i < 4; i++)
#pragma unroll
            for (int j = 0; j < 4; j++) acc[i][j] += av[i] * bb[j];
    }
    int kn0 = (w - 1) * WINSZ + c0 + tx * 4;
    bool valid = (unsigned)kn0 < (unsigned)NN;
    float* ob = sc + ((size_t)bw * WINSZ + m0) * 768 + c0;
#pragma unroll
    for (int i = 0; i < 4; i++) {
        float4 o;
        o.x = valid ? acc[i][0] * 0.125f : -1e9f;
        o.y = valid ? acc[i][1] * 0.125f : -1e9f;
        o.z = valid ? acc[i][2] * 0.125f : -1e9f;
        o.w = valid ? acc[i][3] * 0.125f : -1e9f;
        *(float4*)(ob + (size_t)(ty * 4 + i) * 768 + tx * 4) = o;
    }
}

// ---------------- row stats: m and 1/sum(exp) per score row ----------------
__global__ void rowstats_kernel(const float* __restrict__ sc,
                                float* __restrict__ rm, float* __restrict__ rs)
{
    int row = blockIdx.x * 8 + (threadIdx.x >> 5);
    int lane = threadIdx.x & 31;
    const float* r = sc + (size_t)row * 768;
    float vals[24];
    float m = -1e30f;
#pragma unroll
    for (int i = 0; i < 24; i++) { vals[i] = r[lane + i * 32]; m = fmaxf(m, vals[i]); }
#pragma unroll
    for (int o = 16; o > 0; o >>= 1) m = fmaxf(m, __shfl_xor_sync(0xffffffffu, m, o));
    float s = 0.f;
#pragma unroll
    for (int i = 0; i < 24; i++) s += expf(vals[i] - m);
#pragma unroll
    for (int o = 16; o > 0; o >>= 1) s += __shfl_xor_sync(0xffffffffu, s, o);
    if (lane == 0) { rm[row] = m; rs[row] = 1.f / s; }
}

// ---------------- out_l = softmax(sc) @ bv3 -> att (exp fused in load) ----------------
__global__ void __launch_bounds__(256) outl_kernel(
    const float* __restrict__ sc, const float* __restrict__ rm, const float* __restrict__ rs,
    const float* __restrict__ v, float* __restrict__ att)
{
    __shared__ __align__(16) float As[32][68];
    __shared__ __align__(16) float Vs[32][68];
    __shared__ float sm_m[64], sm_is[64];
    int bw = blockIdx.y; int bh = bw >> 5; int w = bw & 31;
    int b = bh >> 1, lh = bh & 1;
    int m0 = blockIdx.x * 64;
    int tid = threadIdx.x;
    int tx = tid & 15, ty = tid >> 4;
    int rowbase = bw * WINSZ + m0;
    if (tid < 64) { sm_m[tid] = rm[rowbase + tid]; sm_is[tid] = rs[rowbase + tid]; }
    __syncthreads();
    float acc[4][4] = {};
    const float* sb = sc + (size_t)rowbase * 768;
    const float* vb = v + (size_t)b * NN * DIMM + (GH + lh) * 64;
    for (int k0 = 0; k0 < 768; k0 += 32) {
#pragma unroll
        for (int i = 0; i < 2; i++) {
            int s1 = tid + i * 256;
            {
                int r = s1 >> 3, c4 = (s1 & 7) * 4;
                float4 a = *(const float4*)(sb + (size_t)r * 768 + k0 + c4);
                float mm = sm_m[r], is = sm_is[r];
                As[c4+0][r] = expf(a.x - mm) * is;
                As[c4+1][r] = expf(a.y - mm) * is;
                As[c4+2][r] = expf(a.z - mm) * is;
                As[c4+3][r] = expf(a.w - mm) * is;
            }
            {
                int kr = s1 >> 4, c4 = (s1 & 15) * 4;
                int kn = (w - 1) * WINSZ + k0 + kr;
                float4 vv = make_float4(0.f, 0.f, 0.f, 0.f);
                if ((unsigned)kn < (unsigned)NN)
                    vv = *(const float4*)(vb + (size_t)kn * DIMM + c4);
                *(float4*)&Vs[kr][c4] = vv;
            }
        }
        __syncthreads();
#pragma unroll
        for (int kk = 0; kk < 32; kk++) {
            float4 a  = *(const float4*)&As[kk][ty*4];
            float4 bv = *(const float4*)&Vs[kk][tx*4];
            float av[4] = {a.x,a.y,a.z,a.w}, bb[4] = {bv.x,bv.y,bv.z,bv.w};
#pragma unroll
            for (int i = 0; i < 4; i++)
#pragma unroll
                for (int j = 0; j < 4; j++) acc[i][j] += av[i] * bb[j];
        }
        __syncthreads();
    }
#pragma unroll
    for (int i = 0; i < 4; i++) {
        int n = w * WINSZ + m0 + ty * 4 + i;
        float4 o = {acc[i][0], acc[i][1], acc[i][2], acc[i][3]};
        *(float4*)(att + ((size_t)b * NN + n) * DIMM + (GH + lh) * 64 + tx * 4) = o;
    }
}

// ---------------- launcher ----------------
extern "C" void kernel_launch(void* const* d_in, const int* in_sizes, int n_in,
                              void* d_out, int out_size)
{
    (void)in_sizes; (void)n_in; (void)out_size;
    const float* x    = (const float*)d_in[0];
    const float* Wq   = (const float*)d_in[1];
    const float* Wk   = (const float*)d_in[2];
    const float* Wv   = (const float*)d_in[3];
    const float* Wo   = (const float*)d_in[4];
    const float* bo   = (const float*)d_in[5];
    const float* proj = (const float*)d_in[6];
    float* out = (float*)d_out;

    float *q, *k, *v, *qp, *kp, *kdg, *kmp, *km, *part, *ctx, *dinv, *att, *sc, *rq, *rk, *rm, *rs, *bt, *wot;
    cudaGetSymbolAddress((void**)&q, g_q);
    cudaGetSymbolAddress((void**)&k, g_k);
    cudaGetSymbolAddress((void**)&v, g_v);
    cudaGetSymbolAddress((void**)&qp, g_qp);
    cudaGetSymbolAddress((void**)&kp, g_kp);
    cudaGetSymbolAddress((void**)&kdg, g_kdiag);
    cudaGetSymbolAddress((void**)&kmp, g_kmaxp);
    cudaGetSymbolAddress((void**)&km, g_kmax);
    cudaGetSymbolAddress((void**)&part, g_part);
    cudaGetSymbolAddress((void**)&ctx, g_ctx);
    cudaGetSymbolAddress((void**)&dinv, g_dinv);
    cudaGetSymbolAddress((void**)&att, g_att);
    cudaGetSymbolAddress((void**)&sc, g_sc);
    cudaGetSymbolAddress((void**)&rq, g_rq);
    cudaGetSymbolAddress((void**)&rk, g_rk);
    cudaGetSymbolAddress((void**)&rm, g_rowm);
    cudaGetSymbolAddress((void**)&rs, g_rows);
    cudaGetSymbolAddress((void**)&bt, g_bt);
    cudaGetSymbolAddress((void**)&wot, g_wot);

    cudaFuncSetAttribute(gemm_bf3, cudaFuncAttributeMaxDynamicSharedMemorySize, GSMEM_BYTES);

    const int M = BB * NN; // 16384

    // Transpose all 4 weights in one launch
    dim3 tb(32, 8), tg(16, 16, 4);
    wtrans4<<<tg, tb>>>(Wq, Wk, Wv, Wo, bt, bt + 512 * 512, bt + 1024 * 512, wot);

    dim3 gt(DIMM / 64, M / 128);
    gemm_bf3<<<gt, 256, GSMEM_BYTES>>>(x, bt, nullptr, q, M, DIMM, DIMM);
    gemm_bf3<<<gt, 256, GSMEM_BYTES>>>(x, bt + 512 * 512, nullptr, k, M, DIMM, DIMM);
    gemm_bf3<<<gt, 256, GSMEM_BYTES>>>(x, bt + 1024 * 512, nullptr, v, M, DIMM, DIMM);

    dim3 gdd(NN / 64, BHG);
    ddq_mma<<<gdd, 256>>>(q, proj, qp);
    ddk_mma<<<gdd, 256>>>(k, proj, kp, kdg, kmp);
    kmax_final_kernel<<<BHG, 128>>>(kmp, km);

    ctx_partial_kernel<<<dim3(BHG, NSPLIT), 256>>>(kp, kdg, km, v, part);
    ctx_reduce_kernel<<<(BHG * 256 * 65 + 255) / 256, 256>>>(part, ctx);

    denom_kernel<<<BHG * NN / 8, 256>>>(qp, ctx, dinv);
    outg_kernel<<<dim3(NN / 64, BHG), 256>>>(qp, ctx, dinv, att);

    rope_kernel<<<BHL * NN * 32 / 256, 256>>>(q, k, rq, rk);
    lscore_kernel<<<dim3(12, 4, BHL * NWIN), 256>>>(rq, rk, sc);
    rowstats_kernel<<<BHL * NWIN * WINSZ / 8, 256>>>(sc, rm, rs);
    outl_kernel<<<dim3(4, BHL * NWIN), 256>>>(sc, rm, rs, v, att);

    gemm_bf3<<<gt, 256, GSMEM_BYTES>>>(att, wot, bo, out, M, DIMM, DIMM);
}

// round 12
// speedup vs baseline: 1.6127x; 1.0398x over previous
#include <cuda_runtime.h>
#include <cuda_bf16.h>
#include <math.h>
#include <stdint.h>

#define BB 2
#define NN 8192
#define DIMM 512
#define GH 6
#define DH 64
#define NBF 256
#define NWIN 32
#define WINSZ 256
#define BHG (BB*GH)      // 12
#define BHL 4            // B * LOCAL_HEADS
#define NSPLIT 32

// ---------------- scratch (device globals: alloc-free) ----------------
__device__ float g_q[BB*NN*DIMM];
__device__ float g_k[BB*NN*DIMM];
__device__ float g_v[BB*NN*DIMM];
__device__ float g_qp[BHG*NN*NBF];
__device__ float g_kp[BHG*NN*NBF];      // raw k dd scores
__device__ float g_kdiag[BHG*NN];
__device__ float g_kmaxp[BHG*128];
__device__ float g_kmax[BHG];
__device__ float g_part[BHG*NSPLIT*256*65];
__device__ float g_ctx[BHG*256*68];
__device__ float g_dinv[BHG*NN];
__device__ float g_att[BB*NN*DIMM];
__device__ float g_sc[(size_t)BHL*NWIN*WINSZ*768];
__device__ float g_rq[BHL*NN*DH];
__device__ float g_rk[BHL*NN*DH];
__device__ float g_rowm[BHL*NWIN*WINSZ];
__device__ float g_rows[BHL*NWIN*WINSZ];
__device__ float g_bt[3*512*512];   // Wq/Wk/Wv transposed: [n][k]
__device__ float g_wot[512*512];    // Wo transposed: [n][k]

// ================= bf16 hi/lo split helpers =================
__device__ __forceinline__ void cvt_hl(float f0, float f1, uint32_t& hi, uint32_t& lo) {
    __nv_bfloat16 h0 = __float2bfloat16_rn(f0), h1 = __float2bfloat16_rn(f1);
    float r0 = f0 - __bfloat162float(h0), r1 = f1 - __bfloat162float(h1);
    __nv_bfloat162 hh; hh.x = h0; hh.y = h1;
    __nv_bfloat162 ll = __floats2bfloat162_rn(r0, r1);
    hi = *reinterpret_cast<uint32_t*>(&hh);
    lo = *reinterpret_cast<uint32_t*>(&ll);
}
__device__ __forceinline__ void mma_bf16(float* c, const uint32_t* a, const uint32_t* b) {
    asm volatile(
        "mma.sync.aligned.m16n8k16.row.col.f32.bf16.bf16.f32 "
        "{%0,%1,%2,%3}, {%4,%5,%6,%7}, {%8,%9}, {%0,%1,%2,%3};"
        : "+f"(c[0]), "+f"(c[1]), "+f"(c[2]), "+f"(c[3])
        : "r"(a[0]), "r"(a[1]), "r"(a[2]), "r"(a[3]), "r"(b[0]), "r"(b[1]));
}
__device__ __forceinline__ uint32_t cvta_smem(const void* p) {
    uint32_t a;
    asm("{ .reg .u64 t; cvta.to.shared.u64 t, %1; cvt.u32.u64 %0, t; }" : "=r"(a) : "l"(p));
    return a;
}
__device__ __forceinline__ void ldsm_x4(uint32_t addr, uint32_t* d) {
    asm volatile("ldmatrix.sync.aligned.m8n8.x4.shared.b16 {%0,%1,%2,%3}, [%4];"
        : "=r"(d[0]), "=r"(d[1]), "=r"(d[2]), "=r"(d[3]) : "r"(addr));
}

// ================= weight transpose (all 4 in one launch) =================
__global__ void wtrans4(const float* __restrict__ W0, const float* __restrict__ W1,
                        const float* __restrict__ W2, const float* __restrict__ W3,
                        float* __restrict__ o0, float* __restrict__ o1,
                        float* __restrict__ o2, float* __restrict__ o3)
{
    __shared__ float t[32][33];
    const float* W = (blockIdx.z == 0) ? W0 : (blockIdx.z == 1) ? W1 : (blockIdx.z == 2) ? W2 : W3;
    float* out = (blockIdx.z == 0) ? o0 : (blockIdx.z == 1) ? o1 : (blockIdx.z == 2) ? o2 : o3;
    int n0 = blockIdx.x * 32, k0 = blockIdx.y * 32;
    int tx = threadIdx.x, ty = threadIdx.y;
#pragma unroll
    for (int i = ty; i < 32; i += 8) t[i][tx] = W[(size_t)(k0 + i) * 512 + n0 + tx];
    __syncthreads();
#pragma unroll
    for (int i = ty; i < 32; i += 8) out[(size_t)(n0 + i) * 512 + k0 + tx] = t[tx][i];
}

// ================= bf16x3 tensor-core GEMM (mma.sync m16n8k16 + ldmatrix) =================
#define STW 20
#define STAGE_W 7680
#define GSMEM_BYTES (2*STAGE_W*4)

__global__ void __launch_bounds__(256, 2) gemm_bf3(
    const float* __restrict__ A, const float* __restrict__ Bt,
    const float* __restrict__ bias, float* __restrict__ C,
    int M, int Nn, int K)
{
    extern __shared__ uint32_t smw[];
    int tid = threadIdx.x;
    int wid = tid >> 5, lane = tid & 31;
    int wm = wid >> 1, wn = wid & 1;
    int m0 = blockIdx.y * 128, n0 = blockIdx.x * 64;
    int r = lane >> 2, cq = lane & 3;
    int lr = lane & 7, lg = lane >> 3;
    float acc[2][4][4] = {};

    int arow = tid >> 1, akq = (tid & 1) * 16;
    int brow = tid >> 2, bkq = (tid & 3) * 8;
    const float* aptr = A + (size_t)(m0 + arow) * K + akq;
    const float* bptr = Bt + (size_t)(n0 + brow) * K + bkq;

    uint32_t smbase = cvta_smem(smw);
    // ldmatrix per-lane fragment base offsets (bytes), within stage
    uint32_t aoff = (uint32_t)(((wm * 32 + (lg & 1) * 8 + lr) * STW + (lg >> 1) * 4) * 4);
    uint32_t boff = (uint32_t)(((wn * 32 + (lg >> 1) * 8 + lr) * STW + (lg & 1) * 4) * 4);

    float4 pa[4], pb[2];

#define LOAD_REGS(k0) do { \
    pa[0] = *(const float4*)(aptr + (k0)); \
    pa[1] = *(const float4*)(aptr + (k0) + 4); \
    pa[2] = *(const float4*)(aptr + (k0) + 8); \
    pa[3] = *(const float4*)(aptr + (k0) + 12); \
    pb[0] = *(const float4*)(bptr + (k0)); \
    pb[1] = *(const float4*)(bptr + (k0) + 4); \
} while (0)

#define STORE_STAGE(s) do { \
    uint32_t* Ah = smw + (s) * STAGE_W; \
    uint32_t* Al = Ah + 2560; \
    uint32_t* Bh = Ah + 5120; \
    uint32_t* Bl = Ah + 6400; \
    float av[16] = {pa[0].x,pa[0].y,pa[0].z,pa[0].w, pa[1].x,pa[1].y,pa[1].z,pa[1].w, \
                    pa[2].x,pa[2].y,pa[2].z,pa[2].w, pa[3].x,pa[3].y,pa[3].z,pa[3].w}; \
    uint32_t ahv[8], alv[8]; \
    _Pragma("unroll") \
    for (int i = 0; i < 8; i++) cvt_hl(av[2*i], av[2*i+1], ahv[i], alv[i]); \
    int aoffw = arow * STW + (akq >> 1); \
    *(uint4*)(Ah + aoffw)     = make_uint4(ahv[0], ahv[1], ahv[2], ahv[3]); \
    *(uint4*)(Ah + aoffw + 4) = make_uint4(ahv[4], ahv[5], ahv[6], ahv[7]); \
    *(uint4*)(Al + aoffw)     = make_uint4(alv[0], alv[1], alv[2], alv[3]); \
    *(uint4*)(Al + aoffw + 4) = make_uint4(alv[4], alv[5], alv[6], alv[7]); \
    float bv[8] = {pb[0].x,pb[0].y,pb[0].z,pb[0].w, pb[1].x,pb[1].y,pb[1].z,pb[1].w}; \
    uint32_t bhv[4], blv[4]; \
    _Pragma("unroll") \
    for (int i = 0; i < 4; i++) cvt_hl(bv[2*i], bv[2*i+1], bhv[i], blv[i]); \
    int boffw = brow * STW + (bkq >> 1); \
    *(uint4*)(Bh + boffw) = make_uint4(bhv[0], bhv[1], bhv[2], bhv[3]); \
    *(uint4*)(Bl + boffw) = make_uint4(blv[0], blv[1], blv[2], blv[3]); \
} while (0)

#define DO_MMA(s) do { \
    uint32_t sb0 = smbase + (uint32_t)(s) * (STAGE_W * 4); \
    _Pragma("unroll") \
    for (int ks = 0; ks < 2; ks++) { \
        uint32_t kb = (uint32_t)(ks * 32); \
        uint32_t ah[2][4], al[2][4], bq[2][4], bl[2][4]; \
        _Pragma("unroll") \
        for (int mt = 0; mt < 2; mt++) { \
            ldsm_x4(sb0 + aoff + mt * (16 * STW * 4) + kb, ah[mt]); \
            ldsm_x4(sb0 + 2560 * 4 + aoff + mt * (16 * STW * 4) + kb, al[mt]); \
        } \
        _Pragma("unroll") \
        for (int p = 0; p < 2; p++) { \
            ldsm_x4(sb0 + 5120 * 4 + boff + p * (16 * STW * 4) + kb, bq[p]); \
            ldsm_x4(sb0 + 6400 * 4 + boff + p * (16 * STW * 4) + kb, bl[p]); \
        } \
        _Pragma("unroll") \
        for (int mt = 0; mt < 2; mt++) \
            _Pragma("unroll") \
            for (int nt = 0; nt < 4; nt++) { \
                const uint32_t* bh2 = &bq[nt >> 1][(nt & 1) * 2]; \
                const uint32_t* bl2 = &bl[nt >> 1][(nt & 1) * 2]; \
                mma_bf16(acc[mt][nt], ah[mt], bh2); \
                mma_bf16(acc[mt][nt], ah[mt], bl2); \
                mma_bf16(acc[mt][nt], al[mt], bh2); \
            } \
    } \
} while (0)

    const int NC = K / 32;
    LOAD_REGS(0);
    STORE_STAGE(0);
    __syncthreads();
    for (int it = 0; it < NC; ++it) {
        if (it + 1 < NC) LOAD_REGS((it + 1) * 32);
        DO_MMA(it & 1);
        if (it + 1 < NC) {
            __syncthreads();
            STORE_STAGE((it + 1) & 1);
            __syncthreads();
        }
    }

#pragma unroll
    for (int mt = 0; mt < 2; mt++)
#pragma unroll
        for (int nt = 0; nt < 4; nt++) {
            int row = m0 + wm * 32 + mt * 16 + r;
            int col = n0 + wn * 32 + nt * 8 + 2 * cq;
            float2 v0 = make_float2(acc[mt][nt][0], acc[mt][nt][1]);
            float2 v1 = make_float2(acc[mt][nt][2], acc[mt][nt][3]);
            if (bias) {
                float2 bv = *(const float2*)(bias + col);
                v0.x += bv.x; v0.y += bv.y;
                v1.x += bv.x; v1.y += bv.y;
            }
            *(float2*)(C + (size_t)row * Nn + col) = v0;
            *(float2*)(C + (size_t)(row + 8) * Nn + col) = v1;
        }
#undef LOAD_REGS
#undef STORE_STAGE
#undef DO_MMA
}

// ================= dd via bf16x3 mma: CTA = 64 rows x 256 features, K=64 =================
#define DSTW 12

#define DD_MAINLOOP() \
    float acc[2][8][4]; \
    _Pragma("unroll") \
    for (int i = 0; i < 2; i++) _Pragma("unroll") for (int j = 0; j < 8; j++) \
        _Pragma("unroll") for (int t = 0; t < 4; t++) acc[i][j][t] = 0.f; \
    int ar = tid >> 2, akq = (tid & 3) * 4; \
    const float* ab = data + ((size_t)b * NN + n0 + ar) * DIMM + h * 64 + akq; \
    const float* pbb = proj + (size_t)tid * 64; \
    float sumsq = 0.f; \
    for (int kc = 0; kc < 4; kc++) { \
        float4 va = *(const float4*)(ab + kc * 16); \
        float x0 = va.x * NORM, x1 = va.y * NORM, x2 = va.z * NORM, x3 = va.w * NORM; \
        sumsq += x0 * x0 + x1 * x1 + x2 * x2 + x3 * x3; \
        uint32_t ah0, al0, ah1, al1; \
        cvt_hl(x0, x1, ah0, al0); cvt_hl(x2, x3, ah1, al1); \
        float4 vb0 = *(const float4*)(pbb + kc * 16); \
        float4 vb1 = *(const float4*)(pbb + kc * 16 + 4); \
        float4 vb2 = *(const float4*)(pbb + kc * 16 + 8); \
        float4 vb3 = *(const float4*)(pbb + kc * 16 + 12); \
        float bvv[16] = {vb0.x,vb0.y,vb0.z,vb0.w, vb1.x,vb1.y,vb1.z,vb1.w, \
                         vb2.x,vb2.y,vb2.z,vb2.w, vb3.x,vb3.y,vb3.z,vb3.w}; \
        uint32_t bhv[8], blv[8]; \
        _Pragma("unroll") \
        for (int i = 0; i < 8; i++) cvt_hl(bvv[2*i], bvv[2*i+1], bhv[i], blv[i]); \
        __syncthreads(); \
        *(uint2*)(Ahs + ar * DSTW + (akq >> 1)) = make_uint2(ah0, ah1); \
        *(uint2*)(Als + ar * DSTW + (akq >> 1)) = make_uint2(al0, al1); \
        *(uint4*)(Bhs + tid * DSTW)     = make_uint4(bhv[0], bhv[1], bhv[2], bhv[3]); \
        *(uint4*)(Bhs + tid * DSTW + 4) = make_uint4(bhv[4], bhv[5], bhv[6], bhv[7]); \
        *(uint4*)(Bls + tid * DSTW)     = make_uint4(blv[0], blv[1], blv[2], blv[3]); \
        *(uint4*)(Bls + tid * DSTW + 4) = make_uint4(blv[4], blv[5], blv[6], blv[7]); \
        __syncthreads(); \
        uint32_t afh[2][4], afl[2][4]; \
        _Pragma("unroll") \
        for (int mt = 0; mt < 2; mt++) { \
            int mr = (wm * 32 + mt * 16 + r) * DSTW + cq; \
            afh[mt][0] = Ahs[mr];       afh[mt][1] = Ahs[mr + 8 * DSTW]; \
            afh[mt][2] = Ahs[mr + 4];   afh[mt][3] = Ahs[mr + 8 * DSTW + 4]; \
            afl[mt][0] = Als[mr];       afl[mt][1] = Als[mr + 8 * DSTW]; \
            afl[mt][2] = Als[mr + 4];   afl[mt][3] = Als[mr + 8 * DSTW + 4]; \
        } \
        _Pragma("unroll") \
        for (int nt = 0; nt < 8; nt++) { \
            int nr = (wn * 64 + nt * 8 + r) * DSTW + cq; \
            uint32_t bf[2] = {Bhs[nr], Bhs[nr + 4]}; \
            uint32_t bg[2] = {Bls[nr], Bls[nr + 4]}; \
            _Pragma("unroll") \
            for (int mt = 0; mt < 2; mt++) { \
                mma_bf16(acc[mt][nt], afh[mt], bf); \
                mma_bf16(acc[mt][nt], afh[mt], bg); \
                mma_bf16(acc[mt][nt], afl[mt], bf); \
            } \
        } \
    }

__global__ void __launch_bounds__(256, 2) ddq_mma(
    const float* __restrict__ data, const float* __restrict__ proj, float* __restrict__ qp)
{
    __shared__ uint32_t Ahs[64*DSTW], Als[64*DSTW], Bhs[256*DSTW], Bls[256*DSTW];
    __shared__ float ssq[64][4];
    __shared__ float wred[64][4];
    __shared__ float rowbase[64];
    int bh = blockIdx.y; int b = bh / GH, h = bh % GH;
    int n0 = blockIdx.x * 64;
    int tid = threadIdx.x;
    int wid = tid >> 5, lane = tid & 31;
    int wm = wid >> 2, wn = wid & 3;
    int r = lane >> 2, cq = lane & 3;
    const float NORM = 0.35355339059327373f;

    DD_MAINLOOP();

    ssq[ar][tid & 3] = sumsq;
    float mx[2][2];
#pragma unroll
    for (int mt = 0; mt < 2; mt++)
#pragma unroll
        for (int hf = 0; hf < 2; hf++) {
            float m = -1e30f;
#pragma unroll
            for (int nt = 0; nt < 8; nt++)
                m = fmaxf(m, fmaxf(acc[mt][nt][hf*2], acc[mt][nt][hf*2+1]));
            m = fmaxf(m, __shfl_xor_sync(0xffffffffu, m, 1));
            m = fmaxf(m, __shfl_xor_sync(0xffffffffu, m, 2));
            mx[mt][hf] = m;
        }
    if (cq == 0) {
#pragma unroll
        for (int mt = 0; mt < 2; mt++)
#pragma unroll
            for (int hf = 0; hf < 2; hf++)
                wred[wm * 32 + mt * 16 + hf * 8 + r][wn] = mx[mt][hf];
    }
    __syncthreads();
    if (tid < 64) {
        float mm = fmaxf(fmaxf(wred[tid][0], wred[tid][1]), fmaxf(wred[tid][2], wred[tid][3]));
        float dg = 0.5f * (ssq[tid][0] + ssq[tid][1] + ssq[tid][2] + ssq[tid][3]);
        rowbase[tid] = dg + mm;
    }
    __syncthreads();
#pragma unroll
    for (int mt = 0; mt < 2; mt++) {
        int row_a = wm * 32 + mt * 16 + r, row_b = row_a + 8;
        float ba = rowbase[row_a], bb2 = rowbase[row_b];
        float* oa = qp + ((size_t)bh * NN + n0 + row_a) * NBF;
        float* ob = qp + ((size_t)bh * NN + n0 + row_b) * NBF;
#pragma unroll
        for (int nt = 0; nt < 8; nt++) {
            int col = wn * 64 + nt * 8 + 2 * cq;
            float2 o1, o2;
            o1.x = 0.0625f * (expf(acc[mt][nt][0] - ba) + 1e-4f);
            o1.y = 0.0625f * (expf(acc[mt][nt][1] - ba) + 1e-4f);
            o2.x = 0.0625f * (expf(acc[mt][nt][2] - bb2) + 1e-4f);
            o2.y = 0.0625f * (expf(acc[mt][nt][3] - bb2) + 1e-4f);
            *(float2*)(oa + col) = o1;
            *(float2*)(ob + col) = o2;
        }
    }
}

__global__ void __launch_bounds__(256, 2) ddk_mma(
    const float* __restrict__ data, const float* __restrict__ proj,
    float* __restrict__ kdd, float* __restrict__ kdiag, float* __restrict__ kmaxp)
{
    __shared__ uint32_t Ahs[64*DSTW], Als[64*DSTW], Bhs[256*DSTW], Bls[256*DSTW];
    __shared__ float ssq[64][4];
    __shared__ float red[8];
    int bh = blockIdx.y; int b = bh / GH, h = bh % GH;
    int n0 = blockIdx.x * 64;
    int tid = threadIdx.x;
    int wid = tid >> 5, lane = tid & 31;
    int wm = wid >> 2, wn = wid & 3;
    int r = lane >> 2, cq = lane & 3;
    const float NORM = 0.35355339059327373f;

    DD_MAINLOOP();

    ssq[ar][tid & 3] = sumsq;
    __syncthreads();
    if (tid < 64)
        kdiag[(size_t)bh * NN + n0 + tid] =
            0.5f * (ssq[tid][0] + ssq[tid][1] + ssq[tid][2] + ssq[tid][3]);
    float tmax = -1e30f;
#pragma unroll
    for (int mt = 0; mt < 2; mt++) {
        int row_a = wm * 32 + mt * 16 + r, row_b = row_a + 8;
        float* oa = kdd + ((size_t)bh * NN + n0 + row_a) * NBF;
        float* ob = kdd + ((size_t)bh * NN + n0 + row_b) * NBF;
#pragma unroll
        for (int nt = 0; nt < 8; nt++) {
            int col = wn * 64 + nt * 8 + 2 * cq;
            float2 o1 = make_float2(acc[mt][nt][0], acc[mt][nt][1]);
            float2 o2 = make_float2(acc[mt][nt][2], acc[mt][nt][3]);
            tmax = fmaxf(tmax, fmaxf(fmaxf(o1.x, o1.y), fmaxf(o2.x, o2.y)));
            *(float2*)(oa + col) = o1;
            *(float2*)(ob + col) = o2;
        }
    }
#pragma unroll
    for (int o = 16; o > 0; o >>= 1) tmax = fmaxf(tmax, __shfl_xor_sync(0xffffffffu, tmax, o));
    if (lane == 0) red[wid] = tmax;
    __syncthreads();
    if (tid == 0) {
        float z = red[0];
#pragma unroll
        for (int i = 1; i < 8; i++) z = fmaxf(z, red[i]);
        kmaxp[bh * 128 + blockIdx.x] = z;
    }
}

__global__ void kmax_final_kernel(const float* __restrict__ kpart, float* __restrict__ kmax)
{
    int bh = blockIdx.x;
    float m = kpart[bh * 128 + threadIdx.x];
#pragma unroll
    for (int o = 16; o > 0; o >>= 1) m = fmaxf(m, __shfl_xor_sync(0xffffffffu, m, o));
    __shared__ float red[4];
    if ((threadIdx.x & 31) == 0) red[threadIdx.x >> 5] = m;
    __syncthreads();
    if (threadIdx.x == 0)
        kmax[bh] = fmaxf(fmaxf(red[0], red[1]), fmaxf(red[2], red[3]));
}

// ---------------- ctx: exp applied inline on raw kdd ----------------
__global__ void __launch_bounds__(256) ctx_partial_kernel(
    const float* __restrict__ kdd, const float* __restrict__ kdiag,
    const float* __restrict__ kmax, const float* __restrict__ v, float* __restrict__ part)
{
    int bh = blockIdx.x, sp = blockIdx.y;
    int b = bh / GH, h = bh % GH;
    int j = threadIdx.x;
    float acc[65];
#pragma unroll
    for (int d = 0; d < 65; d++) acc[d] = 0.f;
    __shared__ __align__(16) float vs[16][68];
    float km = kmax[bh];
    const float* kpb = kdd + ((size_t)bh * NN + sp * 256) * NBF + j;
    const float* dgb = kdiag + (size_t)bh * NN + sp * 256;
    const float* vb = v + ((size_t)b * NN + sp * 256) * DIMM + h * 64;
    for (int n0 = 0; n0 < 256; n0 += 16) {
        __syncthreads();
        int r = threadIdx.x >> 4;
        int c = (threadIdx.x & 15) * 4;
        float4 vv = *(const float4*)(vb + (size_t)(n0 + r) * DIMM + c);
        *(float4*)&vs[r][c] = vv;
        if ((threadIdx.x & 15) == 0) vs[r][64] = 1.f;
        if ((threadIdx.x & 15) == 1) vs[r][65] = dgb[n0 + r];
        __syncthreads();
#pragma unroll 2
        for (int nn = 0; nn < 16; nn++) {
            float praw = kpb[(size_t)(n0 + nn) * NBF];
            float p = 0.0625f * (expf(praw - vs[nn][65] - km) + 1e-4f);
#pragma unroll
            for (int d = 0; d < 65; d++) acc[d] += p * vs[nn][d];
        }
    }
    float* o = part + (((size_t)bh * NSPLIT + sp) * 256 + j) * 65;
#pragma unroll
    for (int d = 0; d < 65; d++) o[d] = acc[d];
}
__global__ void ctx_reduce_kernel(const float* __restrict__ part, float* __restrict__ ctx)
{
    int idx = blockIdx.x * 256 + threadIdx.x;
    if (idx >= BHG * 256 * 65) return;
    int bh = idx / (256 * 65); int rem = idx - bh * 256 * 65;
    int j = rem / 65, d = rem % 65;
    float s = 0.f;
#pragma unroll
    for (int sp = 0; sp < NSPLIT; sp++)
        s += part[(((size_t)bh * NSPLIT + sp) * 256 + j) * 65 + d];
    ctx[((size_t)bh * 256 + j) * 68 + d] = s;
}

// ---------------- d_inv = 1 / (qp . k_sum) ----------------
__global__ void denom_kernel(const float* __restrict__ qp, const float* __restrict__ ctx,
                             float* __restrict__ dinv)
{
    int row = blockIdx.x * 8 + (threadIdx.x >> 5);
    int lane = threadIdx.x & 31;
    int bh = row >> 13;
    const float* q = qp + (size_t)row * NBF;
    const float* ks = ctx + (size_t)bh * 256 * 68 + 64;
    float s = 0.f;
#pragma unroll
    for (int i = 0; i < 8; i++) s += q[lane + i * 32] * ks[(size_t)(lane + i * 32) * 68];
#pragma unroll
    for (int o = 16; o > 0; o >>= 1) s += __shfl_xor_sync(0xffffffffu, s, o);
    if (lane == 0) dinv[row] = 1.f / s;
}

// ---------------- out_g = (qp @ ctx) * d_inv -> att ----------------
__global__ void __launch_bounds__(256) outg_kernel(
    const float* __restrict__ qp, const float* __restrict__ ctx,
    const float* __restrict__ dinv, float* __restrict__ att)
{
    __shared__ __align__(16) float Qs[32][68];
    __shared__ __align__(16) float Cs[32][68];
    int bh = blockIdx.y; int b = bh / GH, h = bh % GH;
    int n0 = blockIdx.x * 64;
    int tid = threadIdx.x;
    int tx = tid & 15, ty = tid >> 4;
    float acc[4][4] = {};
    const float* qbase = qp + ((size_t)bh * NN + n0) * NBF;
    const float* cbase = ctx + (size_t)bh * 256 * 68;
    for (int k0 = 0; k0 < 256; k0 += 32) {
        int r = tid >> 3, c4 = (tid & 7) * 4;
#pragma unroll
        for (int i = 0; i < 2; i++) {
            float4 v = *(const float4*)(qbase + (size_t)(r + i * 32) * NBF + k0 + c4);
            Qs[c4+0][r+i*32] = v.x; Qs[c4+1][r+i*32] = v.y;
            Qs[c4+2][r+i*32] = v.z; Qs[c4+3][r+i*32] = v.w;
        }
        int cr = tid >> 4, cc4 = (tid & 15) * 4;
#pragma unroll
        for (int i = 0; i < 2; i++) {
            float4 v = *(const float4*)(cbase + (size_t)(k0 + cr + i * 16) * 68 + cc4);
            *(float4*)&Cs[cr + i * 16][cc4] = v;
        }
        __syncthreads();
#pragma unroll
        for (int kk = 0; kk < 32; kk++) {
            float4 a  = *(const float4*)&Qs[kk][ty*4];
            float4 bv = *(const float4*)&Cs[kk][tx*4];
            float av[4] = {a.x,a.y,a.z,a.w}, bb[4] = {bv.x,bv.y,bv.z,bv.w};
#pragma unroll
            for (int i = 0; i < 4; i++)
#pragma unroll
                for (int j = 0; j < 4; j++) acc[i][j] += av[i] * bb[j];
        }
        __syncthreads();
    }
#pragma unroll
    for (int i = 0; i < 4; i++) {
        int n = n0 + ty * 4 + i;
        float di = dinv[(size_t)bh * NN + n];
        float4 o = {acc[i][0]*di, acc[i][1]*di, acc[i][2]*di, acc[i][3]*di};
        *(float4*)(att + ((size_t)b * NN + n) * DIMM + h * 64 + tx * 4) = o;
    }
}

// ---------------- RoPE for local heads ----------------
__global__ void rope_kernel(const float* __restrict__ q, const float* __restrict__ k,
                            float* __restrict__ rq, float* __restrict__ rk)
{
    int idx = blockIdx.x * blockDim.x + threadIdx.x;
    int i = idx & 31;
    int n = (idx >> 5) & (NN - 1);
    int bh = idx >> 18;
    int b = bh >> 1, lh = bh & 1;
    float invf = (float)exp(-(double)(2 * i) / 64.0 * 9.210340371976184);
    float ang = (float)n * invf;
    float s, c;
    sincosf(ang, &s, &c);
    size_t base = ((size_t)b * NN + n) * DIMM + (GH + lh) * 64;
    float q1 = q[base + i], q2 = q[base + 32 + i];
    float k1 = k[base + i], k2 = k[base + 32 + i];
    size_t ob = ((size_t)bh * NN + n) * DH;
    rq[ob + i]      = q1 * c - q2 * s;
    rq[ob + 32 + i] = q2 * c + q1 * s;
    rk[ob + i]      = k1 * c - k2 * s;
    rk[ob + 32 + i] = k2 * c + k1 * s;
}

// ---------------- local scores = 0.125 * bq @ bk3^T with masking ----------------
__global__ void __launch_bounds__(256) lscore_kernel(
    const float* __restrict__ rq, const float* __restrict__ rk, float* __restrict__ sc)
{
    __shared__ __align__(16) float Qs[64][68];
    __shared__ __align__(16) float Ks[64][68];
    int bw = blockIdx.z; int bh = bw >> 5; int w = bw & 31;
    int m0 = blockIdx.y * 64, c0 = blockIdx.x * 64;
    int tid = threadIdx.x;
    int lr = tid >> 2, lc4 = (tid & 3) * 4;
    const float* qb = rq + ((size_t)bh * NN + w * WINSZ + m0) * DH;
    const float* kb = rk + (size_t)bh * NN * DH;
    int knr = (w - 1) * WINSZ + c0 + lr;
    bool kvalid = (unsigned)knr < (unsigned)NN;
#pragma unroll
    for (int i = 0; i < 4; i++) {
        int c = lc4 + i * 16;
        float4 va = *(const float4*)(qb + (size_t)lr * DH + c);
        Qs[c+0][lr] = va.x; Qs[c+1][lr] = va.y; Qs[c+2][lr] = va.z; Qs[c+3][lr] = va.w;
        float4 vk = make_float4(0.f, 0.f, 0.f, 0.f);
        if (kvalid) vk = *(const float4*)(kb + (size_t)knr * DH + c);
        Ks[c+0][lr] = vk.x; Ks[c+1][lr] = vk.y; Ks[c+2][lr] = vk.z; Ks[c+3][lr] = vk.w;
    }
    __syncthreads();
    int tx = tid & 15, ty = tid >> 4;
    float acc[4][4] = {};
#pragma unroll
    for (int kk = 0; kk < 64; kk++) {
        float4 a  = *(const float4*)&Qs[kk][ty*4];
        float4 bv = *(const float4*)&Ks[kk][tx*4];
        float av[4] = {a.x,a.y,a.z,a.w}, bb[4] = {bv.x,bv.y,bv.z,bv.w};
#pragma unroll
        for (int i = 0; i < 4; i++)
#pragma unroll
            for (int j = 0; j < 4; j++) acc[i][j] += av[i] * bb[j];
    }
    int kn0 = (w - 1) * WINSZ + c0 + tx * 4;
    bool valid = (unsigned)kn0 < (unsigned)NN;
    float* ob = sc + ((size_t)bw * WINSZ + m0) * 768 + c0;
#pragma unroll
    for (int i = 0; i < 4; i++) {
        float4 o;
        o.x = valid ? acc[i][0] * 0.125f : -1e9f;
        o.y = valid ? acc[i][1] * 0.125f : -1e9f;
        o.z = valid ? acc[i][2] * 0.125f : -1e9f;
        o.w = valid ? acc[i][3] * 0.125f : -1e9f;
        *(float4*)(ob + (size_t)(ty * 4 + i) * 768 + tx * 4) = o;
    }
}

// ---------------- row stats: m and 1/sum(exp) per score row ----------------
__global__ void rowstats_kernel(const float* __restrict__ sc,
                                float* __restrict__ rm, float* __restrict__ rs)
{
    int row = blockIdx.x * 8 + (threadIdx.x >> 5);
    int lane = threadIdx.x & 31;
    const float* r = sc + (size_t)row * 768;
    float vals[24];
    float m = -1e30f;
#pragma unroll
    for (int i = 0; i < 24; i++) { vals[i] = r[lane + i * 32]; m = fmaxf(m, vals[i]); }
#pragma unroll
    for (int o = 16; o > 0; o >>= 1) m = fmaxf(m, __shfl_xor_sync(0xffffffffu, m, o));
    float s = 0.f;
#pragma unroll
    for (int i = 0; i < 24; i++) s += expf(vals[i] - m);
#pragma unroll
    for (int o = 16; o > 0; o >>= 1) s += __shfl_xor_sync(0xffffffffu, s, o);
    if (lane == 0) { rm[row] = m; rs[row] = 1.f / s; }
}

// ---------------- out_l = softmax(sc) @ bv3 -> att (exp fused in load) ----------------
__global__ void __launch_bounds__(256) outl_kernel(
    const float* __restrict__ sc, const float* __restrict__ rm, const float* __restrict__ rs,
    const float* __restrict__ v, float* __restrict__ att)
{
    __shared__ __align__(16) float As[32][68];
    __shared__ __align__(16) float Vs[32][68];
    __shared__ float sm_m[64], sm_is[64];
    int bw = blockIdx.y; int bh = bw >> 5; int w = bw & 31;
    int b = bh >> 1, lh = bh & 1;
    int m0 = blockIdx.x * 64;
    int tid = threadIdx.x;
    int tx = tid & 15, ty = tid >> 4;
    int rowbase = bw * WINSZ + m0;
    if (tid < 64) { sm_m[tid] = rm[rowbase + tid]; sm_is[tid] = rs[rowbase + tid]; }
    __syncthreads();
    float acc[4][4] = {};
    const float* sb = sc + (size_t)rowbase * 768;
    const float* vb = v + (size_t)b * NN * DIMM + (GH + lh) * 64;
    for (int k0 = 0; k0 < 768; k0 += 32) {
#pragma unroll
        for (int i = 0; i < 2; i++) {
            int s1 = tid + i * 256;
            {
                int r = s1 >> 3, c4 = (s1 & 7) * 4;
                float4 a = *(const float4*)(sb + (size_t)r * 768 + k0 + c4);
                float mm = sm_m[r], is = sm_is[r];
                As[c4+0][r] = expf(a.x - mm) * is;
                As[c4+1][r] = expf(a.y - mm) * is;
                As[c4+2][r] = expf(a.z - mm) * is;
                As[c4+3][r] = expf(a.w - mm) * is;
            }
            {
                int kr = s1 >> 4, c4 = (s1 & 15) * 4;
                int kn = (w - 1) * WINSZ + k0 + kr;
                float4 vv = make_float4(0.f, 0.f, 0.f, 0.f);
                if ((unsigned)kn < (unsigned)NN)
                    vv = *(const float4*)(vb + (size_t)kn * DIMM + c4);
                *(float4*)&Vs[kr][c4] = vv;
            }
        }
        __syncthreads();
#pragma unroll
        for (int kk = 0; kk < 32; kk++) {
            float4 a  = *(const float4*)&As[kk][ty*4];
            float4 bv = *(const float4*)&Vs[kk][tx*4];
            float av[4] = {a.x,a.y,a.z,a.w}, bb[4] = {bv.x,bv.y,bv.z,bv.w};
#pragma unroll
            for (int i = 0; i < 4; i++)
#pragma unroll
                for (int j = 0; j < 4; j++) acc[i][j] += av[i] * bb[j];
        }
        __syncthreads();
    }
#pragma unroll
    for (int i = 0; i < 4; i++) {
        int n = w * WINSZ + m0 + ty * 4 + i;
        float4 o = {acc[i][0], acc[i][1], acc[i][2], acc[i][3]};
        *(float4*)(att + ((size_t)b * NN + n) * DIMM + (GH + lh) * 64 + tx * 4) = o;
    }
}

// ---------------- launcher ----------------
extern "C" void kernel_launch(void* const* d_in, const int* in_sizes, int n_in,
                              void* d_out, int out_size)
{
    (void)in_sizes; (void)n_in; (void)out_size;
    const float* x    = (const float*)d_in[0];
    const float* Wq   = (const float*)d_in[1];
    const float* Wk   = (const float*)d_in[2];
    const float* Wv   = (const float*)d_in[3];
    const float* Wo   = (const float*)d_in[4];
    const float* bo   = (const float*)d_in[5];
    const float* proj = (const float*)d_in[6];
    float* out = (float*)d_out;

    float *q, *k, *v, *qp, *kp, *kdg, *kmp, *km, *part, *ctx, *dinv, *att, *sc, *rq, *rk, *rm, *rs, *bt, *wot;
    cudaGetSymbolAddress((void**)&q, g_q);
    cudaGetSymbolAddress((void**)&k, g_k);
    cudaGetSymbolAddress((void**)&v, g_v);
    cudaGetSymbolAddress((void**)&qp, g_qp);
    cudaGetSymbolAddress((void**)&kp, g_kp);
    cudaGetSymbolAddress((void**)&kdg, g_kdiag);
    cudaGetSymbolAddress((void**)&kmp, g_kmaxp);
    cudaGetSymbolAddress((void**)&km, g_kmax);
    cudaGetSymbolAddress((void**)&part, g_part);
    cudaGetSymbolAddress((void**)&ctx, g_ctx);
    cudaGetSymbolAddress((void**)&dinv, g_dinv);
    cudaGetSymbolAddress((void**)&att, g_att);
    cudaGetSymbolAddress((void**)&sc, g_sc);
    cudaGetSymbolAddress((void**)&rq, g_rq);
    cudaGetSymbolAddress((void**)&rk, g_rk);
    cudaGetSymbolAddress((void**)&rm, g_rowm);
    cudaGetSymbolAddress((void**)&rs, g_rows);
    cudaGetSymbolAddress((void**)&bt, g_bt);
    cudaGetSymbolAddress((void**)&wot, g_wot);

    cudaFuncSetAttribute(gemm_bf3, cudaFuncAttributeMaxDynamicSharedMemorySize, GSMEM_BYTES);

    const int M = BB * NN; // 16384

    dim3 tb(32, 8), tg(16, 16, 4);
    wtrans4<<<tg, tb>>>(Wq, Wk, Wv, Wo, bt, bt + 512 * 512, bt + 1024 * 512, wot);

    dim3 gt(DIMM / 64, M / 128);
    gemm_bf3<<<gt, 256, GSMEM_BYTES>>>(x, bt, nullptr, q, M, DIMM, DIMM);
    gemm_bf3<<<gt, 256, GSMEM_BYTES>>>(x, bt + 512 * 512, nullptr, k, M, DIMM, DIMM);
    gemm_bf3<<<gt, 256, GSMEM_BYTES>>>(x, bt + 1024 * 512, nullptr, v, M, DIMM, DIMM);

    dim3 gdd(NN / 64, BHG);
    ddq_mma<<<gdd, 256>>>(q, proj, qp);
    ddk_mma<<<gdd, 256>>>(k, proj, kp, kdg, kmp);
    kmax_final_kernel<<<BHG, 128>>>(kmp, km);

    ctx_partial_kernel<<<dim3(BHG, NSPLIT), 256>>>(kp, kdg, km, v, part);
    ctx_reduce_kernel<<<(BHG * 256 * 65 + 255) / 256, 256>>>(part, ctx);

    denom_kernel<<<BHG * NN / 8, 256>>>(qp, ctx, dinv);
    outg_kernel<<<dim3(NN / 64, BHG), 256>>>(qp, ctx, dinv, att);

    rope_kernel<<<BHL * NN * 32 / 256, 256>>>(q, k, rq, rk);
    lscore_kernel<<<dim3(12, 4, BHL * NWIN), 256>>>(rq, rk, sc);
    rowstats_kernel<<<BHL * NWIN * WINSZ / 8, 256>>>(sc, rm, rs);
    outl_kernel<<<dim3(4, BHL * NWIN), 256>>>(sc, rm, rs, v, att);

    gemm_bf3<<<gt, 256, GSMEM_BYTES>>>(att, wot, bo, out, M, DIMM, DIMM);
}

// round 13
// speedup vs baseline: 1.7316x; 1.0737x over previous
#include <cuda_runtime.h>
#include <cuda_bf16.h>
#include <math.h>
#include <stdint.h>

#define BB 2
#define NN 8192
#define DIMM 512
#define GH 6
#define DH 64
#define NBF 256
#define NWIN 32
#define WINSZ 256
#define BHG (BB*GH)      // 12
#define BHL 4            // B * LOCAL_HEADS
#define NSPLIT 32

// ---------------- scratch (device globals: alloc-free) ----------------
__device__ float g_q[BB*NN*DIMM];
__device__ float g_k[BB*NN*DIMM];
__device__ float g_v[BB*NN*DIMM];
__device__ float g_qp[BHG*NN*NBF];
__device__ float g_kp[BHG*NN*NBF];      // raw k dd scores
__device__ float g_kdiag[BHG*NN];
__device__ float g_kmaxp[BHG*128];
__device__ float g_kmax[BHG];
__device__ float g_part[BHG*NSPLIT*256*65];
__device__ float g_ctx[BHG*256*68];
__device__ float g_dinv[BHG*NN];
__device__ float g_att[BB*NN*DIMM];
__device__ float g_sc[(size_t)BHL*NWIN*WINSZ*768];
__device__ float g_rq[BHL*NN*DH];
__device__ float g_rk[BHL*NN*DH];
__device__ float g_rowm[BHL*NWIN*WINSZ];
__device__ float g_rows[BHL*NWIN*WINSZ];
__device__ float g_w[4*512*512];                 // transposed weights fp32 (Q,K,V,O)
__device__ __nv_bfloat16 g_wh[4*512*512];        // bf16 hi
__device__ __nv_bfloat16 g_wl[4*512*512];        // bf16 lo
__device__ __nv_bfloat16 g_xh[BB*NN*DIMM];
__device__ __nv_bfloat16 g_xl[BB*NN*DIMM];
__device__ __nv_bfloat16 g_ath[BB*NN*DIMM];
__device__ __nv_bfloat16 g_atl[BB*NN*DIMM];

// ================= bf16 hi/lo split helpers =================
__device__ __forceinline__ void cvt_hl(float f0, float f1, uint32_t& hi, uint32_t& lo) {
    __nv_bfloat16 h0 = __float2bfloat16_rn(f0), h1 = __float2bfloat16_rn(f1);
    float r0 = f0 - __bfloat162float(h0), r1 = f1 - __bfloat162float(h1);
    __nv_bfloat162 hh; hh.x = h0; hh.y = h1;
    __nv_bfloat162 ll = __floats2bfloat162_rn(r0, r1);
    hi = *reinterpret_cast<uint32_t*>(&hh);
    lo = *reinterpret_cast<uint32_t*>(&ll);
}
__device__ __forceinline__ void mma_bf16(float* c, const uint32_t* a, const uint32_t* b) {
    asm volatile(
        "mma.sync.aligned.m16n8k16.row.col.f32.bf16.bf16.f32 "
        "{%0,%1,%2,%3}, {%4,%5,%6,%7}, {%8,%9}, {%0,%1,%2,%3};"
        : "+f"(c[0]), "+f"(c[1]), "+f"(c[2]), "+f"(c[3])
        : "r"(a[0]), "r"(a[1]), "r"(a[2]), "r"(a[3]), "r"(b[0]), "r"(b[1]));
}
__device__ __forceinline__ uint32_t cvta_smem(const void* p) {
    uint32_t a;
    asm("{ .reg .u64 t; cvta.to.shared.u64 t, %1; cvt.u32.u64 %0, t; }" : "=r"(a) : "l"(p));
    return a;
}
__device__ __forceinline__ void ldsm_x4(uint32_t addr, uint32_t* d) {
    asm volatile("ldmatrix.sync.aligned.m8n8.x4.shared.b16 {%0,%1,%2,%3}, [%4];"
        : "=r"(d[0]), "=r"(d[1]), "=r"(d[2]), "=r"(d[3]) : "r"(addr));
}
__device__ __forceinline__ void cp16(uint32_t s, const void* g) {
    asm volatile("cp.async.cg.shared.global [%0], [%1], 16;" :: "r"(s), "l"(g));
}
#define CP_COMMIT() asm volatile("cp.async.commit_group;" ::: "memory")
#define CP_WAIT1()  asm volatile("cp.async.wait_group 1;" ::: "memory")
#define CP_WAIT0()  asm volatile("cp.async.wait_group 0;" ::: "memory")

// ================= weight transpose (all 4 in one launch) =================
__global__ void wtrans4(const float* __restrict__ W0, const float* __restrict__ W1,
                        const float* __restrict__ W2, const float* __restrict__ W3,
                        float* __restrict__ wout)
{
    __shared__ float t[32][33];
    const float* W = (blockIdx.z == 0) ? W0 : (blockIdx.z == 1) ? W1 : (blockIdx.z == 2) ? W2 : W3;
    float* out = wout + (size_t)blockIdx.z * 512 * 512;
    int n0 = blockIdx.x * 32, k0 = blockIdx.y * 32;
    int tx = threadIdx.x, ty = threadIdx.y;
#pragma unroll
    for (int i = ty; i < 32; i += 8) t[i][tx] = W[(size_t)(k0 + i) * 512 + n0 + tx];
    __syncthreads();
#pragma unroll
    for (int i = ty; i < 32; i += 8) out[(size_t)(n0 + i) * 512 + k0 + tx] = t[tx][i];
}

// ================= fp32 -> bf16 hi/lo conversion (8 elems/thread) =================
__global__ void conv_hl(const float* __restrict__ in, __nv_bfloat16* __restrict__ oh,
                        __nv_bfloat16* __restrict__ ol)
{
    size_t i = ((size_t)blockIdx.x * 256 + threadIdx.x) * 8;
    float4 a = *(const float4*)(in + i), b = *(const float4*)(in + i + 4);
    float v[8] = {a.x, a.y, a.z, a.w, b.x, b.y, b.z, b.w};
    uint32_t h[4], l[4];
#pragma unroll
    for (int j = 0; j < 4; j++) cvt_hl(v[2*j], v[2*j+1], h[j], l[j]);
    *(uint4*)(oh + i) = make_uint4(h[0], h[1], h[2], h[3]);
    *(uint4*)(ol + i) = make_uint4(l[0], l[1], l[2], l[3]);
}

// ================= bf16x3 GEMM: cp.async 3-stage + ldmatrix + mma =================
#define STW 20
#define STAGE_W 7680
#define GSMEM_BYTES (3*STAGE_W*4)

__global__ void __launch_bounds__(256, 2) gemm_bfq(
    const __nv_bfloat16* __restrict__ Ah, const __nv_bfloat16* __restrict__ Al,
    const __nv_bfloat16* __restrict__ Bh, const __nv_bfloat16* __restrict__ Bl,
    const float* __restrict__ bias,
    float* __restrict__ o0, float* __restrict__ o1, float* __restrict__ o2)
{
    extern __shared__ uint32_t smw[];
    const int K = 512;
    const int NC = 16;
    int tid = threadIdx.x;
    int wid = tid >> 5, lane = tid & 31;
    int wm = wid >> 1, wn = wid & 1;
    int m0 = blockIdx.y * 128, n0 = blockIdx.x * 64;
    int r = lane >> 2, cq = lane & 3;
    int lr = lane & 7, lg = lane >> 3;
    float acc[2][4][4] = {};
    uint32_t smbase = cvta_smem(smw);
    uint32_t aoff = (uint32_t)(((wm * 32 + (lg & 1) * 8 + lr) * STW + (lg >> 1) * 4) * 4);
    uint32_t boff = (uint32_t)(((wn * 32 + (lg >> 1) * 8 + lr) * STW + (lg & 1) * 4) * 4);

    int arow = tid >> 1, acz = (tid & 1) * 16;
    int brow = tid >> 2, bcz = (tid & 3) * 8;
    const __nv_bfloat16* agh = Ah + (size_t)(m0 + arow) * K + acz;
    const __nv_bfloat16* agl = Al + (size_t)(m0 + arow) * K + acz;
    const __nv_bfloat16* bgh = Bh + (size_t)(n0 + brow) * K + bcz;
    const __nv_bfloat16* bgl = Bl + (size_t)(n0 + brow) * K + bcz;
    uint32_t as_off = (uint32_t)((arow * STW + (tid & 1) * 8) * 4);
    uint32_t bs_off = (uint32_t)((brow * STW + (tid & 3) * 4) * 4);

#define PREFETCH(s, k0) do { \
    uint32_t st = smbase + (uint32_t)(s) * (STAGE_W * 4); \
    cp16(st + as_off,                 agh + (k0)); \
    cp16(st + as_off + 16,            agh + (k0) + 8); \
    cp16(st + 2560 * 4 + as_off,      agl + (k0)); \
    cp16(st + 2560 * 4 + as_off + 16, agl + (k0) + 8); \
    cp16(st + 5120 * 4 + bs_off,      bgh + (k0)); \
    cp16(st + 6400 * 4 + bs_off,      bgl + (k0)); \
    CP_COMMIT(); \
} while (0)

#define DO_MMA(s) do { \
    uint32_t sb0 = smbase + (uint32_t)(s) * (STAGE_W * 4); \
    _Pragma("unroll") \
    for (int ks = 0; ks < 2; ks++) { \
        uint32_t kb = (uint32_t)(ks * 32); \
        uint32_t ah[2][4], al[2][4], bq[2][4], bl[2][4]; \
        _Pragma("unroll") \
        for (int mt = 0; mt < 2; mt++) { \
            ldsm_x4(sb0 + aoff + mt * (16 * STW * 4) + kb, ah[mt]); \
            ldsm_x4(sb0 + 2560 * 4 + aoff + mt * (16 * STW * 4) + kb, al[mt]); \
        } \
        _Pragma("unroll") \
        for (int p = 0; p < 2; p++) { \
            ldsm_x4(sb0 + 5120 * 4 + boff + p * (16 * STW * 4) + kb, bq[p]); \
            ldsm_x4(sb0 + 6400 * 4 + boff + p * (16 * STW * 4) + kb, bl[p]); \
        } \
        _Pragma("unroll") \
        for (int mt = 0; mt < 2; mt++) \
            _Pragma("unroll") \
            for (int nt = 0; nt < 4; nt++) { \
                const uint32_t* bh2 = &bq[nt >> 1][(nt & 1) * 2]; \
                const uint32_t* bl2 = &bl[nt >> 1][(nt & 1) * 2]; \
                mma_bf16(acc[mt][nt], ah[mt], bh2); \
                mma_bf16(acc[mt][nt], ah[mt], bl2); \
                mma_bf16(acc[mt][nt], al[mt], bh2); \
            } \
    } \
} while (0)

    PREFETCH(0, 0);
    PREFETCH(1, 32);
    for (int it = 0; it < NC; ++it) {
        if (it < NC - 1) { CP_WAIT1(); } else { CP_WAIT0(); }
        __syncthreads();
        if (it + 2 < NC) PREFETCH((it + 2) % 3, (it + 2) * 32);
        DO_MMA(it % 3);
    }

    int sel = n0 >> 9;
    int colb = n0 & 511;
    float* ob = (sel == 0) ? o0 : (sel == 1) ? o1 : o2;
#pragma unroll
    for (int mt = 0; mt < 2; mt++)
#pragma unroll
        for (int nt = 0; nt < 4; nt++) {
            int row = m0 + wm * 32 + mt * 16 + r;
            int col = colb + wn * 32 + nt * 8 + 2 * cq;
            float2 v0 = make_float2(acc[mt][nt][0], acc[mt][nt][1]);
            float2 v1 = make_float2(acc[mt][nt][2], acc[mt][nt][3]);
            if (bias) {
                float2 bv = *(const float2*)(bias + col);
                v0.x += bv.x; v0.y += bv.y;
                v1.x += bv.x; v1.y += bv.y;
            }
            *(float2*)(ob + (size_t)row * 512 + col) = v0;
            *(float2*)(ob + (size_t)(row + 8) * 512 + col) = v1;
        }
#undef PREFETCH
#undef DO_MMA
}

// ================= dd via bf16x3 mma: CTA = 64 rows x 256 features, K=64 =================
#define DSTW 12

#define DD_MAINLOOP() \
    float acc[2][8][4]; \
    _Pragma("unroll") \
    for (int i = 0; i < 2; i++) _Pragma("unroll") for (int j = 0; j < 8; j++) \
        _Pragma("unroll") for (int t = 0; t < 4; t++) acc[i][j][t] = 0.f; \
    int ar = tid >> 2, akq = (tid & 3) * 4; \
    const float* ab = data + ((size_t)b * NN + n0 + ar) * DIMM + h * 64 + akq; \
    const float* pbb = proj + (size_t)tid * 64; \
    float sumsq = 0.f; \
    for (int kc = 0; kc < 4; kc++) { \
        float4 va = *(const float4*)(ab + kc * 16); \
        float x0 = va.x * NORM, x1 = va.y * NORM, x2 = va.z * NORM, x3 = va.w * NORM; \
        sumsq += x0 * x0 + x1 * x1 + x2 * x2 + x3 * x3; \
        uint32_t ah0, al0, ah1, al1; \
        cvt_hl(x0, x1, ah0, al0); cvt_hl(x2, x3, ah1, al1); \
        float4 vb0 = *(const float4*)(pbb + kc * 16); \
        float4 vb1 = *(const float4*)(pbb + kc * 16 + 4); \
        float4 vb2 = *(const float4*)(pbb + kc * 16 + 8); \
        float4 vb3 = *(const float4*)(pbb + kc * 16 + 12); \
        float bvv[16] = {vb0.x,vb0.y,vb0.z,vb0.w, vb1.x,vb1.y,vb1.z,vb1.w, \
                         vb2.x,vb2.y,vb2.z,vb2.w, vb3.x,vb3.y,vb3.z,vb3.w}; \
        uint32_t bhv[8], blv[8]; \
        _Pragma("unroll") \
        for (int i = 0; i < 8; i++) cvt_hl(bvv[2*i], bvv[2*i+1], bhv[i], blv[i]); \
        __syncthreads(); \
        *(uint2*)(Ahs + ar * DSTW + (akq >> 1)) = make_uint2(ah0, ah1); \
        *(uint2*)(Als + ar * DSTW + (akq >> 1)) = make_uint2(al0, al1); \
        *(uint4*)(Bhs + tid * DSTW)     = make_uint4(bhv[0], bhv[1], bhv[2], bhv[3]); \
        *(uint4*)(Bhs + tid * DSTW + 4) = make_uint4(bhv[4], bhv[5], bhv[6], bhv[7]); \
        *(uint4*)(Bls + tid * DSTW)     = make_uint4(blv[0], blv[1], blv[2], blv[3]); \
        *(uint4*)(Bls + tid * DSTW + 4) = make_uint4(blv[4], blv[5], blv[6], blv[7]); \
        __syncthreads(); \
        uint32_t afh[2][4], afl[2][4]; \
        _Pragma("unroll") \
        for (int mt = 0; mt < 2; mt++) { \
            int mr = (wm * 32 + mt * 16 + r) * DSTW + cq; \
            afh[mt][0] = Ahs[mr];       afh[mt][1] = Ahs[mr + 8 * DSTW]; \
            afh[mt][2] = Ahs[mr + 4];   afh[mt][3] = Ahs[mr + 8 * DSTW + 4]; \
            afl[mt][0] = Als[mr];       afl[mt][1] = Als[mr + 8 * DSTW]; \
            afl[mt][2] = Als[mr + 4];   afl[mt][3] = Als[mr + 8 * DSTW + 4]; \
        } \
        _Pragma("unroll") \
        for (int nt = 0; nt < 8; nt++) { \
            int nr = (wn * 64 + nt * 8 + r) * DSTW + cq; \
            uint32_t bf[2] = {Bhs[nr], Bhs[nr + 4]}; \
            uint32_t bg[2] = {Bls[nr], Bls[nr + 4]}; \
            _Pragma("unroll") \
            for (int mt = 0; mt < 2; mt++) { \
                mma_bf16(acc[mt][nt], afh[mt], bf); \
                mma_bf16(acc[mt][nt], afh[mt], bg); \
                mma_bf16(acc[mt][nt], afl[mt], bf); \
            } \
        } \
    }

__global__ void __launch_bounds__(256, 2) ddq_mma(
    const float* __restrict__ data, const float* __restrict__ proj, float* __restrict__ qp)
{
    __shared__ uint32_t Ahs[64*DSTW], Als[64*DSTW], Bhs[256*DSTW], Bls[256*DSTW];
    __shared__ float ssq[64][4];
    __shared__ float wred[64][4];
    __shared__ float rowbase[64];
    int bh = blockIdx.y; int b = bh / GH, h = bh % GH;
    int n0 = blockIdx.x * 64;
    int tid = threadIdx.x;
    int wid = tid >> 5, lane = tid & 31;
    int wm = wid >> 2, wn = wid & 3;
    int r = lane >> 2, cq = lane & 3;
    const float NORM = 0.35355339059327373f;

    DD_MAINLOOP();

    ssq[ar][tid & 3] = sumsq;
    float mx[2][2];
#pragma unroll
    for (int mt = 0; mt < 2; mt++)
#pragma unroll
        for (int hf = 0; hf < 2; hf++) {
            float m = -1e30f;
#pragma unroll
            for (int nt = 0; nt < 8; nt++)
                m = fmaxf(m, fmaxf(acc[mt][nt][hf*2], acc[mt][nt][hf*2+1]));
            m = fmaxf(m, __shfl_xor_sync(0xffffffffu, m, 1));
            m = fmaxf(m, __shfl_xor_sync(0xffffffffu, m, 2));
            mx[mt][hf] = m;
        }
    if (cq == 0) {
#pragma unroll
        for (int mt = 0; mt < 2; mt++)
#pragma unroll
            for (int hf = 0; hf < 2; hf++)
                wred[wm * 32 + mt * 16 + hf * 8 + r][wn] = mx[mt][hf];
    }
    __syncthreads();
    if (tid < 64) {
        float mm = fmaxf(fmaxf(wred[tid][0], wred[tid][1]), fmaxf(wred[tid][2], wred[tid][3]));
        float dg = 0.5f * (ssq[tid][0] + ssq[tid][1] + ssq[tid][2] + ssq[tid][3]);
        rowbase[tid] = dg + mm;
    }
    __syncthreads();
#pragma unroll
    for (int mt = 0; mt < 2; mt++) {
        int row_a = wm * 32 + mt * 16 + r, row_b = row_a + 8;
        float ba = rowbase[row_a], bb2 = rowbase[row_b];
        float* oa = qp + ((size_t)bh * NN + n0 + row_a) * NBF;
        float* ob = qp + ((size_t)bh * NN + n0 + row_b) * NBF;
#pragma unroll
        for (int nt = 0; nt < 8; nt++) {
            int col = wn * 64 + nt * 8 + 2 * cq;
            float2 o1, o2;
            o1.x = 0.0625f * (expf(acc[mt][nt][0] - ba) + 1e-4f);
            o1.y = 0.0625f * (expf(acc[mt][nt][1] - ba) + 1e-4f);
            o2.x = 0.0625f * (expf(acc[mt][nt][2] - bb2) + 1e-4f);
            o2.y = 0.0625f * (expf(acc[mt][nt][3] - bb2) + 1e-4f);
            *(float2*)(oa + col) = o1;
            *(float2*)(ob + col) = o2;
        }
    }
}

__global__ void __launch_bounds__(256, 2) ddk_mma(
    const float* __restrict__ data, const float* __restrict__ proj,
    float* __restrict__ kdd, float* __restrict__ kdiag, float* __restrict__ kmaxp)
{
    __shared__ uint32_t Ahs[64*DSTW], Als[64*DSTW], Bhs[256*DSTW], Bls[256*DSTW];
    __shared__ float ssq[64][4];
    __shared__ float red[8];
    int bh = blockIdx.y; int b = bh / GH, h = bh % GH;
    int n0 = blockIdx.x * 64;
    int tid = threadIdx.x;
    int wid = tid >> 5, lane = tid & 31;
    int wm = wid >> 2, wn = wid & 3;
    int r = lane >> 2, cq = lane & 3;
    const float NORM = 0.35355339059327373f;

    DD_MAINLOOP();

    ssq[ar][tid & 3] = sumsq;
    __syncthreads();
    if (tid < 64)
        kdiag[(size_t)bh * NN + n0 + tid] =
            0.5f * (ssq[tid][0] + ssq[tid][1] + ssq[tid][2] + ssq[tid][3]);
    float tmax = -1e30f;
#pragma unroll
    for (int mt = 0; mt < 2; mt++) {
        int row_a = wm * 32 + mt * 16 + r, row_b = row_a + 8;
        float* oa = kdd + ((size_t)bh * NN + n0 + row_a) * NBF;
        float* ob = kdd + ((size_t)bh * NN + n0 + row_b) * NBF;
#pragma unroll
        for (int nt = 0; nt < 8; nt++) {
            int col = wn * 64 + nt * 8 + 2 * cq;
            float2 o1 = make_float2(acc[mt][nt][0], acc[mt][nt][1]);
            float2 o2 = make_float2(acc[mt][nt][2], acc[mt][nt][3]);
            tmax = fmaxf(tmax, fmaxf(fmaxf(o1.x, o1.y), fmaxf(o2.x, o2.y)));
            *(float2*)(oa + col) = o1;
            *(float2*)(ob + col) = o2;
        }
    }
#pragma unroll
    for (int o = 16; o > 0; o >>= 1) tmax = fmaxf(tmax, __shfl_xor_sync(0xffffffffu, tmax, o));
    if (lane == 0) red[wid] = tmax;
    __syncthreads();
    if (tid == 0) {
        float z = red[0];
#pragma unroll
        for (int i = 1; i < 8; i++) z = fmaxf(z, red[i]);
        kmaxp[bh * 128 + blockIdx.x] = z;
    }
}

__global__ void kmax_final_kernel(const float* __restrict__ kpart, float* __restrict__ kmax)
{
    int bh = blockIdx.x;
    float m = kpart[bh * 128 + threadIdx.x];
#pragma unroll
    for (int o = 16; o > 0; o >>= 1) m = fmaxf(m, __shfl_xor_sync(0xffffffffu, m, o));
    __shared__ float red[4];
    if ((threadIdx.x & 31) == 0) red[threadIdx.x >> 5] = m;
    __syncthreads();
    if (threadIdx.x == 0)
        kmax[bh] = fmaxf(fmaxf(red[0], red[1]), fmaxf(red[2], red[3]));
}

// ---------------- ctx: exp applied inline on raw kdd ----------------
__global__ void __launch_bounds__(256) ctx_partial_kernel(
    const float* __restrict__ kdd, const float* __restrict__ kdiag,
    const float* __restrict__ kmax, const float* __restrict__ v, float* __restrict__ part)
{
    int bh = blockIdx.x, sp = blockIdx.y;
    int b = bh / GH, h = bh % GH;
    int j = threadIdx.x;
    float acc[65];
#pragma unroll
    for (int d = 0; d < 65; d++) acc[d] = 0.f;
    __shared__ __align__(16) float vs[16][68];
    float km = kmax[bh];
    const float* kpb = kdd + ((size_t)bh * NN + sp * 256) * NBF + j;
    const float* dgb = kdiag + (size_t)bh * NN + sp * 256;
    const float* vb = v + ((size_t)b * NN + sp * 256) * DIMM + h * 64;
    for (int n0 = 0; n0 < 256; n0 += 16) {
        __syncthreads();
        int r = threadIdx.x >> 4;
        int c = (threadIdx.x & 15) * 4;
        float4 vv = *(const float4*)(vb + (size_t)(n0 + r) * DIMM + c);
        *(float4*)&vs[r][c] = vv;
        if ((threadIdx.x & 15) == 0) vs[r][64] = 1.f;
        if ((threadIdx.x & 15) == 1) vs[r][65] = dgb[n0 + r];
        __syncthreads();
#pragma unroll 2
        for (int nn = 0; nn < 16; nn++) {
            float praw = kpb[(size_t)(n0 + nn) * NBF];
            float p = 0.0625f * (expf(praw - vs[nn][65] - km) + 1e-4f);
#pragma unroll
            for (int d = 0; d < 65; d++) acc[d] += p * vs[nn][d];
        }
    }
    float* o = part + (((size_t)bh * NSPLIT + sp) * 256 + j) * 65;
#pragma unroll
    for (int d = 0; d < 65; d++) o[d] = acc[d];
}
__global__ void ctx_reduce_kernel(const float* __restrict__ part, float* __restrict__ ctx)
{
    int idx = blockIdx.x * 256 + threadIdx.x;
    if (idx >= BHG * 256 * 65) return;
    int bh = idx / (256 * 65); int rem = idx - bh * 256 * 65;
    int j = rem / 65, d = rem % 65;
    float s = 0.f;
#pragma unroll
    for (int sp = 0; sp < NSPLIT; sp++)
        s += part[(((size_t)bh * NSPLIT + sp) * 256 + j) * 65 + d];
    ctx[((size_t)bh * 256 + j) * 68 + d] = s;
}

// ---------------- d_inv = 1 / (qp . k_sum) ----------------
__global__ void denom_kernel(const float* __restrict__ qp, const float* __restrict__ ctx,
                             float* __restrict__ dinv)
{
    int row = blockIdx.x * 8 + (threadIdx.x >> 5);
    int lane = threadIdx.x & 31;
    int bh = row >> 13;
    const float* q = qp + (size_t)row * NBF;
    const float* ks = ctx + (size_t)bh * 256 * 68 + 64;
    float s = 0.f;
#pragma unroll
    for (int i = 0; i < 8; i++) s += q[lane + i * 32] * ks[(size_t)(lane + i * 32) * 68];
#pragma unroll
    for (int o = 16; o > 0; o >>= 1) s += __shfl_xor_sync(0xffffffffu, s, o);
    if (lane == 0) dinv[row] = 1.f / s;
}

// ---------------- out_g = (qp @ ctx) * d_inv -> att ----------------
__global__ void __launch_bounds__(256) outg_kernel(
    const float* __restrict__ qp, const float* __restrict__ ctx,
    const float* __restrict__ dinv, float* __restrict__ att)
{
    __shared__ __align__(16) float Qs[32][68];
    __shared__ __align__(16) float Cs[32][68];
    int bh = blockIdx.y; int b = bh / GH, h = bh % GH;
    int n0 = blockIdx.x * 64;
    int tid = threadIdx.x;
    int tx = tid & 15, ty = tid >> 4;
    float acc[4][4] = {};
    const float* qbase = qp + ((size_t)bh * NN + n0) * NBF;
    const float* cbase = ctx + (size_t)bh * 256 * 68;
    for (int k0 = 0; k0 < 256; k0 += 32) {
        int r = tid >> 3, c4 = (tid & 7) * 4;
#pragma unroll
        for (int i = 0; i < 2; i++) {
            float4 v = *(const float4*)(qbase + (size_t)(r + i * 32) * NBF + k0 + c4);
            Qs[c4+0][r+i*32] = v.x; Qs[c4+1][r+i*32] = v.y;
            Qs[c4+2][r+i*32] = v.z; Qs[c4+3][r+i*32] = v.w;
        }
        int cr = tid >> 4, cc4 = (tid & 15) * 4;
#pragma unroll
        for (int i = 0; i < 2; i++) {
            float4 v = *(const float4*)(cbase + (size_t)(k0 + cr + i * 16) * 68 + cc4);
            *(float4*)&Cs[cr + i * 16][cc4] = v;
        }
        __syncthreads();
#pragma unroll
        for (int kk = 0; kk < 32; kk++) {
            float4 a  = *(const float4*)&Qs[kk][ty*4];
            float4 bv = *(const float4*)&Cs[kk][tx*4];
            float av[4] = {a.x,a.y,a.z,a.w}, bb[4] = {bv.x,bv.y,bv.z,bv.w};
#pragma unroll
            for (int i = 0; i < 4; i++)
#pragma unroll
                for (int j = 0; j < 4; j++) acc[i][j] += av[i] * bb[j];
        }
        __syncthreads();
    }
#pragma unroll
    for (int i = 0; i < 4; i++) {
        int n = n0 + ty * 4 + i;
        float di = dinv[(size_t)bh * NN + n];
        float4 o = {acc[i][0]*di, acc[i][1]*di, acc[i][2]*di, acc[i][3]*di};
        *(float4*)(att + ((size_t)b * NN + n) * DIMM + h * 64 + tx * 4) = o;
    }
}

// ---------------- RoPE for local heads ----------------
__global__ void rope_kernel(const float* __restrict__ q, const float* __restrict__ k,
                            float* __restrict__ rq, float* __restrict__ rk)
{
    int idx = blockIdx.x * blockDim.x + threadIdx.x;
    int i = idx & 31;
    int n = (idx >> 5) & (NN - 1);
    int bh = idx >> 18;
    int b = bh >> 1, lh = bh & 1;
    float invf = (float)exp(-(double)(2 * i) / 64.0 * 9.210340371976184);
    float ang = (float)n * invf;
    float s, c;
    sincosf(ang, &s, &c);
    size_t base = ((size_t)b * NN + n) * DIMM + (GH + lh) * 64;
    float q1 = q[base + i], q2 = q[base + 32 + i];
    float k1 = k[base + i], k2 = k[base + 32 + i];
    size_t ob = ((size_t)bh * NN + n) * DH;
    rq[ob + i]      = q1 * c - q2 * s;
    rq[ob + 32 + i] = q2 * c + q1 * s;
    rk[ob + i]      = k1 * c - k2 * s;
    rk[ob + 32 + i] = k2 * c + k1 * s;
}

// ---------------- local scores = 0.125 * bq @ bk3^T with masking ----------------
__global__ void __launch_bounds__(256) lscore_kernel(
    const float* __restrict__ rq, const float* __restrict__ rk, float* __restrict__ sc)
{
    __shared__ __align__(16) float Qs[64][68];
    __shared__ __align__(16) float Ks[64][68];
    int bw = blockIdx.z; int bh = bw >> 5; int w = bw & 31;
    int m0 = blockIdx.y * 64, c0 = blockIdx.x * 64;
    int tid = threadIdx.x;
    int lr = tid >> 2, lc4 = (tid & 3) * 4;
    const float* qb = rq + ((size_t)bh * NN + w * WINSZ + m0) * DH;
    const float* kb = rk + (size_t)bh * NN * DH;
    int knr = (w - 1) * WINSZ + c0 + lr;
    bool kvalid = (unsigned)knr < (unsigned)NN;
#pragma unroll
    for (int i = 0; i < 4; i++) {
        int c = lc4 + i * 16;
        float4 va = *(const float4*)(qb + (size_t)lr * DH + c);
        Qs[c+0][lr] = va.x; Qs[c+1][lr] = va.y; Qs[c+2][lr] = va.z; Qs[c+3][lr] = va.w;
        float4 vk = make_float4(0.f, 0.f, 0.f, 0.f);
        if (kvalid) vk = *(const float4*)(kb + (size_t)knr * DH + c);
        Ks[c+0][lr] = vk.x; Ks[c+1][lr] = vk.y; Ks[c+2][lr] = vk.z; Ks[c+3][lr] = vk.w;
    }
    __syncthreads();
    int tx = tid & 15, ty = tid >> 4;
    float acc[4][4] = {};
#pragma unroll
    for (int kk = 0; kk < 64; kk++) {
        float4 a  = *(const float4*)&Qs[kk][ty*4];
        float4 bv = *(const float4*)&Ks[kk][tx*4];
        float av[4] = {a.x,a.y,a.z,a.w}, bb[4] = {bv.x,bv.y,bv.z,bv.w};
#pragma unroll
        for (int i = 0; i < 4; i++)
#pragma unroll
            for (int j = 0; j < 4; j++) acc[i][j] += av[i] * bb[j];
    }
    int kn0 = (w - 1) * WINSZ + c0 + tx * 4;
    bool valid = (unsigned)kn0 < (unsigned)NN;
    float* ob = sc + ((size_t)bw * WINSZ + m0) * 768 + c0;
#pragma unroll
    for (int i = 0; i < 4; i++) {
        float4 o;
        o.x = valid ? acc[i][0] * 0.125f : -1e9f;
        o.y = valid ? acc[i][1] * 0.125f : -1e9f;
        o.z = valid ? acc[i][2] * 0.125f : -1e9f;
        o.w = valid ? acc[i][3] * 0.125f : -1e9f;
        *(float4*)(ob + (size_t)(ty * 4 + i) * 768 + tx * 4) = o;
    }
}

// ---------------- row stats: m and 1/sum(exp) per score row ----------------
__global__ void rowstats_kernel(const float* __restrict__ sc,
                                float* __restrict__ rm, float* __restrict__ rs)
{
    int row = blockIdx.x * 8 + (threadIdx.x >> 5);
    int lane = threadIdx.x & 31;
    const float* r = sc + (size_t)row * 768;
    float vals[24];
    float m = -1e30f;
#pragma unroll
    for (int i = 0; i < 24; i++) { vals[i] = r[lane + i * 32]; m = fmaxf(m, vals[i]); }
#pragma unroll
    for (int o = 16; o > 0; o >>= 1) m = fmaxf(m, __shfl_xor_sync(0xffffffffu, m, o));
    float s = 0.f;
#pragma unroll
    for (int i = 0; i < 24; i++) s += expf(vals[i] - m);
#pragma unroll
    for (int o = 16; o > 0; o >>= 1) s += __shfl_xor_sync(0xffffffffu, s, o);
    if (lane == 0) { rm[row] = m; rs[row] = 1.f / s; }
}

// ---------------- out_l = softmax(sc) @ bv3 -> att (exp fused in load) ----------------
__global__ void __launch_bounds__(256) outl_kernel(
    const float* __restrict__ sc, const float* __restrict__ rm, const float* __restrict__ rs,
    const float* __restrict__ v, float* __restrict__ att)
{
    __shared__ __align__(16) float As[32][68];
    __shared__ __align__(16) float Vs[32][68];
    __shared__ float sm_m[64], sm_is[64];
    int bw = blockIdx.y; int bh = bw >> 5; int w = bw & 31;
    int b = bh >> 1, lh = bh & 1;
    int m0 = blockIdx.x * 64;
    int tid = threadIdx.x;
    int tx = tid & 15, ty = tid >> 4;
    int rowbase = bw * WINSZ + m0;
    if (tid < 64) { sm_m[tid] = rm[rowbase + tid]; sm_is[tid] = rs[rowbase + tid]; }
    __syncthreads();
    float acc[4][4] = {};
    const float* sb = sc + (size_t)rowbase * 768;
    const float* vb = v + (size_t)b * NN * DIMM + (GH + lh) * 64;
    for (int k0 = 0; k0 < 768; k0 += 32) {
#pragma unroll
        for (int i = 0; i < 2; i++) {
            int s1 = tid + i * 256;
            {
                int r = s1 >> 3, c4 = (s1 & 7) * 4;
                float4 a = *(const float4*)(sb + (size_t)r * 768 + k0 + c4);
                float mm = sm_m[r], is = sm_is[r];
                As[c4+0][r] = expf(a.x - mm) * is;
                As[c4+1][r] = expf(a.y - mm) * is;
                As[c4+2][r] = expf(a.z - mm) * is;
                As[c4+3][r] = expf(a.w - mm) * is;
            }
            {
                int kr = s1 >> 4, c4 = (s1 & 15) * 4;
                int kn = (w - 1) * WINSZ + k0 + kr;
                float4 vv = make_float4(0.f, 0.f, 0.f, 0.f);
                if ((unsigned)kn < (unsigned)NN)
                    vv = *(const float4*)(vb + (size_t)kn * DIMM + c4);
                *(float4*)&Vs[kr][c4] = vv;
            }
        }
        __syncthreads();
#pragma unroll
        for (int kk = 0; kk < 32; kk++) {
            float4 a  = *(const float4*)&As[kk][ty*4];
            float4 bv = *(const float4*)&Vs[kk][tx*4];
            float av[4] = {a.x,a.y,a.z,a.w}, bb[4] = {bv.x,bv.y,bv.z,bv.w};
#pragma unroll
            for (int i = 0; i < 4; i++)
#pragma unroll
                for (int j = 0; j < 4; j++) acc[i][j] += av[i] * bb[j];
        }
        __syncthreads();
    }
#pragma unroll
    for (int i = 0; i < 4; i++) {
        int n = w * WINSZ + m0 + ty * 4 + i;
        float4 o = {acc[i][0], acc[i][1], acc[i][2], acc[i][3]};
        *(float4*)(att + ((size_t)b * NN + n) * DIMM + (GH + lh) * 64 + tx * 4) = o;
    }
}

// ---------------- launcher ----------------
extern "C" void kernel_launch(void* const* d_in, const int* in_sizes, int n_in,
                              void* d_out, int out_size)
{
    (void)in_sizes; (void)n_in; (void)out_size;
    const float* x    = (const float*)d_in[0];
    const float* Wq   = (const float*)d_in[1];
    const float* Wk   = (const float*)d_in[2];
    const float* Wv   = (const float*)d_in[3];
    const float* Wo   = (const float*)d_in[4];
    const float* bo   = (const float*)d_in[5];
    const float* proj = (const float*)d_in[6];
    float* out = (float*)d_out;

    float *q, *k, *v, *qp, *kp, *kdg, *kmp, *km, *part, *ctx, *dinv, *att, *sc, *rq, *rk, *rm, *rs, *w;
    __nv_bfloat16 *wh, *wl, *xh, *xl, *ath, *atl;
    cudaGetSymbolAddress((void**)&q, g_q);
    cudaGetSymbolAddress((void**)&k, g_k);
    cudaGetSymbolAddress((void**)&v, g_v);
    cudaGetSymbolAddress((void**)&qp, g_qp);
    cudaGetSymbolAddress((void**)&kp, g_kp);
    cudaGetSymbolAddress((void**)&kdg, g_kdiag);
    cudaGetSymbolAddress((void**)&kmp, g_kmaxp);
    cudaGetSymbolAddress((void**)&km, g_kmax);
    cudaGetSymbolAddress((void**)&part, g_part);
    cudaGetSymbolAddress((void**)&ctx, g_ctx);
    cudaGetSymbolAddress((void**)&dinv, g_dinv);
    cudaGetSymbolAddress((void**)&att, g_att);
    cudaGetSymbolAddress((void**)&sc, g_sc);
    cudaGetSymbolAddress((void**)&rq, g_rq);
    cudaGetSymbolAddress((void**)&rk, g_rk);
    cudaGetSymbolAddress((void**)&rm, g_rowm);
    cudaGetSymbolAddress((void**)&rs, g_rows);
    cudaGetSymbolAddress((void**)&w, g_w);
    cudaGetSymbolAddress((void**)&wh, g_wh);
    cudaGetSymbolAddress((void**)&wl, g_wl);
    cudaGetSymbolAddress((void**)&xh, g_xh);
    cudaGetSymbolAddress((void**)&xl, g_xl);
    cudaGetSymbolAddress((void**)&ath, g_ath);
    cudaGetSymbolAddress((void**)&atl, g_atl);

    cudaFuncSetAttribute(gemm_bfq, cudaFuncAttributeMaxDynamicSharedMemorySize, GSMEM_BYTES);

    const int M = BB * NN; // 16384

    // weights: transpose then convert; x: convert
    dim3 tb(32, 8), tg(16, 16, 4);
    wtrans4<<<tg, tb>>>(Wq, Wk, Wv, Wo, w);
    conv_hl<<<4 * 512 * 512 / 2048, 256>>>(w, wh, wl);
    conv_hl<<<(size_t)M * DIMM / 2048, 256>>>(x, xh, xl);

    // fused QKV projection (grid.x = 24 -> routes to q/k/v)
    gemm_bfq<<<dim3(24, M / 128), 256, GSMEM_BYTES>>>(xh, xl, wh, wl, nullptr, q, k, v);

    dim3 gdd(NN / 64, BHG);
    ddq_mma<<<gdd, 256>>>(q, proj, qp);
    ddk_mma<<<gdd, 256>>>(k, proj, kp, kdg, kmp);
    kmax_final_kernel<<<BHG, 128>>>(kmp, km);

    ctx_partial_kernel<<<dim3(BHG, NSPLIT), 256>>>(kp, kdg, km, v, part);
    ctx_reduce_kernel<<<(BHG * 256 * 65 + 255) / 256, 256>>>(part, ctx);

    denom_kernel<<<BHG * NN / 8, 256>>>(qp, ctx, dinv);
    outg_kernel<<<dim3(NN / 64, BHG), 256>>>(qp, ctx, dinv, att);

    rope_kernel<<<BHL * NN * 32 / 256, 256>>>(q, k, rq, rk);
    lscore_kernel<<<dim3(12, 4, BHL * NWIN), 256>>>(rq, rk, sc);
    rowstats_kernel<<<BHL * NWIN * WINSZ / 8, 256>>>(sc, rm, rs);
    outl_kernel<<<dim3(4, BHL * NWIN), 256>>>(sc, rm, rs, v, att);

    // output projection
    conv_hl<<<(size_t)M * DIMM / 2048, 256>>>(att, ath, atl);
    gemm_bfq<<<dim3(8, M / 128), 256, GSMEM_BYTES>>>(ath, atl, wh + 3 * 512 * 512, wl + 3 * 512 * 512,
                                                     bo, out, out, out);
}